// round 9
// baseline (speedup 1.0000x reference)
#include <cuda_runtime.h>
#include <cuda_fp16.h>
#include <math.h>
#include <stdint.h>

#define HW 16384
#define NB 8
#define MROWS (NB*HW)      // 131072
#define HID 512
#define FD 128
#define NTOK 256
#define PI_D 3.14159265358979323846

// ---------------- fp16 buffers ----------------
__device__ __half g_gq_h[HW*FD];
__device__ __half g_gl_h[3ull*HW*FD];
__device__ __half g_xq_h[HW*HID];
__device__ __half g_q_h[HW*FD];
__device__ __half g_kv_h[NB*NTOK*256];
__device__ __half g_attn_h[(unsigned long long)MROWS*FD];
__device__ __half g_s_h[(unsigned long long)MROWS*HID];   // S1
__device__ __half g_m0_h[(unsigned long long)MROWS*HID];  // M0, reused as S2
__device__ __half g_g2_h[(unsigned long long)MROWS*HID];  // reluG2
__device__ __half g_tok_h[NB*NTOK*HID];
__device__ __half g_hl_h[3ull*HW*HID];
__device__ __half g_qWT[HID*FD];
__device__ __half g_WqT[FD*HID];
__device__ __half g_WkvT[256*HID];
__device__ __half g_bwWT[3*HID*FD];
__device__ __half g_modWT[3*HID*HID];
__device__ __half g_hvWT[2*HID*HID];
__device__ __half g_WoA[FD*HID];
__device__ __half g_wfT[3*HID*FD];
// ---------------- fp32 buffers ----------------
__device__ float g_tv[HW];
__device__ float g_bf[3*HID];

// ================= helpers =================
__device__ __forceinline__ uint32_t smem_u32(const void* p) {
    uint32_t a;
    asm("{ .reg .u64 t; cvta.to.shared.u64 t, %1; cvt.u32.u64 %0, t; }" : "=r"(a) : "l"(p));
    return a;
}
__device__ __forceinline__ void ldm_x4(uint32_t* r, uint32_t addr) {
    asm volatile("ldmatrix.sync.aligned.m8n8.x4.shared.b16 {%0,%1,%2,%3}, [%4];"
                 : "=r"(r[0]), "=r"(r[1]), "=r"(r[2]), "=r"(r[3]) : "r"(addr));
}
__device__ __forceinline__ void mma16816(float* d, const uint32_t* a, uint32_t b0, uint32_t b1) {
    asm volatile(
        "mma.sync.aligned.m16n8k16.row.col.f32.f16.f16.f32 "
        "{%0,%1,%2,%3}, {%4,%5,%6,%7}, {%8,%9}, {%0,%1,%2,%3};"
        : "+f"(d[0]), "+f"(d[1]), "+f"(d[2]), "+f"(d[3])
        : "r"(a[0]), "r"(a[1]), "r"(a[2]), "r"(a[3]), "r"(b0), "r"(b1));
}
__device__ __forceinline__ void cp16(uint32_t dst, const void* src) {
    asm volatile("cp.async.cg.shared.global [%0], [%1], 16;" :: "r"(dst), "l"(src));
}
#define CP_COMMIT() asm volatile("cp.async.commit_group;" ::: "memory")
#define CP_WAIT(n)  asm volatile("cp.async.wait_group %0;" :: "n"(n) : "memory")

// ================= Fourier features =================
__global__ void gamma_k(const float* __restrict__ x, __half* __restrict__ gq,
                        __half* __restrict__ gl, float* __restrict__ tv)
{
    __shared__ double omg[128];
    int q = blockIdx.x;
    int f = threadIdx.x;
    {
        const double sig[4] = {128.0, 16.0, 64.0, 256.0};
        int s = f >> 5, j = f & 31;
        double step = (log10(sig[s]) - 1.0) / 31.0;
        omg[f] = pow(10.0, 1.0 + (double)j * step);
    }
    __syncthreads();

    float c0 = x[2*q], c1 = x[2*q+1];
    if (f == 0) {
        int r  = (int)(c0 * 16.0f);
        int cc = (int)(c1 * 16.0f);
        tv[q] = (float)(r*16 + cc) * (1.0f/256.0f);
    }
    int d = f >> 6;
    int rr = f & 63;
    int part = rr >> 5;
    int j = rr & 31;
    double coord = d ? (double)c1 : (double)c0;
    #pragma unroll
    for (int s = 0; s < 4; s++) {
        double arg = PI_D * coord * omg[s*32 + j];
        float val = (float)(part ? cos(arg) : sin(arg));
        __half* dst = (s == 0) ? gq : (gl + (size_t)(s-1)*HW*FD);
        dst[(size_t)q*FD + f] = __float2half_rn(val);
    }
}

// ================= merged weight prep =================
__global__ void prep_k(const float* __restrict__ qW, const float* __restrict__ Wq,
                       const float* __restrict__ Wkv, const float* __restrict__ bwW,
                       const float* __restrict__ modW, const float* __restrict__ hvW,
                       const float* __restrict__ Wo, const float* __restrict__ tokens,
                       const float* __restrict__ outb,
                       __half* __restrict__ qWT, __half* __restrict__ WqT,
                       __half* __restrict__ WkvT, __half* __restrict__ bwWT,
                       __half* __restrict__ modWT, __half* __restrict__ hvWT,
                       __half* __restrict__ WoA, __half* __restrict__ tokh,
                       float* __restrict__ total)
{
    long long i = (long long)blockIdx.x * 256 + threadIdx.x;
    if (i < 65536) {
        int k = (int)(i/512), n = (int)(i%512);
        qWT[n*128+k] = __float2half_rn(qW[i]); return;
    } i -= 65536;
    if (i < 65536) {
        int k = (int)(i/128), n = (int)(i%128);
        WqT[n*512+k] = __float2half_rn(Wq[i]); return;
    } i -= 65536;
    if (i < 131072) {
        int k = (int)(i/256), n = (int)(i%256);
        WkvT[n*512+k] = __float2half_rn(Wkv[i]); return;
    } i -= 131072;
    if (i < 196608) {
        int s = (int)(i/65536); long long j = i%65536;
        int k = (int)(j/512), n = (int)(j%512);
        bwWT[s*65536 + n*128+k] = __float2half_rn(bwW[i]); return;
    } i -= 196608;
    if (i < 786432) {
        int s = (int)(i/262144); long long j = i%262144;
        int k = (int)(j/512), n = (int)(j%512);
        modWT[s*262144 + n*512+k] = __float2half_rn(modW[i]); return;
    } i -= 786432;
    if (i < 524288) {
        int s = (int)(i/262144); long long j = i%262144;
        int k = (int)(j/512), n = (int)(j%512);
        hvWT[s*262144 + n*512+k] = __float2half_rn(hvW[i]); return;
    } i -= 524288;
    if (i < 65536) { WoA[i] = __float2half_rn(Wo[i]); return; } i -= 65536;
    if (i < 1048576) { tokh[i] = __float2half_rn(tokens[i]); return; } i -= 1048576;
    if (i < (long long)MROWS*3) {
        int c = (int)(i % 3);
        total[i] = outb[c] + outb[3+c] + outb[6+c];
    }
}
#define PREP_TOTAL 3276800LL

// ================= HMMA fp16 GEMM: 4-stage cp.async, K-chunk 32 =================
// CTA tile 128(M) x 64(N). 8 warps 4(row) x 2(col); warp tile 32x32.
// ITERS = K/32 (compile-time). One __syncthreads per chunk.
// epi: (+bias f32) (+bch[(r&16383),N] fp16) (relu) OUTP(total += v.outWsel) (+af fp16) -> Ch / CTh
#define LDK 40                       // 32 + 8 pad halves (80 B rows)
#define A_P (128*LDK)                // 5120 halves
#define B_P (64*LDK)                 // 2560 halves
#define STG (A_P + B_P)              // 7680 halves = 15360 B
#define TG_SMEM (4*STG*2)            // 61440 B
template<bool RELU, bool BCAST, bool ADDF, bool OUTP, int ITERS>
__global__ __launch_bounds__(256, 3)
void tgemm(const __half* __restrict__ A, const __half* __restrict__ WT,
           const float* __restrict__ bias, const __half* __restrict__ bch,
           const __half* __restrict__ af,
           __half* __restrict__ Ch, __half* __restrict__ CTh,
           const float* __restrict__ outWsel, float* __restrict__ total,
           int M, int N)
{
    const int K = ITERS*32;
    extern __shared__ __half sh_[];
    int tid = threadIdx.x, wid = tid >> 5, lane = tid & 31;
    long long m0 = (long long)blockIdx.y * 128;
    long long n0 = (long long)blockIdx.x * 64;
    int wm = (wid & 3) * 32;
    int wn = (wid >> 2) * 32;

    float d[2][4][4];
    #pragma unroll
    for (int mi = 0; mi < 2; mi++)
        #pragma unroll
        for (int ni = 0; ni < 4; ni++)
            #pragma unroll
            for (int q = 0; q < 4; q++) d[mi][ni][q] = 0.f;

    uint32_t s_u = smem_u32(sh_);
    int ar0 = tid >> 2, ac0 = tid & 3;         // A chunk 0: rows 0..63
    int ar1 = ar0 + 64;                        // A chunk 1: rows 64..127
    int br  = tid >> 2, bc0 = tid & 3;         // B: 64 rows x 4 chunks

    auto load_stage = [&](int t) {
        uint32_t base = s_u + (uint32_t)(t & 3) * (STG*2);
        int kt = t << 5;
        cp16(base + (ar0*LDK + ac0*8)*2, A + (m0 + ar0)*(long long)K + kt + ac0*8);
        cp16(base + (ar1*LDK + ac0*8)*2, A + (m0 + ar1)*(long long)K + kt + ac0*8);
        cp16(base + (A_P + br*LDK + bc0*8)*2, WT + (n0 + br)*(long long)K + kt + bc0*8);
        CP_COMMIT();
    };

    load_stage(0); load_stage(1); load_stage(2);

    uint32_t q_row = (uint32_t)(lane & 15), q_koff = (uint32_t)(lane >> 4) * 8;

    #pragma unroll
    for (int t = 0; t < ITERS; t++) {
        if (t + 2 <= ITERS - 1)      { CP_WAIT(2); }
        else if (t + 1 <= ITERS - 1) { CP_WAIT(1); }
        else                         { CP_WAIT(0); }
        __syncthreads();
        if (t + 3 < ITERS) load_stage(t + 3);

        uint32_t sa_u = s_u + (uint32_t)(t & 3) * (STG*2);
        uint32_t sb_u = sa_u + A_P*2;
        #pragma unroll
        for (int kk = 0; kk < 32; kk += 16) {
            uint32_t afr[2][4], bfr[2][4];
            #pragma unroll
            for (int mi = 0; mi < 2; mi++)
                ldm_x4(afr[mi], sa_u + (((uint32_t)wm + mi*16 + q_row)*LDK + kk + q_koff)*2);
            #pragma unroll
            for (int nj = 0; nj < 2; nj++)
                ldm_x4(bfr[nj], sb_u + (((uint32_t)wn + nj*16 + q_row)*LDK + kk + q_koff)*2);
            #pragma unroll
            for (int mi = 0; mi < 2; mi++)
                #pragma unroll
                for (int ni = 0; ni < 4; ni++)
                    mma16816(d[mi][ni], afr[mi], bfr[ni>>1][ni&1], bfr[ni>>1][(ni&1)+2]);
        }
    }
    __syncthreads();

    float* red = (float*)sh_;
    if (OUTP) {
        for (int i = tid; i < 128*3; i += 256) red[i] = 0.f;
        __syncthreads();
    }

    int qr = lane >> 2;
    int qc = (lane & 3) * 2;
    #pragma unroll
    for (int mi = 0; mi < 2; mi++) {
        #pragma unroll
        for (int rh = 0; rh < 2; rh++) {
            int rloc = wm + mi*16 + rh*8 + qr;
            long long r  = m0 + rloc;
            long long rb_ = BCAST ? (r & (HW - 1)) : r;
            float p0 = 0.f, p1 = 0.f, p2 = 0.f;
            #pragma unroll
            for (int ni = 0; ni < 4; ni++) {
                long long c = n0 + wn + ni*8 + qc;
                float v0 = d[mi][ni][rh*2+0];
                float v1 = d[mi][ni][rh*2+1];
                if (bias) {
                    float2 b2 = *(const float2*)(bias + c);
                    v0 += b2.x; v1 += b2.y;
                }
                if (BCAST) {
                    float2 b2 = __half22float2(*(const __half2*)(bch + rb_*(long long)N + c));
                    v0 += b2.x; v1 += b2.y;
                }
                if (RELU) { v0 = fmaxf(v0, 0.f); v1 = fmaxf(v1, 0.f); }
                if (OUTP) {
                    const float* w0 = outWsel + c*3;
                    p0 += v0*w0[0] + v1*w0[3];
                    p1 += v0*w0[1] + v1*w0[4];
                    p2 += v0*w0[2] + v1*w0[5];
                }
                if (ADDF) {
                    float2 af2 = __half22float2(*(const __half2*)(af + r*(long long)N + c));
                    v0 += af2.x; v1 += af2.y;
                }
                if (Ch) *(__half2*)(Ch + r*(long long)N + c) = __floats2half2_rn(v0, v1);
                if (CTh) {
                    CTh[c*(long long)M + r]     = __float2half_rn(v0);
                    CTh[(c+1)*(long long)M + r] = __float2half_rn(v1);
                }
            }
            if (OUTP) {
                #pragma unroll
                for (int o = 1; o < 4; o <<= 1) {
                    p0 += __shfl_xor_sync(0xffffffffu, p0, o);
                    p1 += __shfl_xor_sync(0xffffffffu, p1, o);
                    p2 += __shfl_xor_sync(0xffffffffu, p2, o);
                }
                if ((lane & 3) == 0) {
                    atomicAdd(&red[rloc*3+0], p0);
                    atomicAdd(&red[rloc*3+1], p1);
                    atomicAdd(&red[rloc*3+2], p2);
                }
            }
        }
    }
    if (OUTP) {
        __syncthreads();
        for (int i = tid; i < 128*3; i += 256)
            atomicAdd(&total[(m0 + (i/3))*3 + (i%3)], red[i]);
    }
}

// ================= pair-band GEMM: G0 + G1 share A (4-stage, K=128) =================
#define PR_STG (A_P + 2*B_P)                 // 10240 halves = 20480 B
#define PR_SMEM (4*PR_STG*2)                 // 81920 B
__global__ __launch_bounds__(256, 2)
void pairgemm(const __half* __restrict__ A, const __half* __restrict__ wfT,
              const float* __restrict__ bf, const __half* __restrict__ hl,
              __half* __restrict__ m0h, __half* __restrict__ s1h,
              const float* __restrict__ outW, float* __restrict__ total)
{
    extern __shared__ __half sh_[];
    int tid = threadIdx.x, wid = tid >> 5, lane = tid & 31;
    long long m0 = (long long)blockIdx.y * 128;
    long long n0 = (long long)blockIdx.x * 64;
    int wm = (wid & 3) * 32;
    int wn = (wid >> 2) * 32;
    uint32_t s_u = smem_u32(sh_);

    float d0[2][4][4], d1[2][4][4];
    #pragma unroll
    for (int mi = 0; mi < 2; mi++)
        #pragma unroll
        for (int ni = 0; ni < 4; ni++)
            #pragma unroll
            for (int q = 0; q < 4; q++) { d0[mi][ni][q] = 0.f; d1[mi][ni][q] = 0.f; }

    int ar0 = tid >> 2, ac0 = tid & 3;
    int ar1 = ar0 + 64;
    int br  = tid >> 2;

    auto load_stage = [&](int t) {
        uint32_t base = s_u + (uint32_t)(t & 3) * (PR_STG*2);
        int kt = t << 5;
        cp16(base + (ar0*LDK + ac0*8)*2, A + (m0 + ar0)*FD + kt + ac0*8);
        cp16(base + (ar1*LDK + ac0*8)*2, A + (m0 + ar1)*FD + kt + ac0*8);
        cp16(base + (A_P + br*LDK + ac0*8)*2, wfT + (n0 + br)*FD + kt + ac0*8);
        cp16(base + (A_P + B_P + br*LDK + ac0*8)*2, wfT + HID*FD + (n0 + br)*FD + kt + ac0*8);
        CP_COMMIT();
    };
    load_stage(0); load_stage(1); load_stage(2);

    uint32_t q_row = (uint32_t)(lane & 15), q_koff = (uint32_t)(lane >> 4) * 8;

    #pragma unroll
    for (int t = 0; t < 4; t++) {
        if (t <= 1)      { CP_WAIT(2); }
        else if (t == 2) { CP_WAIT(1); }
        else             { CP_WAIT(0); }
        __syncthreads();
        if (t + 3 < 4) load_stage(t + 3);

        uint32_t sa_u = s_u + (uint32_t)(t & 3) * (PR_STG*2);
        uint32_t sb0  = sa_u + A_P*2;
        uint32_t sb1  = sb0 + B_P*2;
        #pragma unroll
        for (int kk = 0; kk < 32; kk += 16) {
            uint32_t afr[2][4], b0f[2][4], b1f[2][4];
            #pragma unroll
            for (int mi = 0; mi < 2; mi++)
                ldm_x4(afr[mi], sa_u + (((uint32_t)wm + mi*16 + q_row)*LDK + kk + q_koff)*2);
            #pragma unroll
            for (int nj = 0; nj < 2; nj++) {
                ldm_x4(b0f[nj], sb0 + (((uint32_t)wn + nj*16 + q_row)*LDK + kk + q_koff)*2);
                ldm_x4(b1f[nj], sb1 + (((uint32_t)wn + nj*16 + q_row)*LDK + kk + q_koff)*2);
            }
            #pragma unroll
            for (int mi = 0; mi < 2; mi++)
                #pragma unroll
                for (int ni = 0; ni < 4; ni++) {
                    mma16816(d0[mi][ni], afr[mi], b0f[ni>>1][ni&1], b0f[ni>>1][(ni&1)+2]);
                    mma16816(d1[mi][ni], afr[mi], b1f[ni>>1][ni&1], b1f[ni>>1][(ni&1)+2]);
                }
        }
    }
    __syncthreads();

    float* red = (float*)sh_;
    for (int i = tid; i < 128*3; i += 256) red[i] = 0.f;
    __syncthreads();

    int qr = lane >> 2;
    int qc = (lane & 3) * 2;
    const float* bf0 = bf;
    const float* bf1 = bf + HID;
    const __half* hl0 = hl;
    const __half* hl1 = hl + (size_t)HW*HID;
    #pragma unroll
    for (int mi = 0; mi < 2; mi++) {
        #pragma unroll
        for (int rh = 0; rh < 2; rh++) {
            int rloc = wm + mi*16 + rh*8 + qr;
            long long r  = m0 + rloc;
            long long rb = r & (HW - 1);
            float p0 = 0.f, p1 = 0.f, p2 = 0.f;
            #pragma unroll
            for (int ni = 0; ni < 4; ni++) {
                long long c = n0 + wn + ni*8 + qc;
                float u0 = d0[mi][ni][rh*2+0];
                float u1 = d0[mi][ni][rh*2+1];
                float2 b2 = *(const float2*)(bf0 + c);
                float2 h2 = __half22float2(*(const __half2*)(hl0 + rb*HID + c));
                u0 = fmaxf(u0 + b2.x + h2.x, 0.f);
                u1 = fmaxf(u1 + b2.y + h2.y, 0.f);
                const float* w0 = outW + c*3;
                p0 += u0*w0[0] + u1*w0[3];
                p1 += u0*w0[1] + u1*w0[4];
                p2 += u0*w0[2] + u1*w0[5];
                *(__half2*)(m0h + r*HID + c) = __floats2half2_rn(u0, u1);
                float v0 = d1[mi][ni][rh*2+0];
                float v1 = d1[mi][ni][rh*2+1];
                float2 b3 = *(const float2*)(bf1 + c);
                float2 h3 = __half22float2(*(const __half2*)(hl1 + rb*HID + c));
                v0 = fmaxf(v0 + b3.x + h3.x, 0.f) + u0;
                v1 = fmaxf(v1 + b3.y + h3.y, 0.f) + u1;
                *(__half2*)(s1h + r*HID + c) = __floats2half2_rn(v0, v1);
            }
            #pragma unroll
            for (int o = 1; o < 4; o <<= 1) {
                p0 += __shfl_xor_sync(0xffffffffu, p0, o);
                p1 += __shfl_xor_sync(0xffffffffu, p1, o);
                p2 += __shfl_xor_sync(0xffffffffu, p2, o);
            }
            if ((lane & 3) == 0) {
                atomicAdd(&red[rloc*3+0], p0);
                atomicAdd(&red[rloc*3+1], p1);
                atomicAdd(&red[rloc*3+2], p2);
            }
        }
    }
    __syncthreads();
    for (int i = tid; i < 128*3; i += 256)
        atomicAdd(&total[(m0 + (i/3))*3 + (i%3)], red[i]);
}

// ================= fused bias =================
__global__ void bf_k(const float* __restrict__ bo, const float* __restrict__ modW,
                     const float* __restrict__ modb, float* __restrict__ bf)
{
    int i = blockIdx.x;
    int n = threadIdx.x;
    const float* Wm = modW + (size_t)i*HID*HID;
    float s = modb[i*HID + n];
    for (int k = 0; k < HID; k++) s += bo[k] * Wm[(size_t)k*HID + n];
    bf[i*HID + n] = s;
}

// ================= HMMA attention =================
#define AT_QSTR 72
#define AT_KSTR 72
#define AT_VSTR 264
#define AT_PSTR 264
#define AT_SMEM ((128*AT_QSTR + 256*AT_KSTR + 64*AT_VSTR + 128*AT_PSTR)*2)
__global__ __launch_bounds__(256)
void attn_mma_k(const __half* __restrict__ qh, const __half* __restrict__ kvh,
                const float* __restrict__ tv, __half* __restrict__ out)
{
    extern __shared__ __half sm[];
    __half* sQ = sm;
    __half* sK = sQ + 128*AT_QSTR;
    __half* sV = sK + 256*AT_KSTR;
    __half* sP = sV + 64*AT_VSTR;
    int tid = threadIdx.x, wid = tid >> 5, lane = tid & 31;
    int h = blockIdx.y, b = blockIdx.z;
    long long q0 = (long long)blockIdx.x * 128;
    const __half* kvb = kvh + (size_t)b*NTOK*256;

    for (int idx = tid; idx < 1024; idx += 256) {
        int r = idx >> 3, c8 = idx & 7;
        *(uint4*)(sQ + r*AT_QSTR + c8*8) = *(const uint4*)(qh + (q0 + r)*FD + h*64 + c8*8);
    }
    for (int idx = tid; idx < 2048; idx += 256) {
        int t = idx >> 3, c8 = idx & 7;
        *(uint4*)(sK + t*AT_KSTR + c8*8) = *(const uint4*)(kvb + t*256 + h*64 + c8*8);
    }
    for (int idx = tid; idx < NTOK*64; idx += 256) {
        int t = idx >> 6, dd = idx & 63;
        sV[dd*AT_VSTR + t] = kvb[t*256 + 128 + h*64 + dd];
    }
    __syncthreads();

    uint32_t sQu = smem_u32(sQ), sKu = smem_u32(sK), sVu = smem_u32(sV), sPu = smem_u32(sP);

    float s[32][4];
    #pragma unroll
    for (int ni = 0; ni < 32; ni++)
        #pragma unroll
        for (int q = 0; q < 4; q++) s[ni][q] = 0.f;

    uint32_t a_row = (uint32_t)(wid*16 + (lane & 15)), a_koff = (uint32_t)(lane >> 4) * 8;
    uint32_t q_row = (uint32_t)(lane & 15), q_koff = (uint32_t)(lane >> 4) * 8;
    #pragma unroll
    for (int kk = 0; kk < 64; kk += 16) {
        uint32_t afr[4];
        ldm_x4(afr, sQu + (a_row*AT_QSTR + kk + a_koff)*2);
        #pragma unroll
        for (int nj = 0; nj < 16; nj++) {
            uint32_t bfr[4];
            ldm_x4(bfr, sKu + (((uint32_t)nj*16 + q_row)*AT_KSTR + kk + q_koff)*2);
            mma16816(s[nj*2],   afr, bfr[0], bfr[2]);
            mma16816(s[nj*2+1], afr, bfr[1], bfr[3]);
        }
    }

    int rq = wid*16 + (lane >> 2);
    float tq0 = tv[q0 + rq];
    float tq1 = tv[q0 + rq + 8];
    float mx0 = -1e30f, mx1 = -1e30f;
    #pragma unroll
    for (int ni = 0; ni < 32; ni++) {
        #pragma unroll
        for (int c = 0; c < 2; c++) {
            float pos = ((float)(ni*8 + (lane & 3)*2 + c) + 0.5f) * (1.0f/256.0f);
            float d0 = tq0 - pos, d1 = tq1 - pos;
            s[ni][c]   = s[ni][c]*0.125f   - 10.0f*d0*d0;
            s[ni][c+2] = s[ni][c+2]*0.125f - 10.0f*d1*d1;
            mx0 = fmaxf(mx0, s[ni][c]);
            mx1 = fmaxf(mx1, s[ni][c+2]);
        }
    }
    #pragma unroll
    for (int o = 1; o < 4; o <<= 1) {
        mx0 = fmaxf(mx0, __shfl_xor_sync(0xffffffffu, mx0, o));
        mx1 = fmaxf(mx1, __shfl_xor_sync(0xffffffffu, mx1, o));
    }
    float den0 = 0.f, den1 = 0.f;
    #pragma unroll
    for (int ni = 0; ni < 32; ni++) {
        #pragma unroll
        for (int c = 0; c < 2; c++) {
            s[ni][c]   = __expf(s[ni][c]   - mx0);
            s[ni][c+2] = __expf(s[ni][c+2] - mx1);
            den0 += s[ni][c];
            den1 += s[ni][c+2];
        }
    }
    #pragma unroll
    for (int o = 1; o < 4; o <<= 1) {
        den0 += __shfl_xor_sync(0xffffffffu, den0, o);
        den1 += __shfl_xor_sync(0xffffffffu, den1, o);
    }
    float inv0 = 1.0f / den0, inv1 = 1.0f / den1;
    int cbase = (lane & 3)*2;
    #pragma unroll
    for (int ni = 0; ni < 32; ni++) {
        *(__half2*)(sP + rq*AT_PSTR + ni*8 + cbase) =
            __floats2half2_rn(s[ni][0]*inv0, s[ni][1]*inv0);
        *(__half2*)(sP + (rq+8)*AT_PSTR + ni*8 + cbase) =
            __floats2half2_rn(s[ni][2]*inv1, s[ni][3]*inv1);
    }
    __syncthreads();

    float o[8][4];
    #pragma unroll
    for (int nj = 0; nj < 8; nj++)
        #pragma unroll
        for (int q = 0; q < 4; q++) o[nj][q] = 0.f;

    #pragma unroll
    for (int kk = 0; kk < 256; kk += 16) {
        uint32_t afr[4];
        ldm_x4(afr, sPu + (a_row*AT_PSTR + kk + a_koff)*2);
        #pragma unroll
        for (int nj = 0; nj < 4; nj++) {
            uint32_t bfr[4];
            ldm_x4(bfr, sVu + (((uint32_t)nj*16 + q_row)*AT_VSTR + kk + q_koff)*2);
            mma16816(o[nj*2],   afr, bfr[0], bfr[2]);
            mma16816(o[nj*2+1], afr, bfr[1], bfr[3]);
        }
    }

    long long qi0 = q0 + rq;
    __half* op0 = out + ((size_t)b*HW + qi0)*FD + h*64;
    __half* op1 = op0 + (size_t)8*FD;
    #pragma unroll
    for (int nj = 0; nj < 8; nj++) {
        *(__half2*)(op0 + nj*8 + cbase) = __floats2half2_rn(o[nj][0], o[nj][1]);
        *(__half2*)(op1 + nj*8 + cbase) = __floats2half2_rn(o[nj][2], o[nj][3]);
    }
}

// ================= launch =================
extern "C" void kernel_launch(void* const* d_in, const int* in_sizes, int n_in,
                              void* d_out, int out_size)
{
    const float* x      = (const float*)d_in[0];
    const float* tokens = (const float*)d_in[1];
    const float* qW     = (const float*)d_in[2];
    const float* qb     = (const float*)d_in[3];
    const float* Wq     = (const float*)d_in[4];
    const float* Wkv    = (const float*)d_in[5];
    const float* Wo     = (const float*)d_in[6];
    const float* bo     = (const float*)d_in[7];
    const float* bwW    = (const float*)d_in[8];
    const float* bwb    = (const float*)d_in[9];
    const float* modW   = (const float*)d_in[10];
    const float* modb   = (const float*)d_in[11];
    const float* hvW    = (const float*)d_in[12];
    const float* hvb    = (const float*)d_in[13];
    const float* outW   = (const float*)d_in[14];
    const float* outb   = (const float*)d_in[15];
    float* total = (float*)d_out;

    __half *gqh, *glh, *xqh, *qh, *kvh, *attnh, *s1h, *m0h, *g2h, *tokh, *hlh;
    __half *qWT, *WqT, *WkvT, *bwWT, *modWT, *hvWT, *WoA, *wfT;
    float *tv, *bfp;
    cudaGetSymbolAddress((void**)&gqh,   g_gq_h);
    cudaGetSymbolAddress((void**)&glh,   g_gl_h);
    cudaGetSymbolAddress((void**)&xqh,   g_xq_h);
    cudaGetSymbolAddress((void**)&qh,    g_q_h);
    cudaGetSymbolAddress((void**)&kvh,   g_kv_h);
    cudaGetSymbolAddress((void**)&attnh, g_attn_h);
    cudaGetSymbolAddress((void**)&s1h,   g_s_h);
    cudaGetSymbolAddress((void**)&m0h,   g_m0_h);
    cudaGetSymbolAddress((void**)&g2h,   g_g2_h);
    cudaGetSymbolAddress((void**)&tokh,  g_tok_h);
    cudaGetSymbolAddress((void**)&hlh,   g_hl_h);
    cudaGetSymbolAddress((void**)&qWT,   g_qWT);
    cudaGetSymbolAddress((void**)&WqT,   g_WqT);
    cudaGetSymbolAddress((void**)&WkvT,  g_WkvT);
    cudaGetSymbolAddress((void**)&bwWT,  g_bwWT);
    cudaGetSymbolAddress((void**)&modWT, g_modWT);
    cudaGetSymbolAddress((void**)&hvWT,  g_hvWT);
    cudaGetSymbolAddress((void**)&WoA,   g_WoA);
    cudaGetSymbolAddress((void**)&wfT,   g_wfT);
    cudaGetSymbolAddress((void**)&tv,    g_tv);
    cudaGetSymbolAddress((void**)&bfp,   g_bf);

    cudaFuncSetAttribute(tgemm<true,false,false,false,4>,  cudaFuncAttributeMaxDynamicSharedMemorySize, TG_SMEM);
    cudaFuncSetAttribute(tgemm<false,false,false,false,16>,cudaFuncAttributeMaxDynamicSharedMemorySize, TG_SMEM);
    cudaFuncSetAttribute(tgemm<true,true,false,false,4>,   cudaFuncAttributeMaxDynamicSharedMemorySize, TG_SMEM);
    cudaFuncSetAttribute(tgemm<true,false,true,true,16>,   cudaFuncAttributeMaxDynamicSharedMemorySize, TG_SMEM);
    cudaFuncSetAttribute(tgemm<true,false,false,true,16>,  cudaFuncAttributeMaxDynamicSharedMemorySize, TG_SMEM);
    cudaFuncSetAttribute(pairgemm, cudaFuncAttributeMaxDynamicSharedMemorySize, PR_SMEM);
    cudaFuncSetAttribute(attn_mma_k, cudaFuncAttributeMaxDynamicSharedMemorySize, AT_SMEM);

    // 1) gamma  2) prep  3) bf
    gamma_k<<<HW, 128>>>(x, gqh, glh, tv);
    prep_k<<<(int)((PREP_TOTAL + 255)/256), 256>>>(
        qW, Wq, Wkv, bwW, modW, hvW, Wo, tokens, outb,
        qWT, WqT, WkvT, bwWT, modWT, hvWT, WoA, tokh, total);
    bf_k<<<3, HID>>>(bo, modW, modb, bfp);

    // 4) xq = relu(gq @ qW + qb) -> fp16
    tgemm<true,false,false,false,4><<<dim3(8,128), 256, TG_SMEM>>>(
        gqh, qWT, qb, nullptr, nullptr, xqh, nullptr, nullptr, nullptr, HW, HID);

    // 5) kv = tokens @ Wkv -> fp16
    tgemm<false,false,false,false,16><<<dim3(4,16), 256, TG_SMEM>>>(
        tokh, WkvT, nullptr, nullptr, nullptr, kvh, nullptr, nullptr, nullptr, NB*NTOK, 256);

    // 6-8) h_l[i] -> fp16
    for (int i = 0; i < 3; i++)
        tgemm<true,false,false,false,4><<<dim3(8,128), 256, TG_SMEM>>>(
            glh + (size_t)i*HW*FD, bwWT + (size_t)i*HID*FD, bwb + i*HID,
            nullptr, nullptr, hlh + (size_t)i*HW*HID, nullptr, nullptr, nullptr, HW, HID);

    // 9) q = xq @ Wq -> fp16
    tgemm<false,false,false,false,16><<<dim3(2,128), 256, TG_SMEM>>>(
        xqh, WqT, nullptr, nullptr, nullptr, qh, nullptr, nullptr, nullptr, HW, FD);

    // 10-12) wfT[i] = (Wo @ modW[i])^T -> fp16 [512][128]
    for (int i = 0; i < 3; i++)
        tgemm<false,false,false,false,16><<<dim3(8,1), 256, TG_SMEM>>>(
            WoA, modWT + (size_t)i*HID*HID, nullptr, nullptr, nullptr,
            nullptr, wfT + (size_t)i*HID*FD, nullptr, nullptr, FD, HID);

    // 13) attention
    attn_mma_k<<<dim3(HW/128, 2, NB), 256, AT_SMEM>>>(qh, kvh, tv, attnh);

    // 14) G2 = relu(attn@wf2 + bf2 + hl2) -> g2h
    tgemm<true,true,false,false,4><<<dim3(8,1024), 256, TG_SMEM>>>(
        attnh, wfT + 2*HID*FD, bfp + 2*HID, hlh + 2ull*HW*HID, nullptr,
        g2h, nullptr, nullptr, nullptr, MROWS, HID);

    // 15) pair: m0h (+outproj outW0) and s1h
    pairgemm<<<dim3(8,1024), 256, PR_SMEM>>>(
        attnh, wfT, bfp, hlh, m0h, s1h, outW, total);

    // 16) HV1: relu(s1@hvW0 + hvb0); total += HV1@outW1; +g2 -> s2 (into m0h)
    tgemm<true,false,true,true,16><<<dim3(8,1024), 256, TG_SMEM>>>(
        s1h, hvWT, hvb, nullptr, g2h, m0h, nullptr,
        outW + 512*3, total, MROWS, HID);

    // 17) HV2: relu(s2@hvW1 + hvb1); total += HV2@outW2
    tgemm<true,false,false,true,16><<<dim3(8,1024), 256, TG_SMEM>>>(
        m0h, hvWT + (size_t)HID*HID, hvb + HID, nullptr, nullptr, nullptr,
        nullptr, outW + 2*512*3, total, MROWS, HID);
}

// round 10
// speedup vs baseline: 1.6015x; 1.6015x over previous
#include <cuda_runtime.h>
#include <cuda_fp16.h>
#include <math.h>
#include <stdint.h>

#define HW 16384
#define NB 8
#define MROWS (NB*HW)      // 131072
#define HID 512
#define FD 128
#define NTOK 256
#define PI_D 3.14159265358979323846

// ---------------- fp16 buffers ----------------
__device__ __half g_gq_h[HW*FD];
__device__ __half g_gl_h[3ull*HW*FD];
__device__ __half g_xq_h[HW*HID];
__device__ __half g_q_h[HW*FD];
__device__ __half g_kv_h[NB*NTOK*256];
__device__ __half g_attn_h[(unsigned long long)MROWS*FD];
__device__ __half g_s_h[(unsigned long long)MROWS*HID];   // S1
__device__ __half g_m0_h[(unsigned long long)MROWS*HID];  // M0, reused as S2
__device__ __half g_g2_h[(unsigned long long)MROWS*HID];  // reluG2
__device__ __half g_tok_h[NB*NTOK*HID];
__device__ __half g_hl_h[3ull*HW*HID];
__device__ __half g_qWT[HID*FD];
__device__ __half g_WqT[FD*HID];
__device__ __half g_WkvT[256*HID];
__device__ __half g_bwWT[3*HID*FD];
__device__ __half g_modWT[3*HID*HID];
__device__ __half g_hvWT[2*HID*HID];
__device__ __half g_WoA[FD*HID];
__device__ __half g_wfT[3*HID*FD];
// ---------------- fp32 buffers ----------------
__device__ float g_tv[HW];
__device__ float g_bf[3*HID];

// ================= helpers =================
__device__ __forceinline__ uint32_t smem_u32(const void* p) {
    uint32_t a;
    asm("{ .reg .u64 t; cvta.to.shared.u64 t, %1; cvt.u32.u64 %0, t; }" : "=r"(a) : "l"(p));
    return a;
}
__device__ __forceinline__ void ldm_x4(uint32_t* r, uint32_t addr) {
    asm volatile("ldmatrix.sync.aligned.m8n8.x4.shared.b16 {%0,%1,%2,%3}, [%4];"
                 : "=r"(r[0]), "=r"(r[1]), "=r"(r[2]), "=r"(r[3]) : "r"(addr));
}
__device__ __forceinline__ void mma16816(float* d, const uint32_t* a, uint32_t b0, uint32_t b1) {
    asm volatile(
        "mma.sync.aligned.m16n8k16.row.col.f32.f16.f16.f32 "
        "{%0,%1,%2,%3}, {%4,%5,%6,%7}, {%8,%9}, {%0,%1,%2,%3};"
        : "+f"(d[0]), "+f"(d[1]), "+f"(d[2]), "+f"(d[3])
        : "r"(a[0]), "r"(a[1]), "r"(a[2]), "r"(a[3]), "r"(b0), "r"(b1));
}
__device__ __forceinline__ void cp16(uint32_t dst, const void* src) {
    asm volatile("cp.async.cg.shared.global [%0], [%1], 16;" :: "r"(dst), "l"(src));
}
#define CP_COMMIT() asm volatile("cp.async.commit_group;" ::: "memory")
#define CP_WAIT1()  asm volatile("cp.async.wait_group 1;" ::: "memory")
#define CP_WAIT0()  asm volatile("cp.async.wait_group 0;" ::: "memory")

// ================= Fourier features =================
__global__ void gamma_k(const float* __restrict__ x, __half* __restrict__ gq,
                        __half* __restrict__ gl, float* __restrict__ tv)
{
    __shared__ double omg[128];
    int q = blockIdx.x;
    int f = threadIdx.x;
    {
        const double sig[4] = {128.0, 16.0, 64.0, 256.0};
        int s = f >> 5, j = f & 31;
        double step = (log10(sig[s]) - 1.0) / 31.0;
        omg[f] = pow(10.0, 1.0 + (double)j * step);
    }
    __syncthreads();

    float c0 = x[2*q], c1 = x[2*q+1];
    if (f == 0) {
        int r  = (int)(c0 * 16.0f);
        int cc = (int)(c1 * 16.0f);
        tv[q] = (float)(r*16 + cc) * (1.0f/256.0f);
    }
    int d = f >> 6;
    int rr = f & 63;
    int part = rr >> 5;
    int j = rr & 31;
    double coord = d ? (double)c1 : (double)c0;
    #pragma unroll
    for (int s = 0; s < 4; s++) {
        double arg = PI_D * coord * omg[s*32 + j];
        float val = (float)(part ? cos(arg) : sin(arg));
        __half* dst = (s == 0) ? gq : (gl + (size_t)(s-1)*HW*FD);
        dst[(size_t)q*FD + f] = __float2half_rn(val);
    }
}

// ================= merged weight prep =================
__global__ void prep_k(const float* __restrict__ qW, const float* __restrict__ Wq,
                       const float* __restrict__ Wkv, const float* __restrict__ bwW,
                       const float* __restrict__ modW, const float* __restrict__ hvW,
                       const float* __restrict__ Wo, const float* __restrict__ tokens,
                       const float* __restrict__ outb,
                       __half* __restrict__ qWT, __half* __restrict__ WqT,
                       __half* __restrict__ WkvT, __half* __restrict__ bwWT,
                       __half* __restrict__ modWT, __half* __restrict__ hvWT,
                       __half* __restrict__ WoA, __half* __restrict__ tokh,
                       float* __restrict__ total)
{
    long long i = (long long)blockIdx.x * 256 + threadIdx.x;
    if (i < 65536) {
        int k = (int)(i/512), n = (int)(i%512);
        qWT[n*128+k] = __float2half_rn(qW[i]); return;
    } i -= 65536;
    if (i < 65536) {
        int k = (int)(i/128), n = (int)(i%128);
        WqT[n*512+k] = __float2half_rn(Wq[i]); return;
    } i -= 65536;
    if (i < 131072) {
        int k = (int)(i/256), n = (int)(i%256);
        WkvT[n*512+k] = __float2half_rn(Wkv[i]); return;
    } i -= 131072;
    if (i < 196608) {
        int s = (int)(i/65536); long long j = i%65536;
        int k = (int)(j/512), n = (int)(j%512);
        bwWT[s*65536 + n*128+k] = __float2half_rn(bwW[i]); return;
    } i -= 196608;
    if (i < 786432) {
        int s = (int)(i/262144); long long j = i%262144;
        int k = (int)(j/512), n = (int)(j%512);
        modWT[s*262144 + n*512+k] = __float2half_rn(modW[i]); return;
    } i -= 786432;
    if (i < 524288) {
        int s = (int)(i/262144); long long j = i%262144;
        int k = (int)(j/512), n = (int)(j%512);
        hvWT[s*262144 + n*512+k] = __float2half_rn(hvW[i]); return;
    } i -= 524288;
    if (i < 65536) { WoA[i] = __float2half_rn(Wo[i]); return; } i -= 65536;
    if (i < 1048576) { tokh[i] = __float2half_rn(tokens[i]); return; } i -= 1048576;
    if (i < (long long)MROWS*3) {
        int c = (int)(i % 3);
        total[i] = outb[c] + outb[3+c] + outb[6+c];
    }
}
#define PREP_TOTAL 3276800LL

// ================= HMMA fp16 GEMM (round-8 core + staged stores) =================
// CTA tile 128(M) x 64(N), K-chunk 64, 2-stage cp.async pipeline, K=KT*64.
// 8 warps 4(row) x 2(col); warp tile 32x32.
// epi: (+bias f32) (+bch[(r&16383),N] fp16) (relu) OUTP(total += v.outWsel) (+af fp16)
//      -> Ch (staged, coalesced) / CTh (scattered, small only)
#define LDK 72
#define A_PANEL (128*LDK)
#define B_PANEL (64*LDK)
#define STG (A_PANEL + B_PANEL)
#define TG_SMEM (2*STG*2)          // 55296 B
template<bool RELU, bool BCAST, bool ADDF, bool OUTP, int KT>
__global__ __launch_bounds__(256, 3)
void tgemm(const __half* __restrict__ A, const __half* __restrict__ WT,
           const float* __restrict__ bias, const __half* __restrict__ bch,
           const __half* __restrict__ af,
           __half* __restrict__ Ch, __half* __restrict__ CTh,
           const float* __restrict__ outWsel, float* __restrict__ total,
           int M, int N)
{
    const int K = KT*64;
    extern __shared__ __half sh_[];
    int tid = threadIdx.x, wid = tid >> 5, lane = tid & 31;
    long long m0 = (long long)blockIdx.y * 128;
    long long n0 = (long long)blockIdx.x * 64;
    int wm = (wid & 3) * 32;
    int wn = (wid >> 2) * 32;

    float d[2][4][4];
    #pragma unroll
    for (int mi = 0; mi < 2; mi++)
        #pragma unroll
        for (int ni = 0; ni < 4; ni++)
            #pragma unroll
            for (int q = 0; q < 4; q++) d[mi][ni][q] = 0.f;

    uint32_t s_u = smem_u32(sh_);
    int lr[4], lc[4];
    #pragma unroll
    for (int it = 0; it < 4; it++) {
        int idx = tid + it*256;
        lr[it] = idx >> 3;
        lc[it] = idx & 7;
    }

    auto load_stage = [&](int t) {
        uint32_t base = s_u + (uint32_t)(t & 1) * (STG*2);
        int kt = t << 6;
        #pragma unroll
        for (int it = 0; it < 4; it++)
            cp16(base + (lr[it]*LDK + lc[it]*8)*2, A + (m0 + lr[it])*(long long)K + kt + lc[it]*8);
        #pragma unroll
        for (int it = 0; it < 2; it++)
            cp16(base + (A_PANEL + lr[it]*LDK + lc[it]*8)*2, WT + (n0 + lr[it])*(long long)K + kt + lc[it]*8);
        CP_COMMIT();
    };

    load_stage(0);

    uint32_t q_row = (uint32_t)(lane & 15), q_koff = (uint32_t)(lane >> 4) * 8;

    #pragma unroll
    for (int t = 0; t < KT; t++) {
        if (t + 1 < KT) { load_stage(t + 1); CP_WAIT1(); }
        else            { CP_WAIT0(); }
        __syncthreads();

        uint32_t sa_u = s_u + (uint32_t)(t & 1) * (STG*2);
        uint32_t sb_u = sa_u + A_PANEL*2;
        #pragma unroll
        for (int kk = 0; kk < 64; kk += 16) {
            uint32_t afr[2][4], bfr[2][4];
            #pragma unroll
            for (int mi = 0; mi < 2; mi++)
                ldm_x4(afr[mi], sa_u + (((uint32_t)wm + mi*16 + q_row)*LDK + kk + q_koff)*2);
            #pragma unroll
            for (int nj = 0; nj < 2; nj++)
                ldm_x4(bfr[nj], sb_u + (((uint32_t)wn + nj*16 + q_row)*LDK + kk + q_koff)*2);
            #pragma unroll
            for (int mi = 0; mi < 2; mi++)
                #pragma unroll
                for (int ni = 0; ni < 4; ni++)
                    mma16816(d[mi][ni], afr[mi], bfr[ni>>1][ni&1], bfr[ni>>1][(ni&1)+2]);
        }
        __syncthreads();
    }

    // staging region: 128 x 72 halves at sh_[0]; red after it
    __half* stg = sh_;
    float* red = (float*)((char*)sh_ + 20480);
    if (OUTP) {
        for (int i = tid; i < 128*3; i += 256) red[i] = 0.f;
        __syncthreads();
    }

    int qr = lane >> 2;
    int qc = (lane & 3) * 2;
    #pragma unroll
    for (int mi = 0; mi < 2; mi++) {
        #pragma unroll
        for (int rh = 0; rh < 2; rh++) {
            int rloc = wm + mi*16 + rh*8 + qr;
            long long r  = m0 + rloc;
            long long rb_ = BCAST ? (r & (HW - 1)) : r;
            float p0 = 0.f, p1 = 0.f, p2 = 0.f;
            #pragma unroll
            for (int ni = 0; ni < 4; ni++) {
                int cloc = wn + ni*8 + qc;
                long long c = n0 + cloc;
                float v0 = d[mi][ni][rh*2+0];
                float v1 = d[mi][ni][rh*2+1];
                if (bias) {
                    float2 b2 = *(const float2*)(bias + c);
                    v0 += b2.x; v1 += b2.y;
                }
                if (BCAST) {
                    float2 b2 = __half22float2(*(const __half2*)(bch + rb_*(long long)N + c));
                    v0 += b2.x; v1 += b2.y;
                }
                if (RELU) { v0 = fmaxf(v0, 0.f); v1 = fmaxf(v1, 0.f); }
                if (OUTP) {
                    const float* w0 = outWsel + c*3;
                    p0 += v0*w0[0] + v1*w0[3];
                    p1 += v0*w0[1] + v1*w0[4];
                    p2 += v0*w0[2] + v1*w0[5];
                }
                if (ADDF) {
                    float2 af2 = __half22float2(*(const __half2*)(af + r*(long long)N + c));
                    v0 += af2.x; v1 += af2.y;
                }
                if (Ch) *(__half2*)(stg + rloc*LDK + cloc) = __floats2half2_rn(v0, v1);
                if (CTh) {
                    CTh[c*(long long)M + r]     = __float2half_rn(v0);
                    CTh[(c+1)*(long long)M + r] = __float2half_rn(v1);
                }
            }
            if (OUTP) {
                #pragma unroll
                for (int o = 1; o < 4; o <<= 1) {
                    p0 += __shfl_xor_sync(0xffffffffu, p0, o);
                    p1 += __shfl_xor_sync(0xffffffffu, p1, o);
                    p2 += __shfl_xor_sync(0xffffffffu, p2, o);
                }
                if ((lane & 3) == 0) {
                    atomicAdd(&red[rloc*3+0], p0);
                    atomicAdd(&red[rloc*3+1], p1);
                    atomicAdd(&red[rloc*3+2], p2);
                }
            }
        }
    }
    __syncthreads();
    if (Ch) {
        #pragma unroll
        for (int it = 0; it < 4; it++) {
            int c = tid + it*256;           // 1024 uint4 chunks
            int row = c >> 3, off = (c & 7) * 8;
            *(uint4*)(Ch + (m0 + row)*(long long)N + n0 + off) = *(const uint4*)(stg + row*LDK + off);
        }
    }
    if (OUTP) {
        for (int i = tid; i < 128*3; i += 256)
            atomicAdd(&total[(m0 + (i/3))*3 + (i%3)], red[i]);
    }
}

// ================= pair-band GEMM: G0 + G1 share A (K=128) =================
#define PR_STG (A_PANEL + 2*B_PANEL)         // 18432 halves
#define PR_SMEM (2*PR_STG*2)                 // 73728 B
__global__ __launch_bounds__(256, 2)
void pairgemm(const __half* __restrict__ A, const __half* __restrict__ wfT,
              const float* __restrict__ bf, const __half* __restrict__ hl,
              __half* __restrict__ m0h, __half* __restrict__ s1h,
              const float* __restrict__ outW, float* __restrict__ total)
{
    extern __shared__ __half sh_[];
    int tid = threadIdx.x, wid = tid >> 5, lane = tid & 31;
    long long m0 = (long long)blockIdx.y * 128;
    long long n0 = (long long)blockIdx.x * 64;
    int wm = (wid & 3) * 32;
    int wn = (wid >> 2) * 32;
    uint32_t s_u = smem_u32(sh_);

    float d0[2][4][4], d1[2][4][4];
    #pragma unroll
    for (int mi = 0; mi < 2; mi++)
        #pragma unroll
        for (int ni = 0; ni < 4; ni++)
            #pragma unroll
            for (int q = 0; q < 4; q++) { d0[mi][ni][q] = 0.f; d1[mi][ni][q] = 0.f; }

    int lr[4], lc[4];
    #pragma unroll
    for (int it = 0; it < 4; it++) {
        int idx = tid + it*256;
        lr[it] = idx >> 3;
        lc[it] = idx & 7;
    }

    auto load_stage = [&](int t) {
        uint32_t base = s_u + (uint32_t)(t & 1) * (PR_STG*2);
        int kt = t << 6;
        #pragma unroll
        for (int it = 0; it < 4; it++)
            cp16(base + (lr[it]*LDK + lc[it]*8)*2, A + (m0 + lr[it])*FD + kt + lc[it]*8);
        #pragma unroll
        for (int it = 0; it < 2; it++) {
            cp16(base + (A_PANEL + lr[it]*LDK + lc[it]*8)*2, wfT + (n0 + lr[it])*FD + kt + lc[it]*8);
            cp16(base + (A_PANEL + B_PANEL + lr[it]*LDK + lc[it]*8)*2,
                 wfT + HID*FD + (n0 + lr[it])*FD + kt + lc[it]*8);
        }
        CP_COMMIT();
    };
    load_stage(0);

    uint32_t q_row = (uint32_t)(lane & 15), q_koff = (uint32_t)(lane >> 4) * 8;

    #pragma unroll
    for (int t = 0; t < 2; t++) {
        if (t == 0) { load_stage(1); CP_WAIT1(); } else { CP_WAIT0(); }
        __syncthreads();
        uint32_t sa_u = s_u + (uint32_t)(t & 1) * (PR_STG*2);
        uint32_t sb0  = sa_u + A_PANEL*2;
        uint32_t sb1  = sb0 + B_PANEL*2;
        #pragma unroll
        for (int kk = 0; kk < 64; kk += 16) {
            uint32_t afr[2][4], b0f[2][4], b1f[2][4];
            #pragma unroll
            for (int mi = 0; mi < 2; mi++)
                ldm_x4(afr[mi], sa_u + (((uint32_t)wm + mi*16 + q_row)*LDK + kk + q_koff)*2);
            #pragma unroll
            for (int nj = 0; nj < 2; nj++) {
                ldm_x4(b0f[nj], sb0 + (((uint32_t)wn + nj*16 + q_row)*LDK + kk + q_koff)*2);
                ldm_x4(b1f[nj], sb1 + (((uint32_t)wn + nj*16 + q_row)*LDK + kk + q_koff)*2);
            }
            #pragma unroll
            for (int mi = 0; mi < 2; mi++)
                #pragma unroll
                for (int ni = 0; ni < 4; ni++) {
                    mma16816(d0[mi][ni], afr[mi], b0f[ni>>1][ni&1], b0f[ni>>1][(ni&1)+2]);
                    mma16816(d1[mi][ni], afr[mi], b1f[ni>>1][ni&1], b1f[ni>>1][(ni&1)+2]);
                }
        }
        __syncthreads();
    }

    // staging: m0 tile at [0], s1 tile at [128*LDK], red after
    __half* stg0 = sh_;
    __half* stg1 = sh_ + 128*LDK;
    float* red = (float*)((char*)sh_ + 40960);
    for (int i = tid; i < 128*3; i += 256) red[i] = 0.f;
    __syncthreads();

    int qr = lane >> 2;
    int qc = (lane & 3) * 2;
    const float* bf0 = bf;
    const float* bf1 = bf + HID;
    const __half* hl0 = hl;
    const __half* hl1 = hl + (size_t)HW*HID;
    #pragma unroll
    for (int mi = 0; mi < 2; mi++) {
        #pragma unroll
        for (int rh = 0; rh < 2; rh++) {
            int rloc = wm + mi*16 + rh*8 + qr;
            long long r  = m0 + rloc;
            long long rb = r & (HW - 1);
            float p0 = 0.f, p1 = 0.f, p2 = 0.f;
            #pragma unroll
            for (int ni = 0; ni < 4; ni++) {
                int cloc = wn + ni*8 + qc;
                long long c = n0 + cloc;
                float u0 = d0[mi][ni][rh*2+0];
                float u1 = d0[mi][ni][rh*2+1];
                float2 b2 = *(const float2*)(bf0 + c);
                float2 h2 = __half22float2(*(const __half2*)(hl0 + rb*HID + c));
                u0 = fmaxf(u0 + b2.x + h2.x, 0.f);
                u1 = fmaxf(u1 + b2.y + h2.y, 0.f);
                const float* w0 = outW + c*3;
                p0 += u0*w0[0] + u1*w0[3];
                p1 += u0*w0[1] + u1*w0[4];
                p2 += u0*w0[2] + u1*w0[5];
                *(__half2*)(stg0 + rloc*LDK + cloc) = __floats2half2_rn(u0, u1);
                float v0 = d1[mi][ni][rh*2+0];
                float v1 = d1[mi][ni][rh*2+1];
                float2 b3 = *(const float2*)(bf1 + c);
                float2 h3 = __half22float2(*(const __half2*)(hl1 + rb*HID + c));
                v0 = fmaxf(v0 + b3.x + h3.x, 0.f) + u0;
                v1 = fmaxf(v1 + b3.y + h3.y, 0.f) + u1;
                *(__half2*)(stg1 + rloc*LDK + cloc) = __floats2half2_rn(v0, v1);
            }
            #pragma unroll
            for (int o = 1; o < 4; o <<= 1) {
                p0 += __shfl_xor_sync(0xffffffffu, p0, o);
                p1 += __shfl_xor_sync(0xffffffffu, p1, o);
                p2 += __shfl_xor_sync(0xffffffffu, p2, o);
            }
            if ((lane & 3) == 0) {
                atomicAdd(&red[rloc*3+0], p0);
                atomicAdd(&red[rloc*3+1], p1);
                atomicAdd(&red[rloc*3+2], p2);
            }
        }
    }
    __syncthreads();
    #pragma unroll
    for (int it = 0; it < 4; it++) {
        int c = tid + it*256;
        int row = c >> 3, off = (c & 7) * 8;
        *(uint4*)(m0h + (m0 + row)*HID + n0 + off) = *(const uint4*)(stg0 + row*LDK + off);
        *(uint4*)(s1h + (m0 + row)*HID + n0 + off) = *(const uint4*)(stg1 + row*LDK + off);
    }
    for (int i = tid; i < 128*3; i += 256)
        atomicAdd(&total[(m0 + (i/3))*3 + (i%3)], red[i]);
}

// ================= fused bias =================
__global__ void bf_k(const float* __restrict__ bo, const float* __restrict__ modW,
                     const float* __restrict__ modb, float* __restrict__ bf)
{
    int i = blockIdx.x;
    int n = threadIdx.x;
    const float* Wm = modW + (size_t)i*HID*HID;
    float s = modb[i*HID + n];
    for (int k = 0; k < HID; k++) s += bo[k] * Wm[(size_t)k*HID + n];
    bf[i*HID + n] = s;
}

// ================= HMMA attention =================
#define AT_QSTR 72
#define AT_KSTR 72
#define AT_VSTR 264
#define AT_PSTR 264
#define AT_SMEM ((128*AT_QSTR + 256*AT_KSTR + 64*AT_VSTR + 128*AT_PSTR)*2)
__global__ __launch_bounds__(256)
void attn_mma_k(const __half* __restrict__ qh, const __half* __restrict__ kvh,
                const float* __restrict__ tv, __half* __restrict__ out)
{
    extern __shared__ __half sm[];
    __half* sQ = sm;
    __half* sK = sQ + 128*AT_QSTR;
    __half* sV = sK + 256*AT_KSTR;
    __half* sP = sV + 64*AT_VSTR;
    int tid = threadIdx.x, wid = tid >> 5, lane = tid & 31;
    int h = blockIdx.y, b = blockIdx.z;
    long long q0 = (long long)blockIdx.x * 128;
    const __half* kvb = kvh + (size_t)b*NTOK*256;

    for (int idx = tid; idx < 1024; idx += 256) {
        int r = idx >> 3, c8 = idx & 7;
        *(uint4*)(sQ + r*AT_QSTR + c8*8) = *(const uint4*)(qh + (q0 + r)*FD + h*64 + c8*8);
    }
    for (int idx = tid; idx < 2048; idx += 256) {
        int t = idx >> 3, c8 = idx & 7;
        *(uint4*)(sK + t*AT_KSTR + c8*8) = *(const uint4*)(kvb + t*256 + h*64 + c8*8);
    }
    for (int idx = tid; idx < NTOK*64; idx += 256) {
        int t = idx >> 6, dd = idx & 63;
        sV[dd*AT_VSTR + t] = kvb[t*256 + 128 + h*64 + dd];
    }
    __syncthreads();

    uint32_t sQu = smem_u32(sQ), sKu = smem_u32(sK), sVu = smem_u32(sV), sPu = smem_u32(sP);

    float s[32][4];
    #pragma unroll
    for (int ni = 0; ni < 32; ni++)
        #pragma unroll
        for (int q = 0; q < 4; q++) s[ni][q] = 0.f;

    uint32_t a_row = (uint32_t)(wid*16 + (lane & 15)), a_koff = (uint32_t)(lane >> 4) * 8;
    uint32_t q_row = (uint32_t)(lane & 15), q_koff = (uint32_t)(lane >> 4) * 8;
    #pragma unroll
    for (int kk = 0; kk < 64; kk += 16) {
        uint32_t afr[4];
        ldm_x4(afr, sQu + (a_row*AT_QSTR + kk + a_koff)*2);
        #pragma unroll
        for (int nj = 0; nj < 16; nj++) {
            uint32_t bfr[4];
            ldm_x4(bfr, sKu + (((uint32_t)nj*16 + q_row)*AT_KSTR + kk + q_koff)*2);
            mma16816(s[nj*2],   afr, bfr[0], bfr[2]);
            mma16816(s[nj*2+1], afr, bfr[1], bfr[3]);
        }
    }

    int rq = wid*16 + (lane >> 2);
    float tq0 = tv[q0 + rq];
    float tq1 = tv[q0 + rq + 8];
    float mx0 = -1e30f, mx1 = -1e30f;
    #pragma unroll
    for (int ni = 0; ni < 32; ni++) {
        #pragma unroll
        for (int c = 0; c < 2; c++) {
            float pos = ((float)(ni*8 + (lane & 3)*2 + c) + 0.5f) * (1.0f/256.0f);
            float d0 = tq0 - pos, d1 = tq1 - pos;
            s[ni][c]   = s[ni][c]*0.125f   - 10.0f*d0*d0;
            s[ni][c+2] = s[ni][c+2]*0.125f - 10.0f*d1*d1;
            mx0 = fmaxf(mx0, s[ni][c]);
            mx1 = fmaxf(mx1, s[ni][c+2]);
        }
    }
    #pragma unroll
    for (int o = 1; o < 4; o <<= 1) {
        mx0 = fmaxf(mx0, __shfl_xor_sync(0xffffffffu, mx0, o));
        mx1 = fmaxf(mx1, __shfl_xor_sync(0xffffffffu, mx1, o));
    }
    float den0 = 0.f, den1 = 0.f;
    #pragma unroll
    for (int ni = 0; ni < 32; ni++) {
        #pragma unroll
        for (int c = 0; c < 2; c++) {
            s[ni][c]   = __expf(s[ni][c]   - mx0);
            s[ni][c+2] = __expf(s[ni][c+2] - mx1);
            den0 += s[ni][c];
            den1 += s[ni][c+2];
        }
    }
    #pragma unroll
    for (int o = 1; o < 4; o <<= 1) {
        den0 += __shfl_xor_sync(0xffffffffu, den0, o);
        den1 += __shfl_xor_sync(0xffffffffu, den1, o);
    }
    float inv0 = 1.0f / den0, inv1 = 1.0f / den1;
    int cbase = (lane & 3)*2;
    #pragma unroll
    for (int ni = 0; ni < 32; ni++) {
        *(__half2*)(sP + rq*AT_PSTR + ni*8 + cbase) =
            __floats2half2_rn(s[ni][0]*inv0, s[ni][1]*inv0);
        *(__half2*)(sP + (rq+8)*AT_PSTR + ni*8 + cbase) =
            __floats2half2_rn(s[ni][2]*inv1, s[ni][3]*inv1);
    }
    __syncthreads();

    float o[8][4];
    #pragma unroll
    for (int nj = 0; nj < 8; nj++)
        #pragma unroll
        for (int q = 0; q < 4; q++) o[nj][q] = 0.f;

    #pragma unroll
    for (int kk = 0; kk < 256; kk += 16) {
        uint32_t afr[4];
        ldm_x4(afr, sPu + (a_row*AT_PSTR + kk + a_koff)*2);
        #pragma unroll
        for (int nj = 0; nj < 4; nj++) {
            uint32_t bfr[4];
            ldm_x4(bfr, sVu + (((uint32_t)nj*16 + q_row)*AT_VSTR + kk + q_koff)*2);
            mma16816(o[nj*2],   afr, bfr[0], bfr[2]);
            mma16816(o[nj*2+1], afr, bfr[1], bfr[3]);
        }
    }

    long long qi0 = q0 + rq;
    __half* op0 = out + ((size_t)b*HW + qi0)*FD + h*64;
    __half* op1 = op0 + (size_t)8*FD;
    #pragma unroll
    for (int nj = 0; nj < 8; nj++) {
        *(__half2*)(op0 + nj*8 + cbase) = __floats2half2_rn(o[nj][0], o[nj][1]);
        *(__half2*)(op1 + nj*8 + cbase) = __floats2half2_rn(o[nj][2], o[nj][3]);
    }
}

// ================= launch =================
extern "C" void kernel_launch(void* const* d_in, const int* in_sizes, int n_in,
                              void* d_out, int out_size)
{
    const float* x      = (const float*)d_in[0];
    const float* tokens = (const float*)d_in[1];
    const float* qW     = (const float*)d_in[2];
    const float* qb     = (const float*)d_in[3];
    const float* Wq     = (const float*)d_in[4];
    const float* Wkv    = (const float*)d_in[5];
    const float* Wo     = (const float*)d_in[6];
    const float* bo     = (const float*)d_in[7];
    const float* bwW    = (const float*)d_in[8];
    const float* bwb    = (const float*)d_in[9];
    const float* modW   = (const float*)d_in[10];
    const float* modb   = (const float*)d_in[11];
    const float* hvW    = (const float*)d_in[12];
    const float* hvb    = (const float*)d_in[13];
    const float* outW   = (const float*)d_in[14];
    const float* outb   = (const float*)d_in[15];
    float* total = (float*)d_out;

    __half *gqh, *glh, *xqh, *qh, *kvh, *attnh, *s1h, *m0h, *g2h, *tokh, *hlh;
    __half *qWT, *WqT, *WkvT, *bwWT, *modWT, *hvWT, *WoA, *wfT;
    float *tv, *bfp;
    cudaGetSymbolAddress((void**)&gqh,   g_gq_h);
    cudaGetSymbolAddress((void**)&glh,   g_gl_h);
    cudaGetSymbolAddress((void**)&xqh,   g_xq_h);
    cudaGetSymbolAddress((void**)&qh,    g_q_h);
    cudaGetSymbolAddress((void**)&kvh,   g_kv_h);
    cudaGetSymbolAddress((void**)&attnh, g_attn_h);
    cudaGetSymbolAddress((void**)&s1h,   g_s_h);
    cudaGetSymbolAddress((void**)&m0h,   g_m0_h);
    cudaGetSymbolAddress((void**)&g2h,   g_g2_h);
    cudaGetSymbolAddress((void**)&tokh,  g_tok_h);
    cudaGetSymbolAddress((void**)&hlh,   g_hl_h);
    cudaGetSymbolAddress((void**)&qWT,   g_qWT);
    cudaGetSymbolAddress((void**)&WqT,   g_WqT);
    cudaGetSymbolAddress((void**)&WkvT,  g_WkvT);
    cudaGetSymbolAddress((void**)&bwWT,  g_bwWT);
    cudaGetSymbolAddress((void**)&modWT, g_modWT);
    cudaGetSymbolAddress((void**)&hvWT,  g_hvWT);
    cudaGetSymbolAddress((void**)&WoA,   g_WoA);
    cudaGetSymbolAddress((void**)&wfT,   g_wfT);
    cudaGetSymbolAddress((void**)&tv,    g_tv);
    cudaGetSymbolAddress((void**)&bfp,   g_bf);

    cudaFuncSetAttribute(tgemm<true,false,false,false,2>,  cudaFuncAttributeMaxDynamicSharedMemorySize, TG_SMEM);
    cudaFuncSetAttribute(tgemm<false,false,false,false,8>, cudaFuncAttributeMaxDynamicSharedMemorySize, TG_SMEM);
    cudaFuncSetAttribute(tgemm<true,true,false,false,2>,   cudaFuncAttributeMaxDynamicSharedMemorySize, TG_SMEM);
    cudaFuncSetAttribute(tgemm<true,false,true,true,8>,    cudaFuncAttributeMaxDynamicSharedMemorySize, TG_SMEM);
    cudaFuncSetAttribute(tgemm<true,false,false,true,8>,   cudaFuncAttributeMaxDynamicSharedMemorySize, TG_SMEM);
    cudaFuncSetAttribute(pairgemm, cudaFuncAttributeMaxDynamicSharedMemorySize, PR_SMEM);
    cudaFuncSetAttribute(attn_mma_k, cudaFuncAttributeMaxDynamicSharedMemorySize, AT_SMEM);

    // 1) gamma  2) prep  3) bf
    gamma_k<<<HW, 128>>>(x, gqh, glh, tv);
    prep_k<<<(int)((PREP_TOTAL + 255)/256), 256>>>(
        qW, Wq, Wkv, bwW, modW, hvW, Wo, tokens, outb,
        qWT, WqT, WkvT, bwWT, modWT, hvWT, WoA, tokh, total);
    bf_k<<<3, HID>>>(bo, modW, modb, bfp);

    // 4) xq = relu(gq @ qW + qb) -> fp16
    tgemm<true,false,false,false,2><<<dim3(8,128), 256, TG_SMEM>>>(
        gqh, qWT, qb, nullptr, nullptr, xqh, nullptr, nullptr, nullptr, HW, HID);

    // 5) kv = tokens @ Wkv -> fp16
    tgemm<false,false,false,false,8><<<dim3(4,16), 256, TG_SMEM>>>(
        tokh, WkvT, nullptr, nullptr, nullptr, kvh, nullptr, nullptr, nullptr, NB*NTOK, 256);

    // 6-8) h_l[i] -> fp16
    for (int i = 0; i < 3; i++)
        tgemm<true,false,false,false,2><<<dim3(8,128), 256, TG_SMEM>>>(
            glh + (size_t)i*HW*FD, bwWT + (size_t)i*HID*FD, bwb + i*HID,
            nullptr, nullptr, hlh + (size_t)i*HW*HID, nullptr, nullptr, nullptr, HW, HID);

    // 9) q = xq @ Wq -> fp16
    tgemm<false,false,false,false,8><<<dim3(2,128), 256, TG_SMEM>>>(
        xqh, WqT, nullptr, nullptr, nullptr, qh, nullptr, nullptr, nullptr, HW, FD);

    // 10-12) wfT[i] = (Wo @ modW[i])^T -> fp16 [512][128]
    for (int i = 0; i < 3; i++)
        tgemm<false,false,false,false,8><<<dim3(8,1), 256, TG_SMEM>>>(
            WoA, modWT + (size_t)i*HID*HID, nullptr, nullptr, nullptr,
            nullptr, wfT + (size_t)i*HID*FD, nullptr, nullptr, FD, HID);

    // 13) attention
    attn_mma_k<<<dim3(HW/128, 2, NB), 256, AT_SMEM>>>(qh, kvh, tv, attnh);

    // 14) G2 = relu(attn@wf2 + bf2 + hl2) -> g2h
    tgemm<true,true,false,false,2><<<dim3(8,1024), 256, TG_SMEM>>>(
        attnh, wfT + 2*HID*FD, bfp + 2*HID, hlh + 2ull*HW*HID, nullptr,
        g2h, nullptr, nullptr, nullptr, MROWS, HID);

    // 15) pair: m0h (+outproj outW0) and s1h
    pairgemm<<<dim3(8,1024), 256, PR_SMEM>>>(
        attnh, wfT, bfp, hlh, m0h, s1h, outW, total);

    // 16) HV1: relu(s1@hvW0 + hvb0); total += HV1@outW1; +g2 -> s2 (into m0h)
    tgemm<true,false,true,true,8><<<dim3(8,1024), 256, TG_SMEM>>>(
        s1h, hvWT, hvb, nullptr, g2h, m0h, nullptr,
        outW + 512*3, total, MROWS, HID);

    // 17) HV2: relu(s2@hvW1 + hvb1); total += HV2@outW2
    tgemm<true,false,false,true,8><<<dim3(8,1024), 256, TG_SMEM>>>(
        m0h, hvWT + (size_t)HID*HID, hvb + HID, nullptr, nullptr, nullptr,
        nullptr, outW + 2*512*3, total, MROWS, HID);
}

// round 11
// speedup vs baseline: 1.8161x; 1.1340x over previous
#include <cuda_runtime.h>
#include <cuda_fp16.h>
#include <math.h>
#include <stdint.h>

#define HW 16384
#define NB 8
#define MROWS (NB*HW)      // 131072
#define HID 512
#define FD 128
#define NTOK 256
#define PI_D 3.14159265358979323846
#define TWO_PI_D 6.28318530717958647692
#define INV_2PI_D 0.15915494309189533577

// ---------------- fp16 buffers ----------------
__device__ __half g_gq_h[HW*FD];
__device__ __half g_gl_h[3ull*HW*FD];
__device__ __half g_xq_h[HW*HID];
__device__ __half g_q_h[HW*FD];
__device__ __half g_kv_h[NB*NTOK*256];
__device__ __half g_attn_h[(unsigned long long)MROWS*FD];
__device__ __half g_s_h[(unsigned long long)MROWS*HID];   // S1
__device__ __half g_m0_h[(unsigned long long)MROWS*HID];  // M0, reused as S2
__device__ __half g_g2_h[(unsigned long long)MROWS*HID];  // reluG2
__device__ __half g_tok_h[NB*NTOK*HID];
__device__ __half g_hl_h[3ull*HW*HID];
__device__ __half g_qWT[HID*FD];
__device__ __half g_WqT[FD*HID];
__device__ __half g_WkvT[256*HID];
__device__ __half g_bwWT[3*HID*FD];
__device__ __half g_modWT[3*HID*HID];
__device__ __half g_hvWT[2*HID*HID];
__device__ __half g_WoA[FD*HID];
__device__ __half g_wfT[3*HID*FD];
// ---------------- fp32 buffers ----------------
__device__ float g_tv[HW];
__device__ float g_bf[3*HID];

// ================= helpers =================
__device__ __forceinline__ uint32_t smem_u32(const void* p) {
    uint32_t a;
    asm("{ .reg .u64 t; cvta.to.shared.u64 t, %1; cvt.u32.u64 %0, t; }" : "=r"(a) : "l"(p));
    return a;
}
__device__ __forceinline__ void ldm_x4(uint32_t* r, uint32_t addr) {
    asm volatile("ldmatrix.sync.aligned.m8n8.x4.shared.b16 {%0,%1,%2,%3}, [%4];"
                 : "=r"(r[0]), "=r"(r[1]), "=r"(r[2]), "=r"(r[3]) : "r"(addr));
}
__device__ __forceinline__ void mma16816(float* d, const uint32_t* a, uint32_t b0, uint32_t b1) {
    asm volatile(
        "mma.sync.aligned.m16n8k16.row.col.f32.f16.f16.f32 "
        "{%0,%1,%2,%3}, {%4,%5,%6,%7}, {%8,%9}, {%0,%1,%2,%3};"
        : "+f"(d[0]), "+f"(d[1]), "+f"(d[2]), "+f"(d[3])
        : "r"(a[0]), "r"(a[1]), "r"(a[2]), "r"(a[3]), "r"(b0), "r"(b1));
}
__device__ __forceinline__ void cp16(uint32_t dst, const void* src) {
    asm volatile("cp.async.cg.shared.global [%0], [%1], 16;" :: "r"(dst), "l"(src));
}
#define CP_COMMIT() asm volatile("cp.async.commit_group;" ::: "memory")
#define CP_WAIT1()  asm volatile("cp.async.wait_group 1;" ::: "memory")
#define CP_WAIT0()  asm volatile("cp.async.wait_group 0;" ::: "memory")

// ================= Fourier features (fp32 trig + DP range reduction) =================
__global__ void gamma_k(const float* __restrict__ x, __half* __restrict__ gq,
                        __half* __restrict__ gl, float* __restrict__ tv)
{
    __shared__ double omg[128];
    int q = blockIdx.x;
    int f = threadIdx.x;
    {
        const double sig[4] = {128.0, 16.0, 64.0, 256.0};
        int s = f >> 5, j = f & 31;
        double step = (log10(sig[s]) - 1.0) / 31.0;
        omg[f] = pow(10.0, 1.0 + (double)j * step);
    }
    __syncthreads();

    float c0 = x[2*q], c1 = x[2*q+1];
    if (f == 0) {
        int r  = (int)(c0 * 16.0f);
        int cc = (int)(c1 * 16.0f);
        tv[q] = (float)(r*16 + cc) * (1.0f/256.0f);
    }
    int d = f >> 6;
    int rr = f & 63;
    int part = rr >> 5;
    int j = rr & 31;
    double pc = PI_D * (d ? (double)c1 : (double)c0);
    #pragma unroll
    for (int s = 0; s < 4; s++) {
        double arg = pc * omg[s*32 + j];
        double qf  = floor(arg * INV_2PI_D);
        float r    = (float)(arg - qf * TWO_PI_D);   // [0, 2pi), exact to ~1e-7
        float val  = part ? cosf(r) : sinf(r);
        __half* dst = (s == 0) ? gq : (gl + (size_t)(s-1)*HW*FD);
        dst[(size_t)q*FD + f] = __float2half_rn(val);
    }
}

// ================= merged weight prep =================
__global__ void prep_k(const float* __restrict__ qW, const float* __restrict__ Wq,
                       const float* __restrict__ Wkv, const float* __restrict__ bwW,
                       const float* __restrict__ modW, const float* __restrict__ hvW,
                       const float* __restrict__ Wo, const float* __restrict__ tokens,
                       const float* __restrict__ outb,
                       __half* __restrict__ qWT, __half* __restrict__ WqT,
                       __half* __restrict__ WkvT, __half* __restrict__ bwWT,
                       __half* __restrict__ modWT, __half* __restrict__ hvWT,
                       __half* __restrict__ WoA, __half* __restrict__ tokh,
                       float* __restrict__ total)
{
    long long i = (long long)blockIdx.x * 256 + threadIdx.x;
    if (i < 65536) {
        int k = (int)(i/512), n = (int)(i%512);
        qWT[n*128+k] = __float2half_rn(qW[i]); return;
    } i -= 65536;
    if (i < 65536) {
        int k = (int)(i/128), n = (int)(i%128);
        WqT[n*512+k] = __float2half_rn(Wq[i]); return;
    } i -= 65536;
    if (i < 131072) {
        int k = (int)(i/256), n = (int)(i%256);
        WkvT[n*512+k] = __float2half_rn(Wkv[i]); return;
    } i -= 131072;
    if (i < 196608) {
        int s = (int)(i/65536); long long j = i%65536;
        int k = (int)(j/512), n = (int)(j%512);
        bwWT[s*65536 + n*128+k] = __float2half_rn(bwW[i]); return;
    } i -= 196608;
    if (i < 786432) {
        int s = (int)(i/262144); long long j = i%262144;
        int k = (int)(j/512), n = (int)(j%512);
        modWT[s*262144 + n*512+k] = __float2half_rn(modW[i]); return;
    } i -= 786432;
    if (i < 524288) {
        int s = (int)(i/262144); long long j = i%262144;
        int k = (int)(j/512), n = (int)(j%512);
        hvWT[s*262144 + n*512+k] = __float2half_rn(hvW[i]); return;
    } i -= 524288;
    if (i < 65536) { WoA[i] = __float2half_rn(Wo[i]); return; } i -= 65536;
    if (i < 1048576) { tokh[i] = __float2half_rn(tokens[i]); return; } i -= 1048576;
    if (i < (long long)MROWS*3) {
        int c = (int)(i % 3);
        total[i] = outb[c] + outb[3+c] + outb[6+c];
    }
}
#define PREP_TOTAL 3276800LL

// ================= HMMA fp16 GEMM (round-8 core + staged stores) =================
#define LDK 72
#define A_PANEL (128*LDK)
#define B_PANEL (64*LDK)
#define STG (A_PANEL + B_PANEL)
#define TG_SMEM (2*STG*2)          // 55296 B
template<bool RELU, bool BCAST, bool ADDF, bool OUTP, int KT>
__global__ __launch_bounds__(256, 3)
void tgemm(const __half* __restrict__ A, const __half* __restrict__ WT,
           const float* __restrict__ bias, const __half* __restrict__ bch,
           const __half* __restrict__ af,
           __half* __restrict__ Ch, __half* __restrict__ CTh,
           const float* __restrict__ outWsel, float* __restrict__ total,
           int M, int N)
{
    const int K = KT*64;
    extern __shared__ __half sh_[];
    int tid = threadIdx.x, wid = tid >> 5, lane = tid & 31;
    long long m0 = (long long)blockIdx.y * 128;
    long long n0 = (long long)blockIdx.x * 64;
    int wm = (wid & 3) * 32;
    int wn = (wid >> 2) * 32;

    float d[2][4][4];
    #pragma unroll
    for (int mi = 0; mi < 2; mi++)
        #pragma unroll
        for (int ni = 0; ni < 4; ni++)
            #pragma unroll
            for (int q = 0; q < 4; q++) d[mi][ni][q] = 0.f;

    uint32_t s_u = smem_u32(sh_);
    int lr[4], lc[4];
    #pragma unroll
    for (int it = 0; it < 4; it++) {
        int idx = tid + it*256;
        lr[it] = idx >> 3;
        lc[it] = idx & 7;
    }

    auto load_stage = [&](int t) {
        uint32_t base = s_u + (uint32_t)(t & 1) * (STG*2);
        int kt = t << 6;
        #pragma unroll
        for (int it = 0; it < 4; it++)
            cp16(base + (lr[it]*LDK + lc[it]*8)*2, A + (m0 + lr[it])*(long long)K + kt + lc[it]*8);
        #pragma unroll
        for (int it = 0; it < 2; it++)
            cp16(base + (A_PANEL + lr[it]*LDK + lc[it]*8)*2, WT + (n0 + lr[it])*(long long)K + kt + lc[it]*8);
        CP_COMMIT();
    };

    load_stage(0);

    uint32_t q_row = (uint32_t)(lane & 15), q_koff = (uint32_t)(lane >> 4) * 8;

    #pragma unroll
    for (int t = 0; t < KT; t++) {
        if (t + 1 < KT) { load_stage(t + 1); CP_WAIT1(); }
        else            { CP_WAIT0(); }
        __syncthreads();

        uint32_t sa_u = s_u + (uint32_t)(t & 1) * (STG*2);
        uint32_t sb_u = sa_u + A_PANEL*2;
        #pragma unroll
        for (int kk = 0; kk < 64; kk += 16) {
            uint32_t afr[2][4], bfr[2][4];
            #pragma unroll
            for (int mi = 0; mi < 2; mi++)
                ldm_x4(afr[mi], sa_u + (((uint32_t)wm + mi*16 + q_row)*LDK + kk + q_koff)*2);
            #pragma unroll
            for (int nj = 0; nj < 2; nj++)
                ldm_x4(bfr[nj], sb_u + (((uint32_t)wn + nj*16 + q_row)*LDK + kk + q_koff)*2);
            #pragma unroll
            for (int mi = 0; mi < 2; mi++)
                #pragma unroll
                for (int ni = 0; ni < 4; ni++)
                    mma16816(d[mi][ni], afr[mi], bfr[ni>>1][ni&1], bfr[ni>>1][(ni&1)+2]);
        }
        __syncthreads();
    }

    __half* stg = sh_;
    float* red = (float*)((char*)sh_ + 20480);
    if (OUTP) {
        for (int i = tid; i < 128*3; i += 256) red[i] = 0.f;
        __syncthreads();
    }

    int qr = lane >> 2;
    int qc = (lane & 3) * 2;
    #pragma unroll
    for (int mi = 0; mi < 2; mi++) {
        #pragma unroll
        for (int rh = 0; rh < 2; rh++) {
            int rloc = wm + mi*16 + rh*8 + qr;
            long long r  = m0 + rloc;
            long long rb_ = BCAST ? (r & (HW - 1)) : r;
            float p0 = 0.f, p1 = 0.f, p2 = 0.f;
            #pragma unroll
            for (int ni = 0; ni < 4; ni++) {
                int cloc = wn + ni*8 + qc;
                long long c = n0 + cloc;
                float v0 = d[mi][ni][rh*2+0];
                float v1 = d[mi][ni][rh*2+1];
                if (bias) {
                    float2 b2 = *(const float2*)(bias + c);
                    v0 += b2.x; v1 += b2.y;
                }
                if (BCAST) {
                    float2 b2 = __half22float2(*(const __half2*)(bch + rb_*(long long)N + c));
                    v0 += b2.x; v1 += b2.y;
                }
                if (RELU) { v0 = fmaxf(v0, 0.f); v1 = fmaxf(v1, 0.f); }
                if (OUTP) {
                    const float* w0 = outWsel + c*3;
                    p0 += v0*w0[0] + v1*w0[3];
                    p1 += v0*w0[1] + v1*w0[4];
                    p2 += v0*w0[2] + v1*w0[5];
                }
                if (ADDF) {
                    float2 af2 = __half22float2(*(const __half2*)(af + r*(long long)N + c));
                    v0 += af2.x; v1 += af2.y;
                }
                if (Ch) *(__half2*)(stg + rloc*LDK + cloc) = __floats2half2_rn(v0, v1);
                if (CTh) {
                    CTh[c*(long long)M + r]     = __float2half_rn(v0);
                    CTh[(c+1)*(long long)M + r] = __float2half_rn(v1);
                }
            }
            if (OUTP) {
                #pragma unroll
                for (int o = 1; o < 4; o <<= 1) {
                    p0 += __shfl_xor_sync(0xffffffffu, p0, o);
                    p1 += __shfl_xor_sync(0xffffffffu, p1, o);
                    p2 += __shfl_xor_sync(0xffffffffu, p2, o);
                }
                if ((lane & 3) == 0) {
                    atomicAdd(&red[rloc*3+0], p0);
                    atomicAdd(&red[rloc*3+1], p1);
                    atomicAdd(&red[rloc*3+2], p2);
                }
            }
        }
    }
    __syncthreads();
    if (Ch) {
        #pragma unroll
        for (int it = 0; it < 4; it++) {
            int c = tid + it*256;
            int row = c >> 3, off = (c & 7) * 8;
            *(uint4*)(Ch + (m0 + row)*(long long)N + n0 + off) = *(const uint4*)(stg + row*LDK + off);
        }
    }
    if (OUTP) {
        for (int i = tid; i < 128*3; i += 256)
            atomicAdd(&total[(m0 + (i/3))*3 + (i%3)], red[i]);
    }
}

// ================= pair-band GEMM: G0 + G1 share A (K=128) =================
#define PR_STG (A_PANEL + 2*B_PANEL)
#define PR_SMEM (2*PR_STG*2)                 // 73728 B
__global__ __launch_bounds__(256, 2)
void pairgemm(const __half* __restrict__ A, const __half* __restrict__ wfT,
              const float* __restrict__ bf, const __half* __restrict__ hl,
              __half* __restrict__ m0h, __half* __restrict__ s1h,
              const float* __restrict__ outW, float* __restrict__ total)
{
    extern __shared__ __half sh_[];
    int tid = threadIdx.x, wid = tid >> 5, lane = tid & 31;
    long long m0 = (long long)blockIdx.y * 128;
    long long n0 = (long long)blockIdx.x * 64;
    int wm = (wid & 3) * 32;
    int wn = (wid >> 2) * 32;
    uint32_t s_u = smem_u32(sh_);

    float d0[2][4][4], d1[2][4][4];
    #pragma unroll
    for (int mi = 0; mi < 2; mi++)
        #pragma unroll
        for (int ni = 0; ni < 4; ni++)
            #pragma unroll
            for (int q = 0; q < 4; q++) { d0[mi][ni][q] = 0.f; d1[mi][ni][q] = 0.f; }

    int lr[4], lc[4];
    #pragma unroll
    for (int it = 0; it < 4; it++) {
        int idx = tid + it*256;
        lr[it] = idx >> 3;
        lc[it] = idx & 7;
    }

    auto load_stage = [&](int t) {
        uint32_t base = s_u + (uint32_t)(t & 1) * (PR_STG*2);
        int kt = t << 6;
        #pragma unroll
        for (int it = 0; it < 4; it++)
            cp16(base + (lr[it]*LDK + lc[it]*8)*2, A + (m0 + lr[it])*FD + kt + lc[it]*8);
        #pragma unroll
        for (int it = 0; it < 2; it++) {
            cp16(base + (A_PANEL + lr[it]*LDK + lc[it]*8)*2, wfT + (n0 + lr[it])*FD + kt + lc[it]*8);
            cp16(base + (A_PANEL + B_PANEL + lr[it]*LDK + lc[it]*8)*2,
                 wfT + HID*FD + (n0 + lr[it])*FD + kt + lc[it]*8);
        }
        CP_COMMIT();
    };
    load_stage(0);

    uint32_t q_row = (uint32_t)(lane & 15), q_koff = (uint32_t)(lane >> 4) * 8;

    #pragma unroll
    for (int t = 0; t < 2; t++) {
        if (t == 0) { load_stage(1); CP_WAIT1(); } else { CP_WAIT0(); }
        __syncthreads();
        uint32_t sa_u = s_u + (uint32_t)(t & 1) * (PR_STG*2);
        uint32_t sb0  = sa_u + A_PANEL*2;
        uint32_t sb1  = sb0 + B_PANEL*2;
        #pragma unroll
        for (int kk = 0; kk < 64; kk += 16) {
            uint32_t afr[2][4], b0f[2][4], b1f[2][4];
            #pragma unroll
            for (int mi = 0; mi < 2; mi++)
                ldm_x4(afr[mi], sa_u + (((uint32_t)wm + mi*16 + q_row)*LDK + kk + q_koff)*2);
            #pragma unroll
            for (int nj = 0; nj < 2; nj++) {
                ldm_x4(b0f[nj], sb0 + (((uint32_t)wn + nj*16 + q_row)*LDK + kk + q_koff)*2);
                ldm_x4(b1f[nj], sb1 + (((uint32_t)wn + nj*16 + q_row)*LDK + kk + q_koff)*2);
            }
            #pragma unroll
            for (int mi = 0; mi < 2; mi++)
                #pragma unroll
                for (int ni = 0; ni < 4; ni++) {
                    mma16816(d0[mi][ni], afr[mi], b0f[ni>>1][ni&1], b0f[ni>>1][(ni&1)+2]);
                    mma16816(d1[mi][ni], afr[mi], b1f[ni>>1][ni&1], b1f[ni>>1][(ni&1)+2]);
                }
        }
        __syncthreads();
    }

    __half* stg0 = sh_;
    __half* stg1 = sh_ + 128*LDK;
    float* red = (float*)((char*)sh_ + 40960);
    for (int i = tid; i < 128*3; i += 256) red[i] = 0.f;
    __syncthreads();

    int qr = lane >> 2;
    int qc = (lane & 3) * 2;
    const float* bf0 = bf;
    const float* bf1 = bf + HID;
    const __half* hl0 = hl;
    const __half* hl1 = hl + (size_t)HW*HID;
    #pragma unroll
    for (int mi = 0; mi < 2; mi++) {
        #pragma unroll
        for (int rh = 0; rh < 2; rh++) {
            int rloc = wm + mi*16 + rh*8 + qr;
            long long r  = m0 + rloc;
            long long rb = r & (HW - 1);
            float p0 = 0.f, p1 = 0.f, p2 = 0.f;
            #pragma unroll
            for (int ni = 0; ni < 4; ni++) {
                int cloc = wn + ni*8 + qc;
                long long c = n0 + cloc;
                float u0 = d0[mi][ni][rh*2+0];
                float u1 = d0[mi][ni][rh*2+1];
                float2 b2 = *(const float2*)(bf0 + c);
                float2 h2 = __half22float2(*(const __half2*)(hl0 + rb*HID + c));
                u0 = fmaxf(u0 + b2.x + h2.x, 0.f);
                u1 = fmaxf(u1 + b2.y + h2.y, 0.f);
                const float* w0 = outW + c*3;
                p0 += u0*w0[0] + u1*w0[3];
                p1 += u0*w0[1] + u1*w0[4];
                p2 += u0*w0[2] + u1*w0[5];
                *(__half2*)(stg0 + rloc*LDK + cloc) = __floats2half2_rn(u0, u1);
                float v0 = d1[mi][ni][rh*2+0];
                float v1 = d1[mi][ni][rh*2+1];
                float2 b3 = *(const float2*)(bf1 + c);
                float2 h3 = __half22float2(*(const __half2*)(hl1 + rb*HID + c));
                v0 = fmaxf(v0 + b3.x + h3.x, 0.f) + u0;
                v1 = fmaxf(v1 + b3.y + h3.y, 0.f) + u1;
                *(__half2*)(stg1 + rloc*LDK + cloc) = __floats2half2_rn(v0, v1);
            }
            #pragma unroll
            for (int o = 1; o < 4; o <<= 1) {
                p0 += __shfl_xor_sync(0xffffffffu, p0, o);
                p1 += __shfl_xor_sync(0xffffffffu, p1, o);
                p2 += __shfl_xor_sync(0xffffffffu, p2, o);
            }
            if ((lane & 3) == 0) {
                atomicAdd(&red[rloc*3+0], p0);
                atomicAdd(&red[rloc*3+1], p1);
                atomicAdd(&red[rloc*3+2], p2);
            }
        }
    }
    __syncthreads();
    #pragma unroll
    for (int it = 0; it < 4; it++) {
        int c = tid + it*256;
        int row = c >> 3, off = (c & 7) * 8;
        *(uint4*)(m0h + (m0 + row)*HID + n0 + off) = *(const uint4*)(stg0 + row*LDK + off);
        *(uint4*)(s1h + (m0 + row)*HID + n0 + off) = *(const uint4*)(stg1 + row*LDK + off);
    }
    for (int i = tid; i < 128*3; i += 256)
        atomicAdd(&total[(m0 + (i/3))*3 + (i%3)], red[i]);
}

// ================= fused bias (parallelized): bf[i] = bo @ mod_W[i] + mod_b[i] =================
__global__ void bf_k(const float* __restrict__ bo, const float* __restrict__ modW,
                     const float* __restrict__ modb, float* __restrict__ bf)
{
    __shared__ float red[256];
    int band = blockIdx.y;
    int n0 = blockIdx.x * 64;
    int nl = threadIdx.x & 63;
    int ks = threadIdx.x >> 6;       // 0..3
    const float* Wm = modW + (size_t)band*HID*HID;
    float s = 0.f;
    for (int k = ks*128; k < ks*128 + 128; k++)
        s += bo[k] * Wm[(size_t)k*HID + n0 + nl];
    red[threadIdx.x] = s;
    __syncthreads();
    if (threadIdx.x < 64) {
        float t = red[threadIdx.x] + red[threadIdx.x+64] + red[threadIdx.x+128] + red[threadIdx.x+192];
        bf[band*HID + n0 + threadIdx.x] = t + modb[band*HID + n0 + threadIdx.x];
    }
}

// ================= HMMA attention =================
#define AT_QSTR 72
#define AT_KSTR 72
#define AT_VSTR 264
#define AT_PSTR 264
#define AT_SMEM ((128*AT_QSTR + 256*AT_KSTR + 64*AT_VSTR + 128*AT_PSTR)*2)
__global__ __launch_bounds__(256)
void attn_mma_k(const __half* __restrict__ qh, const __half* __restrict__ kvh,
                const float* __restrict__ tv, __half* __restrict__ out)
{
    extern __shared__ __half sm[];
    __half* sQ = sm;
    __half* sK = sQ + 128*AT_QSTR;
    __half* sV = sK + 256*AT_KSTR;
    __half* sP = sV + 64*AT_VSTR;
    int tid = threadIdx.x, wid = tid >> 5, lane = tid & 31;
    int h = blockIdx.y, b = blockIdx.z;
    long long q0 = (long long)blockIdx.x * 128;
    const __half* kvb = kvh + (size_t)b*NTOK*256;

    for (int idx = tid; idx < 1024; idx += 256) {
        int r = idx >> 3, c8 = idx & 7;
        *(uint4*)(sQ + r*AT_QSTR + c8*8) = *(const uint4*)(qh + (q0 + r)*FD + h*64 + c8*8);
    }
    for (int idx = tid; idx < 2048; idx += 256) {
        int t = idx >> 3, c8 = idx & 7;
        *(uint4*)(sK + t*AT_KSTR + c8*8) = *(const uint4*)(kvb + t*256 + h*64 + c8*8);
    }
    for (int idx = tid; idx < NTOK*64; idx += 256) {
        int t = idx >> 6, dd = idx & 63;
        sV[dd*AT_VSTR + t] = kvb[t*256 + 128 + h*64 + dd];
    }
    __syncthreads();

    uint32_t sQu = smem_u32(sQ), sKu = smem_u32(sK), sVu = smem_u32(sV), sPu = smem_u32(sP);

    float s[32][4];
    #pragma unroll
    for (int ni = 0; ni < 32; ni++)
        #pragma unroll
        for (int q = 0; q < 4; q++) s[ni][q] = 0.f;

    uint32_t a_row = (uint32_t)(wid*16 + (lane & 15)), a_koff = (uint32_t)(lane >> 4) * 8;
    uint32_t q_row = (uint32_t)(lane & 15), q_koff = (uint32_t)(lane >> 4) * 8;
    #pragma unroll
    for (int kk = 0; kk < 64; kk += 16) {
        uint32_t afr[4];
        ldm_x4(afr, sQu + (a_row*AT_QSTR + kk + a_koff)*2);
        #pragma unroll
        for (int nj = 0; nj < 16; nj++) {
            uint32_t bfr[4];
            ldm_x4(bfr, sKu + (((uint32_t)nj*16 + q_row)*AT_KSTR + kk + q_koff)*2);
            mma16816(s[nj*2],   afr, bfr[0], bfr[2]);
            mma16816(s[nj*2+1], afr, bfr[1], bfr[3]);
        }
    }

    int rq = wid*16 + (lane >> 2);
    float tq0 = tv[q0 + rq];
    float tq1 = tv[q0 + rq + 8];
    float mx0 = -1e30f, mx1 = -1e30f;
    #pragma unroll
    for (int ni = 0; ni < 32; ni++) {
        #pragma unroll
        for (int c = 0; c < 2; c++) {
            float pos = ((float)(ni*8 + (lane & 3)*2 + c) + 0.5f) * (1.0f/256.0f);
            float d0 = tq0 - pos, d1 = tq1 - pos;
            s[ni][c]   = s[ni][c]*0.125f   - 10.0f*d0*d0;
            s[ni][c+2] = s[ni][c+2]*0.125f - 10.0f*d1*d1;
            mx0 = fmaxf(mx0, s[ni][c]);
            mx1 = fmaxf(mx1, s[ni][c+2]);
        }
    }
    #pragma unroll
    for (int o = 1; o < 4; o <<= 1) {
        mx0 = fmaxf(mx0, __shfl_xor_sync(0xffffffffu, mx0, o));
        mx1 = fmaxf(mx1, __shfl_xor_sync(0xffffffffu, mx1, o));
    }
    float den0 = 0.f, den1 = 0.f;
    #pragma unroll
    for (int ni = 0; ni < 32; ni++) {
        #pragma unroll
        for (int c = 0; c < 2; c++) {
            s[ni][c]   = __expf(s[ni][c]   - mx0);
            s[ni][c+2] = __expf(s[ni][c+2] - mx1);
            den0 += s[ni][c];
            den1 += s[ni][c+2];
        }
    }
    #pragma unroll
    for (int o = 1; o < 4; o <<= 1) {
        den0 += __shfl_xor_sync(0xffffffffu, den0, o);
        den1 += __shfl_xor_sync(0xffffffffu, den1, o);
    }
    float inv0 = 1.0f / den0, inv1 = 1.0f / den1;
    int cbase = (lane & 3)*2;
    #pragma unroll
    for (int ni = 0; ni < 32; ni++) {
        *(__half2*)(sP + rq*AT_PSTR + ni*8 + cbase) =
            __floats2half2_rn(s[ni][0]*inv0, s[ni][1]*inv0);
        *(__half2*)(sP + (rq+8)*AT_PSTR + ni*8 + cbase) =
            __floats2half2_rn(s[ni][2]*inv1, s[ni][3]*inv1);
    }
    __syncthreads();

    float o[8][4];
    #pragma unroll
    for (int nj = 0; nj < 8; nj++)
        #pragma unroll
        for (int q = 0; q < 4; q++) o[nj][q] = 0.f;

    #pragma unroll
    for (int kk = 0; kk < 256; kk += 16) {
        uint32_t afr[4];
        ldm_x4(afr, sPu + (a_row*AT_PSTR + kk + a_koff)*2);
        #pragma unroll
        for (int nj = 0; nj < 4; nj++) {
            uint32_t bfr[4];
            ldm_x4(bfr, sVu + (((uint32_t)nj*16 + q_row)*AT_VSTR + kk + q_koff)*2);
            mma16816(o[nj*2],   afr, bfr[0], bfr[2]);
            mma16816(o[nj*2+1], afr, bfr[1], bfr[3]);
        }
    }

    long long qi0 = q0 + rq;
    __half* op0 = out + ((size_t)b*HW + qi0)*FD + h*64;
    __half* op1 = op0 + (size_t)8*FD;
    #pragma unroll
    for (int nj = 0; nj < 8; nj++) {
        *(__half2*)(op0 + nj*8 + cbase) = __floats2half2_rn(o[nj][0], o[nj][1]);
        *(__half2*)(op1 + nj*8 + cbase) = __floats2half2_rn(o[nj][2], o[nj][3]);
    }
}

// ================= launch =================
extern "C" void kernel_launch(void* const* d_in, const int* in_sizes, int n_in,
                              void* d_out, int out_size)
{
    const float* x      = (const float*)d_in[0];
    const float* tokens = (const float*)d_in[1];
    const float* qW     = (const float*)d_in[2];
    const float* qb     = (const float*)d_in[3];
    const float* Wq     = (const float*)d_in[4];
    const float* Wkv    = (const float*)d_in[5];
    const float* Wo     = (const float*)d_in[6];
    const float* bo     = (const float*)d_in[7];
    const float* bwW    = (const float*)d_in[8];
    const float* bwb    = (const float*)d_in[9];
    const float* modW   = (const float*)d_in[10];
    const float* modb   = (const float*)d_in[11];
    const float* hvW    = (const float*)d_in[12];
    const float* hvb    = (const float*)d_in[13];
    const float* outW   = (const float*)d_in[14];
    const float* outb   = (const float*)d_in[15];
    float* total = (float*)d_out;

    __half *gqh, *glh, *xqh, *qh, *kvh, *attnh, *s1h, *m0h, *g2h, *tokh, *hlh;
    __half *qWT, *WqT, *WkvT, *bwWT, *modWT, *hvWT, *WoA, *wfT;
    float *tv, *bfp;
    cudaGetSymbolAddress((void**)&gqh,   g_gq_h);
    cudaGetSymbolAddress((void**)&glh,   g_gl_h);
    cudaGetSymbolAddress((void**)&xqh,   g_xq_h);
    cudaGetSymbolAddress((void**)&qh,    g_q_h);
    cudaGetSymbolAddress((void**)&kvh,   g_kv_h);
    cudaGetSymbolAddress((void**)&attnh, g_attn_h);
    cudaGetSymbolAddress((void**)&s1h,   g_s_h);
    cudaGetSymbolAddress((void**)&m0h,   g_m0_h);
    cudaGetSymbolAddress((void**)&g2h,   g_g2_h);
    cudaGetSymbolAddress((void**)&tokh,  g_tok_h);
    cudaGetSymbolAddress((void**)&hlh,   g_hl_h);
    cudaGetSymbolAddress((void**)&qWT,   g_qWT);
    cudaGetSymbolAddress((void**)&WqT,   g_WqT);
    cudaGetSymbolAddress((void**)&WkvT,  g_WkvT);
    cudaGetSymbolAddress((void**)&bwWT,  g_bwWT);
    cudaGetSymbolAddress((void**)&modWT, g_modWT);
    cudaGetSymbolAddress((void**)&hvWT,  g_hvWT);
    cudaGetSymbolAddress((void**)&WoA,   g_WoA);
    cudaGetSymbolAddress((void**)&wfT,   g_wfT);
    cudaGetSymbolAddress((void**)&tv,    g_tv);
    cudaGetSymbolAddress((void**)&bfp,   g_bf);

    cudaFuncSetAttribute(tgemm<true,false,false,false,2>,  cudaFuncAttributeMaxDynamicSharedMemorySize, TG_SMEM);
    cudaFuncSetAttribute(tgemm<false,false,false,false,8>, cudaFuncAttributeMaxDynamicSharedMemorySize, TG_SMEM);
    cudaFuncSetAttribute(tgemm<true,true,false,false,2>,   cudaFuncAttributeMaxDynamicSharedMemorySize, TG_SMEM);
    cudaFuncSetAttribute(tgemm<true,false,true,true,8>,    cudaFuncAttributeMaxDynamicSharedMemorySize, TG_SMEM);
    cudaFuncSetAttribute(tgemm<true,false,false,true,8>,   cudaFuncAttributeMaxDynamicSharedMemorySize, TG_SMEM);
    cudaFuncSetAttribute(pairgemm, cudaFuncAttributeMaxDynamicSharedMemorySize, PR_SMEM);
    cudaFuncSetAttribute(attn_mma_k, cudaFuncAttributeMaxDynamicSharedMemorySize, AT_SMEM);

    // 1) gamma  2) prep  3) bf
    gamma_k<<<HW, 128>>>(x, gqh, glh, tv);
    prep_k<<<(int)((PREP_TOTAL + 255)/256), 256>>>(
        qW, Wq, Wkv, bwW, modW, hvW, Wo, tokens, outb,
        qWT, WqT, WkvT, bwWT, modWT, hvWT, WoA, tokh, total);
    bf_k<<<dim3(8,3), 256>>>(bo, modW, modb, bfp);

    // 4) xq = relu(gq @ qW + qb) -> fp16
    tgemm<true,false,false,false,2><<<dim3(8,128), 256, TG_SMEM>>>(
        gqh, qWT, qb, nullptr, nullptr, xqh, nullptr, nullptr, nullptr, HW, HID);

    // 5) kv = tokens @ Wkv -> fp16
    tgemm<false,false,false,false,8><<<dim3(4,16), 256, TG_SMEM>>>(
        tokh, WkvT, nullptr, nullptr, nullptr, kvh, nullptr, nullptr, nullptr, NB*NTOK, 256);

    // 6-8) h_l[i] -> fp16
    for (int i = 0; i < 3; i++)
        tgemm<true,false,false,false,2><<<dim3(8,128), 256, TG_SMEM>>>(
            glh + (size_t)i*HW*FD, bwWT + (size_t)i*HID*FD, bwb + i*HID,
            nullptr, nullptr, hlh + (size_t)i*HW*HID, nullptr, nullptr, nullptr, HW, HID);

    // 9) q = xq @ Wq -> fp16
    tgemm<false,false,false,false,8><<<dim3(2,128), 256, TG_SMEM>>>(
        xqh, WqT, nullptr, nullptr, nullptr, qh, nullptr, nullptr, nullptr, HW, FD);

    // 10-12) wfT[i] = (Wo @ modW[i])^T -> fp16 [512][128]
    for (int i = 0; i < 3; i++)
        tgemm<false,false,false,false,8><<<dim3(8,1), 256, TG_SMEM>>>(
            WoA, modWT + (size_t)i*HID*HID, nullptr, nullptr, nullptr,
            nullptr, wfT + (size_t)i*HID*FD, nullptr, nullptr, FD, HID);

    // 13) attention
    attn_mma_k<<<dim3(HW/128, 2, NB), 256, AT_SMEM>>>(qh, kvh, tv, attnh);

    // 14) G2 = relu(attn@wf2 + bf2 + hl2) -> g2h
    tgemm<true,true,false,false,2><<<dim3(8,1024), 256, TG_SMEM>>>(
        attnh, wfT + 2*HID*FD, bfp + 2*HID, hlh + 2ull*HW*HID, nullptr,
        g2h, nullptr, nullptr, nullptr, MROWS, HID);

    // 15) pair: m0h (+outproj outW0) and s1h
    pairgemm<<<dim3(8,1024), 256, PR_SMEM>>>(
        attnh, wfT, bfp, hlh, m0h, s1h, outW, total);

    // 16) HV1: relu(s1@hvW0 + hvb0); total += HV1@outW1; +g2 -> s2 (into m0h)
    tgemm<true,false,true,true,8><<<dim3(8,1024), 256, TG_SMEM>>>(
        s1h, hvWT, hvb, nullptr, g2h, m0h, nullptr,
        outW + 512*3, total, MROWS, HID);

    // 17) HV2: relu(s2@hvW1 + hvb1); total += HV2@outW2
    tgemm<true,false,false,true,8><<<dim3(8,1024), 256, TG_SMEM>>>(
        m0h, hvWT + (size_t)HID*HID, hvb + HID, nullptr, nullptr, nullptr,
        nullptr, outW + 2*512*3, total, MROWS, HID);
}

// round 12
// speedup vs baseline: 1.8391x; 1.0127x over previous
#include <cuda_runtime.h>
#include <cuda_fp16.h>
#include <math.h>
#include <stdint.h>

#define HW 16384
#define NB 8
#define MROWS (NB*HW)      // 131072
#define HID 512
#define FD 128
#define NTOK 256
#define PI_D 3.14159265358979323846
#define TWO_PI_D 6.28318530717958647692
#define INV_2PI_D 0.15915494309189533577

// ---------------- fp16 buffers ----------------
__device__ __half g_gq_h[HW*FD];
__device__ __half g_gl_h[3ull*HW*FD];
__device__ __half g_xq_h[HW*HID];
__device__ __half g_q_h[HW*FD];
__device__ __half g_kv_h[NB*NTOK*256];
__device__ __half g_attn_h[(unsigned long long)MROWS*FD];
__device__ __half g_s_h[(unsigned long long)MROWS*HID];   // S1
__device__ __half g_m0_h[(unsigned long long)MROWS*HID];  // M0, reused as S2
__device__ __half g_g2_h[(unsigned long long)MROWS*HID];  // reluG2
__device__ __half g_tok_h[NB*NTOK*HID];
__device__ __half g_hl_h[3ull*HW*HID];
__device__ __half g_qWT[HID*FD];
__device__ __half g_WqT[FD*HID];
__device__ __half g_WkvT[256*HID];
__device__ __half g_bwWT[3*HID*FD];
__device__ __half g_modWT[3*HID*HID];
__device__ __half g_hvWT[2*HID*HID];
__device__ __half g_WoA[FD*HID];
__device__ __half g_wfT[3*HID*FD];
// ---------------- fp32 buffers ----------------
__device__ float g_tv[HW];
__device__ float g_bf[3*HID];

// ================= helpers =================
__device__ __forceinline__ uint32_t smem_u32(const void* p) {
    uint32_t a;
    asm("{ .reg .u64 t; cvta.to.shared.u64 t, %1; cvt.u32.u64 %0, t; }" : "=r"(a) : "l"(p));
    return a;
}
__device__ __forceinline__ void ldm_x4(uint32_t* r, uint32_t addr) {
    asm volatile("ldmatrix.sync.aligned.m8n8.x4.shared.b16 {%0,%1,%2,%3}, [%4];"
                 : "=r"(r[0]), "=r"(r[1]), "=r"(r[2]), "=r"(r[3]) : "r"(addr));
}
__device__ __forceinline__ void mma16816(float* d, const uint32_t* a, uint32_t b0, uint32_t b1) {
    asm volatile(
        "mma.sync.aligned.m16n8k16.row.col.f32.f16.f16.f32 "
        "{%0,%1,%2,%3}, {%4,%5,%6,%7}, {%8,%9}, {%0,%1,%2,%3};"
        : "+f"(d[0]), "+f"(d[1]), "+f"(d[2]), "+f"(d[3])
        : "r"(a[0]), "r"(a[1]), "r"(a[2]), "r"(a[3]), "r"(b0), "r"(b1));
}
__device__ __forceinline__ void cp16(uint32_t dst, const void* src) {
    asm volatile("cp.async.cg.shared.global [%0], [%1], 16;" :: "r"(dst), "l"(src));
}
#define CP_COMMIT() asm volatile("cp.async.commit_group;" ::: "memory")
#define CP_WAIT1()  asm volatile("cp.async.wait_group 1;" ::: "memory")
#define CP_WAIT0()  asm volatile("cp.async.wait_group 0;" ::: "memory")

// ================= Fourier features (fp32 trig + DP range reduction) =================
__global__ void gamma_k(const float* __restrict__ x, __half* __restrict__ gq,
                        __half* __restrict__ gl, float* __restrict__ tv)
{
    __shared__ double omg[128];
    int q = blockIdx.x;
    int f = threadIdx.x;
    {
        const double sig[4] = {128.0, 16.0, 64.0, 256.0};
        int s = f >> 5, j = f & 31;
        double step = (log10(sig[s]) - 1.0) / 31.0;
        omg[f] = pow(10.0, 1.0 + (double)j * step);
    }
    __syncthreads();

    float c0 = x[2*q], c1 = x[2*q+1];
    if (f == 0) {
        int r  = (int)(c0 * 16.0f);
        int cc = (int)(c1 * 16.0f);
        tv[q] = (float)(r*16 + cc) * (1.0f/256.0f);
    }
    int d = f >> 6;
    int rr = f & 63;
    int part = rr >> 5;
    int j = rr & 31;
    double pc = PI_D * (d ? (double)c1 : (double)c0);
    #pragma unroll
    for (int s = 0; s < 4; s++) {
        double arg = pc * omg[s*32 + j];
        double qf  = floor(arg * INV_2PI_D);
        float r    = (float)(arg - qf * TWO_PI_D);
        float val  = part ? cosf(r) : sinf(r);
        __half* dst = (s == 0) ? gq : (gl + (size_t)(s-1)*HW*FD);
        dst[(size_t)q*FD + f] = __float2half_rn(val);
    }
}

// ================= merged weight prep =================
__global__ void prep_k(const float* __restrict__ qW, const float* __restrict__ Wq,
                       const float* __restrict__ Wkv, const float* __restrict__ bwW,
                       const float* __restrict__ modW, const float* __restrict__ hvW,
                       const float* __restrict__ Wo, const float* __restrict__ tokens,
                       const float* __restrict__ outb,
                       __half* __restrict__ qWT, __half* __restrict__ WqT,
                       __half* __restrict__ WkvT, __half* __restrict__ bwWT,
                       __half* __restrict__ modWT, __half* __restrict__ hvWT,
                       __half* __restrict__ WoA, __half* __restrict__ tokh,
                       float* __restrict__ total)
{
    long long i = (long long)blockIdx.x * 256 + threadIdx.x;
    if (i < 65536) {
        int k = (int)(i/512), n = (int)(i%512);
        qWT[n*128+k] = __float2half_rn(qW[i]); return;
    } i -= 65536;
    if (i < 65536) {
        int k = (int)(i/128), n = (int)(i%128);
        WqT[n*512+k] = __float2half_rn(Wq[i]); return;
    } i -= 65536;
    if (i < 131072) {
        int k = (int)(i/256), n = (int)(i%256);
        WkvT[n*512+k] = __float2half_rn(Wkv[i]); return;
    } i -= 131072;
    if (i < 196608) {
        int s = (int)(i/65536); long long j = i%65536;
        int k = (int)(j/512), n = (int)(j%512);
        bwWT[s*65536 + n*128+k] = __float2half_rn(bwW[i]); return;
    } i -= 196608;
    if (i < 786432) {
        int s = (int)(i/262144); long long j = i%262144;
        int k = (int)(j/512), n = (int)(j%512);
        modWT[s*262144 + n*512+k] = __float2half_rn(modW[i]); return;
    } i -= 786432;
    if (i < 524288) {
        int s = (int)(i/262144); long long j = i%262144;
        int k = (int)(j/512), n = (int)(j%512);
        hvWT[s*262144 + n*512+k] = __float2half_rn(hvW[i]); return;
    } i -= 524288;
    if (i < 65536) { WoA[i] = __float2half_rn(Wo[i]); return; } i -= 65536;
    if (i < 1048576) { tokh[i] = __float2half_rn(tokens[i]); return; } i -= 1048576;
    if (i < (long long)MROWS*3) {
        int c = (int)(i % 3);
        total[i] = outb[c] + outb[3+c] + outb[6+c];
    }
}
#define PREP_TOTAL 3276800LL

// ================= HMMA fp16 GEMM (round-10 core; z-strided for banded launches) =================
#define LDK 72
#define A_PANEL (128*LDK)
#define B_PANEL (64*LDK)
#define STG (A_PANEL + B_PANEL)
#define TG_SMEM (2*STG*2)          // 55296 B
template<bool RELU, bool BCAST, bool ADDF, bool OUTP, int KT>
__global__ __launch_bounds__(256, 3)
void tgemm(const __half* __restrict__ A, const __half* __restrict__ WT,
           const float* __restrict__ bias, const __half* __restrict__ bch,
           const __half* __restrict__ af,
           __half* __restrict__ Ch, __half* __restrict__ CTh,
           const float* __restrict__ outWsel, float* __restrict__ total,
           int M, int N,
           long long zA, long long zW, long long zB, long long zC, long long zCT)
{
    const int K = KT*64;
    // banded offsets (blockIdx.z selects band; strides are 0 for non-banded launches)
    long long z = blockIdx.z;
    A   += z * zA;
    WT  += z * zW;
    if (bias) bias += z * zB;
    if (bch)  bch  += z * zA * 0;   // not used banded
    if (Ch)   Ch   += z * zC;
    if (CTh)  CTh  += z * zCT;

    extern __shared__ __half sh_[];
    int tid = threadIdx.x, wid = tid >> 5, lane = tid & 31;
    long long m0 = (long long)blockIdx.y * 128;
    long long n0 = (long long)blockIdx.x * 64;
    int wm = (wid & 3) * 32;
    int wn = (wid >> 2) * 32;

    float d[2][4][4];
    #pragma unroll
    for (int mi = 0; mi < 2; mi++)
        #pragma unroll
        for (int ni = 0; ni < 4; ni++)
            #pragma unroll
            for (int q = 0; q < 4; q++) d[mi][ni][q] = 0.f;

    uint32_t s_u = smem_u32(sh_);
    int lr[4], lc[4];
    #pragma unroll
    for (int it = 0; it < 4; it++) {
        int idx = tid + it*256;
        lr[it] = idx >> 3;
        lc[it] = idx & 7;
    }

    auto load_stage = [&](int t) {
        uint32_t base = s_u + (uint32_t)(t & 1) * (STG*2);
        int kt = t << 6;
        #pragma unroll
        for (int it = 0; it < 4; it++)
            cp16(base + (lr[it]*LDK + lc[it]*8)*2, A + (m0 + lr[it])*(long long)K + kt + lc[it]*8);
        #pragma unroll
        for (int it = 0; it < 2; it++)
            cp16(base + (A_PANEL + lr[it]*LDK + lc[it]*8)*2, WT + (n0 + lr[it])*(long long)K + kt + lc[it]*8);
        CP_COMMIT();
    };

    load_stage(0);

    uint32_t q_row = (uint32_t)(lane & 15), q_koff = (uint32_t)(lane >> 4) * 8;

    #pragma unroll
    for (int t = 0; t < KT; t++) {
        if (t + 1 < KT) { load_stage(t + 1); CP_WAIT1(); }
        else            { CP_WAIT0(); }
        __syncthreads();

        uint32_t sa_u = s_u + (uint32_t)(t & 1) * (STG*2);
        uint32_t sb_u = sa_u + A_PANEL*2;
        #pragma unroll
        for (int kk = 0; kk < 64; kk += 16) {
            uint32_t afr[2][4], bfr[2][4];
            #pragma unroll
            for (int mi = 0; mi < 2; mi++)
                ldm_x4(afr[mi], sa_u + (((uint32_t)wm + mi*16 + q_row)*LDK + kk + q_koff)*2);
            #pragma unroll
            for (int nj = 0; nj < 2; nj++)
                ldm_x4(bfr[nj], sb_u + (((uint32_t)wn + nj*16 + q_row)*LDK + kk + q_koff)*2);
            #pragma unroll
            for (int mi = 0; mi < 2; mi++)
                #pragma unroll
                for (int ni = 0; ni < 4; ni++)
                    mma16816(d[mi][ni], afr[mi], bfr[ni>>1][ni&1], bfr[ni>>1][(ni&1)+2]);
        }
        __syncthreads();
    }

    __half* stg = sh_;
    float* red = (float*)((char*)sh_ + 20480);
    if (OUTP) {
        for (int i = tid; i < 128*3; i += 256) red[i] = 0.f;
        __syncthreads();
    }

    int qr = lane >> 2;
    int qc = (lane & 3) * 2;
    #pragma unroll
    for (int mi = 0; mi < 2; mi++) {
        #pragma unroll
        for (int rh = 0; rh < 2; rh++) {
            int rloc = wm + mi*16 + rh*8 + qr;
            long long r  = m0 + rloc;
            long long rb_ = BCAST ? (r & (HW - 1)) : r;
            float p0 = 0.f, p1 = 0.f, p2 = 0.f;
            #pragma unroll
            for (int ni = 0; ni < 4; ni++) {
                int cloc = wn + ni*8 + qc;
                long long c = n0 + cloc;
                float v0 = d[mi][ni][rh*2+0];
                float v1 = d[mi][ni][rh*2+1];
                if (bias) {
                    float2 b2 = *(const float2*)(bias + c);
                    v0 += b2.x; v1 += b2.y;
                }
                if (BCAST) {
                    float2 b2 = __half22float2(*(const __half2*)(bch + rb_*(long long)N + c));
                    v0 += b2.x; v1 += b2.y;
                }
                if (RELU) { v0 = fmaxf(v0, 0.f); v1 = fmaxf(v1, 0.f); }
                if (OUTP) {
                    const float* w0 = outWsel + c*3;
                    p0 += v0*w0[0] + v1*w0[3];
                    p1 += v0*w0[1] + v1*w0[4];
                    p2 += v0*w0[2] + v1*w0[5];
                }
                if (ADDF) {
                    float2 af2 = __half22float2(*(const __half2*)(af + r*(long long)N + c));
                    v0 += af2.x; v1 += af2.y;
                }
                if (Ch) *(__half2*)(stg + rloc*LDK + cloc) = __floats2half2_rn(v0, v1);
                if (CTh) {
                    CTh[c*(long long)M + r]     = __float2half_rn(v0);
                    CTh[(c+1)*(long long)M + r] = __float2half_rn(v1);
                }
            }
            if (OUTP) {
                #pragma unroll
                for (int o = 1; o < 4; o <<= 1) {
                    p0 += __shfl_xor_sync(0xffffffffu, p0, o);
                    p1 += __shfl_xor_sync(0xffffffffu, p1, o);
                    p2 += __shfl_xor_sync(0xffffffffu, p2, o);
                }
                if ((lane & 3) == 0) {
                    atomicAdd(&red[rloc*3+0], p0);
                    atomicAdd(&red[rloc*3+1], p1);
                    atomicAdd(&red[rloc*3+2], p2);
                }
            }
        }
    }
    __syncthreads();
    if (Ch) {
        #pragma unroll
        for (int it = 0; it < 4; it++) {
            int c = tid + it*256;
            int row = c >> 3, off = (c & 7) * 8;
            *(uint4*)(Ch + (m0 + row)*(long long)N + n0 + off) = *(const uint4*)(stg + row*LDK + off);
        }
    }
    if (OUTP) {
        for (int i = tid; i < 128*3; i += 256)
            atomicAdd(&total[(m0 + (i/3))*3 + (i%3)], red[i]);
    }
}

// ================= pair-band GEMM: G0 + G1 share A (K=128) =================
#define PR_STG (A_PANEL + 2*B_PANEL)
#define PR_SMEM (2*PR_STG*2)                 // 73728 B
__global__ __launch_bounds__(256, 2)
void pairgemm(const __half* __restrict__ A, const __half* __restrict__ wfT,
              const float* __restrict__ bf, const __half* __restrict__ hl,
              __half* __restrict__ m0h, __half* __restrict__ s1h,
              const float* __restrict__ outW, float* __restrict__ total)
{
    extern __shared__ __half sh_[];
    int tid = threadIdx.x, wid = tid >> 5, lane = tid & 31;
    long long m0 = (long long)blockIdx.y * 128;
    long long n0 = (long long)blockIdx.x * 64;
    int wm = (wid & 3) * 32;
    int wn = (wid >> 2) * 32;
    uint32_t s_u = smem_u32(sh_);

    float d0[2][4][4], d1[2][4][4];
    #pragma unroll
    for (int mi = 0; mi < 2; mi++)
        #pragma unroll
        for (int ni = 0; ni < 4; ni++)
            #pragma unroll
            for (int q = 0; q < 4; q++) { d0[mi][ni][q] = 0.f; d1[mi][ni][q] = 0.f; }

    int lr[4], lc[4];
    #pragma unroll
    for (int it = 0; it < 4; it++) {
        int idx = tid + it*256;
        lr[it] = idx >> 3;
        lc[it] = idx & 7;
    }

    auto load_stage = [&](int t) {
        uint32_t base = s_u + (uint32_t)(t & 1) * (PR_STG*2);
        int kt = t << 6;
        #pragma unroll
        for (int it = 0; it < 4; it++)
            cp16(base + (lr[it]*LDK + lc[it]*8)*2, A + (m0 + lr[it])*FD + kt + lc[it]*8);
        #pragma unroll
        for (int it = 0; it < 2; it++) {
            cp16(base + (A_PANEL + lr[it]*LDK + lc[it]*8)*2, wfT + (n0 + lr[it])*FD + kt + lc[it]*8);
            cp16(base + (A_PANEL + B_PANEL + lr[it]*LDK + lc[it]*8)*2,
                 wfT + HID*FD + (n0 + lr[it])*FD + kt + lc[it]*8);
        }
        CP_COMMIT();
    };
    load_stage(0);

    uint32_t q_row = (uint32_t)(lane & 15), q_koff = (uint32_t)(lane >> 4) * 8;

    #pragma unroll
    for (int t = 0; t < 2; t++) {
        if (t == 0) { load_stage(1); CP_WAIT1(); } else { CP_WAIT0(); }
        __syncthreads();
        uint32_t sa_u = s_u + (uint32_t)(t & 1) * (PR_STG*2);
        uint32_t sb0  = sa_u + A_PANEL*2;
        uint32_t sb1  = sb0 + B_PANEL*2;
        #pragma unroll
        for (int kk = 0; kk < 64; kk += 16) {
            uint32_t afr[2][4], b0f[2][4], b1f[2][4];
            #pragma unroll
            for (int mi = 0; mi < 2; mi++)
                ldm_x4(afr[mi], sa_u + (((uint32_t)wm + mi*16 + q_row)*LDK + kk + q_koff)*2);
            #pragma unroll
            for (int nj = 0; nj < 2; nj++) {
                ldm_x4(b0f[nj], sb0 + (((uint32_t)wn + nj*16 + q_row)*LDK + kk + q_koff)*2);
                ldm_x4(b1f[nj], sb1 + (((uint32_t)wn + nj*16 + q_row)*LDK + kk + q_koff)*2);
            }
            #pragma unroll
            for (int mi = 0; mi < 2; mi++)
                #pragma unroll
                for (int ni = 0; ni < 4; ni++) {
                    mma16816(d0[mi][ni], afr[mi], b0f[ni>>1][ni&1], b0f[ni>>1][(ni&1)+2]);
                    mma16816(d1[mi][ni], afr[mi], b1f[ni>>1][ni&1], b1f[ni>>1][(ni&1)+2]);
                }
        }
        __syncthreads();
    }

    __half* stg0 = sh_;
    __half* stg1 = sh_ + 128*LDK;
    float* red = (float*)((char*)sh_ + 40960);
    for (int i = tid; i < 128*3; i += 256) red[i] = 0.f;
    __syncthreads();

    int qr = lane >> 2;
    int qc = (lane & 3) * 2;
    const float* bf0 = bf;
    const float* bf1 = bf + HID;
    const __half* hl0 = hl;
    const __half* hl1 = hl + (size_t)HW*HID;
    #pragma unroll
    for (int mi = 0; mi < 2; mi++) {
        #pragma unroll
        for (int rh = 0; rh < 2; rh++) {
            int rloc = wm + mi*16 + rh*8 + qr;
            long long r  = m0 + rloc;
            long long rb = r & (HW - 1);
            float p0 = 0.f, p1 = 0.f, p2 = 0.f;
            #pragma unroll
            for (int ni = 0; ni < 4; ni++) {
                int cloc = wn + ni*8 + qc;
                long long c = n0 + cloc;
                float u0 = d0[mi][ni][rh*2+0];
                float u1 = d0[mi][ni][rh*2+1];
                float2 b2 = *(const float2*)(bf0 + c);
                float2 h2 = __half22float2(*(const __half2*)(hl0 + rb*HID + c));
                u0 = fmaxf(u0 + b2.x + h2.x, 0.f);
                u1 = fmaxf(u1 + b2.y + h2.y, 0.f);
                const float* w0 = outW + c*3;
                p0 += u0*w0[0] + u1*w0[3];
                p1 += u0*w0[1] + u1*w0[4];
                p2 += u0*w0[2] + u1*w0[5];
                *(__half2*)(stg0 + rloc*LDK + cloc) = __floats2half2_rn(u0, u1);
                float v0 = d1[mi][ni][rh*2+0];
                float v1 = d1[mi][ni][rh*2+1];
                float2 b3 = *(const float2*)(bf1 + c);
                float2 h3 = __half22float2(*(const __half2*)(hl1 + rb*HID + c));
                v0 = fmaxf(v0 + b3.x + h3.x, 0.f) + u0;
                v1 = fmaxf(v1 + b3.y + h3.y, 0.f) + u1;
                *(__half2*)(stg1 + rloc*LDK + cloc) = __floats2half2_rn(v0, v1);
            }
            #pragma unroll
            for (int o = 1; o < 4; o <<= 1) {
                p0 += __shfl_xor_sync(0xffffffffu, p0, o);
                p1 += __shfl_xor_sync(0xffffffffu, p1, o);
                p2 += __shfl_xor_sync(0xffffffffu, p2, o);
            }
            if ((lane & 3) == 0) {
                atomicAdd(&red[rloc*3+0], p0);
                atomicAdd(&red[rloc*3+1], p1);
                atomicAdd(&red[rloc*3+2], p2);
            }
        }
    }
    __syncthreads();
    #pragma unroll
    for (int it = 0; it < 4; it++) {
        int c = tid + it*256;
        int row = c >> 3, off = (c & 7) * 8;
        *(uint4*)(m0h + (m0 + row)*HID + n0 + off) = *(const uint4*)(stg0 + row*LDK + off);
        *(uint4*)(s1h + (m0 + row)*HID + n0 + off) = *(const uint4*)(stg1 + row*LDK + off);
    }
    for (int i = tid; i < 128*3; i += 256)
        atomicAdd(&total[(m0 + (i/3))*3 + (i%3)], red[i]);
}

// ================= fused bias (parallelized) =================
__global__ void bf_k(const float* __restrict__ bo, const float* __restrict__ modW,
                     const float* __restrict__ modb, float* __restrict__ bf)
{
    __shared__ float red[256];
    int band = blockIdx.y;
    int n0 = blockIdx.x * 64;
    int nl = threadIdx.x & 63;
    int ks = threadIdx.x >> 6;
    const float* Wm = modW + (size_t)band*HID*HID;
    float s = 0.f;
    for (int k = ks*128; k < ks*128 + 128; k++)
        s += bo[k] * Wm[(size_t)k*HID + n0 + nl];
    red[threadIdx.x] = s;
    __syncthreads();
    if (threadIdx.x < 64) {
        float t = red[threadIdx.x] + red[threadIdx.x+64] + red[threadIdx.x+128] + red[threadIdx.x+192];
        bf[band*HID + n0 + threadIdx.x] = t + modb[band*HID + n0 + threadIdx.x];
    }
}

// ================= HMMA attention =================
#define AT_QSTR 72
#define AT_KSTR 72
#define AT_VSTR 264
#define AT_PSTR 264
#define AT_SMEM ((128*AT_QSTR + 256*AT_KSTR + 64*AT_VSTR + 128*AT_PSTR)*2)
__global__ __launch_bounds__(256)
void attn_mma_k(const __half* __restrict__ qh, const __half* __restrict__ kvh,
                const float* __restrict__ tv, __half* __restrict__ out)
{
    extern __shared__ __half sm[];
    __half* sQ = sm;
    __half* sK = sQ + 128*AT_QSTR;
    __half* sV = sK + 256*AT_KSTR;
    __half* sP = sV + 64*AT_VSTR;
    int tid = threadIdx.x, wid = tid >> 5, lane = tid & 31;
    int h = blockIdx.y, b = blockIdx.z;
    long long q0 = (long long)blockIdx.x * 128;
    const __half* kvb = kvh + (size_t)b*NTOK*256;

    for (int idx = tid; idx < 1024; idx += 256) {
        int r = idx >> 3, c8 = idx & 7;
        *(uint4*)(sQ + r*AT_QSTR + c8*8) = *(const uint4*)(qh + (q0 + r)*FD + h*64 + c8*8);
    }
    for (int idx = tid; idx < 2048; idx += 256) {
        int t = idx >> 3, c8 = idx & 7;
        *(uint4*)(sK + t*AT_KSTR + c8*8) = *(const uint4*)(kvb + t*256 + h*64 + c8*8);
    }
    for (int idx = tid; idx < NTOK*64; idx += 256) {
        int t = idx >> 6, dd = idx & 63;
        sV[dd*AT_VSTR + t] = kvb[t*256 + 128 + h*64 + dd];
    }
    __syncthreads();

    uint32_t sQu = smem_u32(sQ), sKu = smem_u32(sK), sVu = smem_u32(sV), sPu = smem_u32(sP);

    float s[32][4];
    #pragma unroll
    for (int ni = 0; ni < 32; ni++)
        #pragma unroll
        for (int q = 0; q < 4; q++) s[ni][q] = 0.f;

    uint32_t a_row = (uint32_t)(wid*16 + (lane & 15)), a_koff = (uint32_t)(lane >> 4) * 8;
    uint32_t q_row = (uint32_t)(lane & 15), q_koff = (uint32_t)(lane >> 4) * 8;
    #pragma unroll
    for (int kk = 0; kk < 64; kk += 16) {
        uint32_t afr[4];
        ldm_x4(afr, sQu + (a_row*AT_QSTR + kk + a_koff)*2);
        #pragma unroll
        for (int nj = 0; nj < 16; nj++) {
            uint32_t bfr[4];
            ldm_x4(bfr, sKu + (((uint32_t)nj*16 + q_row)*AT_KSTR + kk + q_koff)*2);
            mma16816(s[nj*2],   afr, bfr[0], bfr[2]);
            mma16816(s[nj*2+1], afr, bfr[1], bfr[3]);
        }
    }

    int rq = wid*16 + (lane >> 2);
    float tq0 = tv[q0 + rq];
    float tq1 = tv[q0 + rq + 8];
    float mx0 = -1e30f, mx1 = -1e30f;
    #pragma unroll
    for (int ni = 0; ni < 32; ni++) {
        #pragma unroll
        for (int c = 0; c < 2; c++) {
            float pos = ((float)(ni*8 + (lane & 3)*2 + c) + 0.5f) * (1.0f/256.0f);
            float d0 = tq0 - pos, d1 = tq1 - pos;
            s[ni][c]   = s[ni][c]*0.125f   - 10.0f*d0*d0;
            s[ni][c+2] = s[ni][c+2]*0.125f - 10.0f*d1*d1;
            mx0 = fmaxf(mx0, s[ni][c]);
            mx1 = fmaxf(mx1, s[ni][c+2]);
        }
    }
    #pragma unroll
    for (int o = 1; o < 4; o <<= 1) {
        mx0 = fmaxf(mx0, __shfl_xor_sync(0xffffffffu, mx0, o));
        mx1 = fmaxf(mx1, __shfl_xor_sync(0xffffffffu, mx1, o));
    }
    float den0 = 0.f, den1 = 0.f;
    #pragma unroll
    for (int ni = 0; ni < 32; ni++) {
        #pragma unroll
        for (int c = 0; c < 2; c++) {
            s[ni][c]   = __expf(s[ni][c]   - mx0);
            s[ni][c+2] = __expf(s[ni][c+2] - mx1);
            den0 += s[ni][c];
            den1 += s[ni][c+2];
        }
    }
    #pragma unroll
    for (int o = 1; o < 4; o <<= 1) {
        den0 += __shfl_xor_sync(0xffffffffu, den0, o);
        den1 += __shfl_xor_sync(0xffffffffu, den1, o);
    }
    float inv0 = 1.0f / den0, inv1 = 1.0f / den1;
    int cbase = (lane & 3)*2;
    #pragma unroll
    for (int ni = 0; ni < 32; ni++) {
        *(__half2*)(sP + rq*AT_PSTR + ni*8 + cbase) =
            __floats2half2_rn(s[ni][0]*inv0, s[ni][1]*inv0);
        *(__half2*)(sP + (rq+8)*AT_PSTR + ni*8 + cbase) =
            __floats2half2_rn(s[ni][2]*inv1, s[ni][3]*inv1);
    }
    __syncthreads();

    float o[8][4];
    #pragma unroll
    for (int nj = 0; nj < 8; nj++)
        #pragma unroll
        for (int q = 0; q < 4; q++) o[nj][q] = 0.f;

    #pragma unroll
    for (int kk = 0; kk < 256; kk += 16) {
        uint32_t afr[4];
        ldm_x4(afr, sPu + (a_row*AT_PSTR + kk + a_koff)*2);
        #pragma unroll
        for (int nj = 0; nj < 4; nj++) {
            uint32_t bfr[4];
            ldm_x4(bfr, sVu + (((uint32_t)nj*16 + q_row)*AT_VSTR + kk + q_koff)*2);
            mma16816(o[nj*2],   afr, bfr[0], bfr[2]);
            mma16816(o[nj*2+1], afr, bfr[1], bfr[3]);
        }
    }

    long long qi0 = q0 + rq;
    __half* op0 = out + ((size_t)b*HW + qi0)*FD + h*64;
    __half* op1 = op0 + (size_t)8*FD;
    #pragma unroll
    for (int nj = 0; nj < 8; nj++) {
        *(__half2*)(op0 + nj*8 + cbase) = __floats2half2_rn(o[nj][0], o[nj][1]);
        *(__half2*)(op1 + nj*8 + cbase) = __floats2half2_rn(o[nj][2], o[nj][3]);
    }
}

// ================= launch =================
extern "C" void kernel_launch(void* const* d_in, const int* in_sizes, int n_in,
                              void* d_out, int out_size)
{
    const float* x      = (const float*)d_in[0];
    const float* tokens = (const float*)d_in[1];
    const float* qW     = (const float*)d_in[2];
    const float* qb     = (const float*)d_in[3];
    const float* Wq     = (const float*)d_in[4];
    const float* Wkv    = (const float*)d_in[5];
    const float* Wo     = (const float*)d_in[6];
    const float* bo     = (const float*)d_in[7];
    const float* bwW    = (const float*)d_in[8];
    const float* bwb    = (const float*)d_in[9];
    const float* modW   = (const float*)d_in[10];
    const float* modb   = (const float*)d_in[11];
    const float* hvW    = (const float*)d_in[12];
    const float* hvb    = (const float*)d_in[13];
    const float* outW   = (const float*)d_in[14];
    const float* outb   = (const float*)d_in[15];
    float* total = (float*)d_out;

    __half *gqh, *glh, *xqh, *qh, *kvh, *attnh, *s1h, *m0h, *g2h, *tokh, *hlh;
    __half *qWT, *WqT, *WkvT, *bwWT, *modWT, *hvWT, *WoA, *wfT;
    float *tv, *bfp;
    cudaGetSymbolAddress((void**)&gqh,   g_gq_h);
    cudaGetSymbolAddress((void**)&glh,   g_gl_h);
    cudaGetSymbolAddress((void**)&xqh,   g_xq_h);
    cudaGetSymbolAddress((void**)&qh,    g_q_h);
    cudaGetSymbolAddress((void**)&kvh,   g_kv_h);
    cudaGetSymbolAddress((void**)&attnh, g_attn_h);
    cudaGetSymbolAddress((void**)&s1h,   g_s_h);
    cudaGetSymbolAddress((void**)&m0h,   g_m0_h);
    cudaGetSymbolAddress((void**)&g2h,   g_g2_h);
    cudaGetSymbolAddress((void**)&tokh,  g_tok_h);
    cudaGetSymbolAddress((void**)&hlh,   g_hl_h);
    cudaGetSymbolAddress((void**)&qWT,   g_qWT);
    cudaGetSymbolAddress((void**)&WqT,   g_WqT);
    cudaGetSymbolAddress((void**)&WkvT,  g_WkvT);
    cudaGetSymbolAddress((void**)&bwWT,  g_bwWT);
    cudaGetSymbolAddress((void**)&modWT, g_modWT);
    cudaGetSymbolAddress((void**)&hvWT,  g_hvWT);
    cudaGetSymbolAddress((void**)&WoA,   g_WoA);
    cudaGetSymbolAddress((void**)&wfT,   g_wfT);
    cudaGetSymbolAddress((void**)&tv,    g_tv);
    cudaGetSymbolAddress((void**)&bfp,   g_bf);

    cudaFuncSetAttribute(tgemm<true,false,false,false,2>,  cudaFuncAttributeMaxDynamicSharedMemorySize, TG_SMEM);
    cudaFuncSetAttribute(tgemm<false,false,false,false,8>, cudaFuncAttributeMaxDynamicSharedMemorySize, TG_SMEM);
    cudaFuncSetAttribute(tgemm<true,true,false,false,2>,   cudaFuncAttributeMaxDynamicSharedMemorySize, TG_SMEM);
    cudaFuncSetAttribute(tgemm<true,false,true,true,8>,    cudaFuncAttributeMaxDynamicSharedMemorySize, TG_SMEM);
    cudaFuncSetAttribute(tgemm<true,false,false,true,8>,   cudaFuncAttributeMaxDynamicSharedMemorySize, TG_SMEM);
    cudaFuncSetAttribute(pairgemm, cudaFuncAttributeMaxDynamicSharedMemorySize, PR_SMEM);
    cudaFuncSetAttribute(attn_mma_k, cudaFuncAttributeMaxDynamicSharedMemorySize, AT_SMEM);

    // 1) gamma  2) prep  3) bf
    gamma_k<<<HW, 128>>>(x, gqh, glh, tv);
    prep_k<<<(int)((PREP_TOTAL + 255)/256), 256>>>(
        qW, Wq, Wkv, bwW, modW, hvW, Wo, tokens, outb,
        qWT, WqT, WkvT, bwWT, modWT, hvWT, WoA, tokh, total);
    bf_k<<<dim3(8,3), 256>>>(bo, modW, modb, bfp);

    // 4) xq = relu(gq @ qW + qb) -> fp16
    tgemm<true,false,false,false,2><<<dim3(8,128), 256, TG_SMEM>>>(
        gqh, qWT, qb, nullptr, nullptr, xqh, nullptr, nullptr, nullptr, HW, HID,
        0, 0, 0, 0, 0);

    // 5) kv = tokens @ Wkv -> fp16
    tgemm<false,false,false,false,8><<<dim3(4,16), 256, TG_SMEM>>>(
        tokh, WkvT, nullptr, nullptr, nullptr, kvh, nullptr, nullptr, nullptr, NB*NTOK, 256,
        0, 0, 0, 0, 0);

    // 6) h_l (banded: z=0..2) -> fp16
    tgemm<true,false,false,false,2><<<dim3(8,128,3), 256, TG_SMEM>>>(
        glh, bwWT, bwb, nullptr, nullptr, hlh, nullptr, nullptr, nullptr, HW, HID,
        (long long)HW*FD, (long long)HID*FD, HID, (long long)HW*HID, 0);

    // 7) q = xq @ Wq -> fp16
    tgemm<false,false,false,false,8><<<dim3(2,128), 256, TG_SMEM>>>(
        xqh, WqT, nullptr, nullptr, nullptr, qh, nullptr, nullptr, nullptr, HW, FD,
        0, 0, 0, 0, 0);

    // 8) wfT (banded: z=0..2) = (Wo @ modW[z])^T -> fp16 [512][128]
    tgemm<false,false,false,false,8><<<dim3(8,1,3), 256, TG_SMEM>>>(
        WoA, modWT, nullptr, nullptr, nullptr,
        nullptr, wfT, nullptr, nullptr, FD, HID,
        0, (long long)HID*HID, 0, 0, (long long)HID*FD);

    // 9) attention
    attn_mma_k<<<dim3(HW/128, 2, NB), 256, AT_SMEM>>>(qh, kvh, tv, attnh);

    // 10) G2 = relu(attn@wf2 + bf2 + hl2) -> g2h
    tgemm<true,true,false,false,2><<<dim3(8,1024), 256, TG_SMEM>>>(
        attnh, wfT + 2*HID*FD, bfp + 2*HID, hlh + 2ull*HW*HID, nullptr,
        g2h, nullptr, nullptr, nullptr, MROWS, HID,
        0, 0, 0, 0, 0);

    // 11) pair: m0h (+outproj outW0) and s1h
    pairgemm<<<dim3(8,1024), 256, PR_SMEM>>>(
        attnh, wfT, bfp, hlh, m0h, s1h, outW, total);

    // 12) HV1: relu(s1@hvW0 + hvb0); total += HV1@outW1; +g2 -> s2 (into m0h)
    tgemm<true,false,true,true,8><<<dim3(8,1024), 256, TG_SMEM>>>(
        s1h, hvWT, hvb, nullptr, g2h, m0h, nullptr,
        outW + 512*3, total, MROWS, HID,
        0, 0, 0, 0, 0);

    // 13) HV2: relu(s2@hvW1 + hvb1); total += HV2@outW2
    tgemm<true,false,false,true,8><<<dim3(8,1024), 256, TG_SMEM>>>(
        m0h, hvWT + (size_t)HID*HID, hvb + HID, nullptr, nullptr, nullptr,
        nullptr, outW + 2*512*3, total, MROWS, HID,
        0, 0, 0, 0, 0);
}

// round 14
// speedup vs baseline: 1.9139x; 1.0407x over previous
#include <cuda_runtime.h>
#include <cuda_fp16.h>
#include <math.h>
#include <stdint.h>

#define HW 16384
#define NB 8
#define MROWS (NB*HW)      // 131072
#define HID 512
#define FD 128
#define NTOK 256
#define PI_D 3.14159265358979323846
#define TWO_PI_D 6.28318530717958647692
#define INV_2PI_D 0.15915494309189533577

// ---------------- fp16 buffers ----------------
__device__ __half g_gq_h[HW*FD];
__device__ __half g_gl_h[3ull*HW*FD];
__device__ __half g_xq_h[HW*HID];
__device__ __half g_q_h[HW*FD];
__device__ __half g_kv_h[NB*NTOK*256];
__device__ __half g_attn_h[(unsigned long long)MROWS*FD];
__device__ __half g_s_h[(unsigned long long)MROWS*HID];   // S1
__device__ __half g_m0_h[(unsigned long long)MROWS*HID];  // M0, reused as S2
__device__ __half g_g2_h[(unsigned long long)MROWS*HID];  // reluG2
__device__ __half g_tok_h[NB*NTOK*HID];
__device__ __half g_hl_h[3ull*HW*HID];
__device__ __half g_qWT[HID*FD];
__device__ __half g_WqT[FD*HID];
__device__ __half g_WkvT[256*HID];
__device__ __half g_bwWT[3*HID*FD];
__device__ __half g_modWT[3*HID*HID];
__device__ __half g_hvWT[2*HID*HID];
__device__ __half g_WoA[FD*HID];
__device__ __half g_wfT[3*HID*FD];
// ---------------- fp32 buffers ----------------
__device__ float g_tv[HW];
__device__ float g_bf[3*HID];

// ================= helpers =================
__device__ __forceinline__ uint32_t smem_u32(const void* p) {
    uint32_t a;
    asm("{ .reg .u64 t; cvta.to.shared.u64 t, %1; cvt.u32.u64 %0, t; }" : "=r"(a) : "l"(p));
    return a;
}
__device__ __forceinline__ void ldm_x4(uint32_t* r, uint32_t addr) {
    asm volatile("ldmatrix.sync.aligned.m8n8.x4.shared.b16 {%0,%1,%2,%3}, [%4];"
                 : "=r"(r[0]), "=r"(r[1]), "=r"(r[2]), "=r"(r[3]) : "r"(addr));
}
__device__ __forceinline__ void mma16816(float* d, const uint32_t* a, uint32_t b0, uint32_t b1) {
    asm volatile(
        "mma.sync.aligned.m16n8k16.row.col.f32.f16.f16.f32 "
        "{%0,%1,%2,%3}, {%4,%5,%6,%7}, {%8,%9}, {%0,%1,%2,%3};"
        : "+f"(d[0]), "+f"(d[1]), "+f"(d[2]), "+f"(d[3])
        : "r"(a[0]), "r"(a[1]), "r"(a[2]), "r"(a[3]), "r"(b0), "r"(b1));
}
__device__ __forceinline__ void cp16(uint32_t dst, const void* src) {
    asm volatile("cp.async.cg.shared.global [%0], [%1], 16;" :: "r"(dst), "l"(src));
}
#define CP_COMMIT() asm volatile("cp.async.commit_group;" ::: "memory")
#define CP_WAIT1()  asm volatile("cp.async.wait_group 1;" ::: "memory")
#define CP_WAIT0()  asm volatile("cp.async.wait_group 0;" ::: "memory")

// ================= Fourier features (fp32 trig + DP range reduction) =================
__global__ void gamma_k(const float* __restrict__ x, __half* __restrict__ gq,
                        __half* __restrict__ gl, float* __restrict__ tv)
{
    __shared__ double omg[128];
    int q = blockIdx.x;
    int f = threadIdx.x;
    {
        const double sig[4] = {128.0, 16.0, 64.0, 256.0};
        int s = f >> 5, j = f & 31;
        double step = (log10(sig[s]) - 1.0) / 31.0;
        omg[f] = pow(10.0, 1.0 + (double)j * step);
    }
    __syncthreads();

    float c0 = x[2*q], c1 = x[2*q+1];
    if (f == 0) {
        int r  = (int)(c0 * 16.0f);
        int cc = (int)(c1 * 16.0f);
        tv[q] = (float)(r*16 + cc) * (1.0f/256.0f);
    }
    int d = f >> 6;
    int rr = f & 63;
    int part = rr >> 5;
    int j = rr & 31;
    double pc = PI_D * (d ? (double)c1 : (double)c0);
    #pragma unroll
    for (int s = 0; s < 4; s++) {
        double arg = pc * omg[s*32 + j];
        double qf  = floor(arg * INV_2PI_D);
        float r    = (float)(arg - qf * TWO_PI_D);
        float val  = part ? cosf(r) : sinf(r);
        __half* dst = (s == 0) ? gq : (gl + (size_t)(s-1)*HW*FD);
        dst[(size_t)q*FD + f] = __float2half_rn(val);
    }
}

// ================= merged weight prep =================
__global__ void prep_k(const float* __restrict__ qW, const float* __restrict__ Wq,
                       const float* __restrict__ Wkv, const float* __restrict__ bwW,
                       const float* __restrict__ modW, const float* __restrict__ hvW,
                       const float* __restrict__ Wo, const float* __restrict__ tokens,
                       const float* __restrict__ outb,
                       __half* __restrict__ qWT, __half* __restrict__ WqT,
                       __half* __restrict__ WkvT, __half* __restrict__ bwWT,
                       __half* __restrict__ modWT, __half* __restrict__ hvWT,
                       __half* __restrict__ WoA, __half* __restrict__ tokh,
                       float* __restrict__ total)
{
    long long i = (long long)blockIdx.x * 256 + threadIdx.x;
    if (i < 65536) {
        int k = (int)(i/512), n = (int)(i%512);
        qWT[n*128+k] = __float2half_rn(qW[i]); return;
    } i -= 65536;
    if (i < 65536) {
        int k = (int)(i/128), n = (int)(i%128);
        WqT[n*512+k] = __float2half_rn(Wq[i]); return;
    } i -= 65536;
    if (i < 131072) {
        int k = (int)(i/256), n = (int)(i%256);
        WkvT[n*512+k] = __float2half_rn(Wkv[i]); return;
    } i -= 131072;
    if (i < 196608) {
        int s = (int)(i/65536); long long j = i%65536;
        int k = (int)(j/512), n = (int)(j%512);
        bwWT[s*65536 + n*128+k] = __float2half_rn(bwW[i]); return;
    } i -= 196608;
    if (i < 786432) {
        int s = (int)(i/262144); long long j = i%262144;
        int k = (int)(j/512), n = (int)(j%512);
        modWT[s*262144 + n*512+k] = __float2half_rn(modW[i]); return;
    } i -= 786432;
    if (i < 524288) {
        int s = (int)(i/262144); long long j = i%262144;
        int k = (int)(j/512), n = (int)(j%512);
        hvWT[s*262144 + n*512+k] = __float2half_rn(hvW[i]); return;
    } i -= 524288;
    if (i < 65536) { WoA[i] = __float2half_rn(Wo[i]); return; } i -= 65536;
    if (i < 1048576) { tokh[i] = __float2half_rn(tokens[i]); return; } i -= 1048576;
    if (i < (long long)MROWS*3) {
        int c = (int)(i % 3);
        total[i] = outb[c] + outb[3+c] + outb[6+c];
    }
}
#define PREP_TOTAL 3276800LL

// ================= HMMA fp16 GEMM (round-10 core; z-strided for banded launches) =================
#define LDK 72
#define A_PANEL (128*LDK)
#define B_PANEL (64*LDK)
#define STG (A_PANEL + B_PANEL)
#define TG_SMEM (2*STG*2)          // 55296 B
template<bool RELU, bool BCAST, bool ADDF, bool OUTP, int KT>
__global__ __launch_bounds__(256, 3)
void tgemm(const __half* __restrict__ A, const __half* __restrict__ WT,
           const float* __restrict__ bias, const __half* __restrict__ bch,
           const __half* __restrict__ af,
           __half* __restrict__ Ch, __half* __restrict__ CTh,
           const float* __restrict__ outWsel, float* __restrict__ total,
           int M, int N,
           long long zA, long long zW, long long zB, long long zC, long long zCT)
{
    const int K = KT*64;
    long long z = blockIdx.z;
    A   += z * zA;
    WT  += z * zW;
    if (bias) bias += z * zB;
    if (Ch)   Ch   += z * zC;
    if (CTh)  CTh  += z * zCT;

    extern __shared__ __half sh_[];
    int tid = threadIdx.x, wid = tid >> 5, lane = tid & 31;
    long long m0 = (long long)blockIdx.y * 128;
    long long n0 = (long long)blockIdx.x * 64;
    int wm = (wid & 3) * 32;
    int wn = (wid >> 2) * 32;

    float d[2][4][4];
    #pragma unroll
    for (int mi = 0; mi < 2; mi++)
        #pragma unroll
        for (int ni = 0; ni < 4; ni++)
            #pragma unroll
            for (int q = 0; q < 4; q++) d[mi][ni][q] = 0.f;

    uint32_t s_u = smem_u32(sh_);
    int lr[4], lc[4];
    #pragma unroll
    for (int it = 0; it < 4; it++) {
        int idx = tid + it*256;
        lr[it] = idx >> 3;
        lc[it] = idx & 7;
    }

    auto load_stage = [&](int t) {
        uint32_t base = s_u + (uint32_t)(t & 1) * (STG*2);
        int kt = t << 6;
        #pragma unroll
        for (int it = 0; it < 4; it++)
            cp16(base + (lr[it]*LDK + lc[it]*8)*2, A + (m0 + lr[it])*(long long)K + kt + lc[it]*8);
        #pragma unroll
        for (int it = 0; it < 2; it++)
            cp16(base + (A_PANEL + lr[it]*LDK + lc[it]*8)*2, WT + (n0 + lr[it])*(long long)K + kt + lc[it]*8);
        CP_COMMIT();
    };

    load_stage(0);

    uint32_t q_row = (uint32_t)(lane & 15), q_koff = (uint32_t)(lane >> 4) * 8;

    #pragma unroll
    for (int t = 0; t < KT; t++) {
        if (t + 1 < KT) { load_stage(t + 1); CP_WAIT1(); }
        else            { CP_WAIT0(); }
        __syncthreads();

        uint32_t sa_u = s_u + (uint32_t)(t & 1) * (STG*2);
        uint32_t sb_u = sa_u + A_PANEL*2;
        #pragma unroll
        for (int kk = 0; kk < 64; kk += 16) {
            uint32_t afr[2][4], bfr[2][4];
            #pragma unroll
            for (int mi = 0; mi < 2; mi++)
                ldm_x4(afr[mi], sa_u + (((uint32_t)wm + mi*16 + q_row)*LDK + kk + q_koff)*2);
            #pragma unroll
            for (int nj = 0; nj < 2; nj++)
                ldm_x4(bfr[nj], sb_u + (((uint32_t)wn + nj*16 + q_row)*LDK + kk + q_koff)*2);
            #pragma unroll
            for (int mi = 0; mi < 2; mi++)
                #pragma unroll
                for (int ni = 0; ni < 4; ni++)
                    mma16816(d[mi][ni], afr[mi], bfr[ni>>1][ni&1], bfr[ni>>1][(ni&1)+2]);
        }
        __syncthreads();
    }

    __half* stg = sh_;
    float* red = (float*)((char*)sh_ + 20480);
    if (OUTP) {
        for (int i = tid; i < 128*3; i += 256) red[i] = 0.f;
        __syncthreads();
    }

    int qr = lane >> 2;
    int qc = (lane & 3) * 2;
    #pragma unroll
    for (int mi = 0; mi < 2; mi++) {
        #pragma unroll
        for (int rh = 0; rh < 2; rh++) {
            int rloc = wm + mi*16 + rh*8 + qr;
            long long r  = m0 + rloc;
            long long rb_ = BCAST ? (r & (HW - 1)) : r;
            float p0 = 0.f, p1 = 0.f, p2 = 0.f;
            #pragma unroll
            for (int ni = 0; ni < 4; ni++) {
                int cloc = wn + ni*8 + qc;
                long long c = n0 + cloc;
                float v0 = d[mi][ni][rh*2+0];
                float v1 = d[mi][ni][rh*2+1];
                if (bias) {
                    float2 b2 = *(const float2*)(bias + c);
                    v0 += b2.x; v1 += b2.y;
                }
                if (BCAST) {
                    float2 b2 = __half22float2(*(const __half2*)(bch + rb_*(long long)N + c));
                    v0 += b2.x; v1 += b2.y;
                }
                if (RELU) { v0 = fmaxf(v0, 0.f); v1 = fmaxf(v1, 0.f); }
                if (OUTP) {
                    const float* w0 = outWsel + c*3;
                    p0 += v0*w0[0] + v1*w0[3];
                    p1 += v0*w0[1] + v1*w0[4];
                    p2 += v0*w0[2] + v1*w0[5];
                }
                if (ADDF) {
                    float2 af2 = __half22float2(*(const __half2*)(af + r*(long long)N + c));
                    v0 += af2.x; v1 += af2.y;
                }
                if (Ch) *(__half2*)(stg + rloc*LDK + cloc) = __floats2half2_rn(v0, v1);
                if (CTh) {
                    CTh[c*(long long)M + r]     = __float2half_rn(v0);
                    CTh[(c+1)*(long long)M + r] = __float2half_rn(v1);
                }
            }
            if (OUTP) {
                #pragma unroll
                for (int o = 1; o < 4; o <<= 1) {
                    p0 += __shfl_xor_sync(0xffffffffu, p0, o);
                    p1 += __shfl_xor_sync(0xffffffffu, p1, o);
                    p2 += __shfl_xor_sync(0xffffffffu, p2, o);
                }
                if ((lane & 3) == 0) {
                    atomicAdd(&red[rloc*3+0], p0);
                    atomicAdd(&red[rloc*3+1], p1);
                    atomicAdd(&red[rloc*3+2], p2);
                }
            }
        }
    }
    __syncthreads();
    if (Ch) {
        #pragma unroll
        for (int it = 0; it < 4; it++) {
            int c = tid + it*256;
            int row = c >> 3, off = (c & 7) * 8;
            *(uint4*)(Ch + (m0 + row)*(long long)N + n0 + off) = *(const uint4*)(stg + row*LDK + off);
        }
    }
    if (OUTP) {
        for (int i = tid; i < 128*3; i += 256)
            atomicAdd(&total[(m0 + (i/3))*3 + (i%3)], red[i]);
    }
}

// ================= pair-band GEMM: G0 + G1 share A (K=128) =================
#define PR_STG (A_PANEL + 2*B_PANEL)
#define PR_SMEM (2*PR_STG*2)                 // 73728 B
__global__ __launch_bounds__(256, 2)
void pairgemm(const __half* __restrict__ A, const __half* __restrict__ wfT,
              const float* __restrict__ bf, const __half* __restrict__ hl,
              __half* __restrict__ m0h, __half* __restrict__ s1h,
              const float* __restrict__ outW, float* __restrict__ total)
{
    extern __shared__ __half sh_[];
    int tid = threadIdx.x, wid = tid >> 5, lane = tid & 31;
    long long m0 = (long long)blockIdx.y * 128;
    long long n0 = (long long)blockIdx.x * 64;
    int wm = (wid & 3) * 32;
    int wn = (wid >> 2) * 32;
    uint32_t s_u = smem_u32(sh_);

    float d0[2][4][4], d1[2][4][4];
    #pragma unroll
    for (int mi = 0; mi < 2; mi++)
        #pragma unroll
        for (int ni = 0; ni < 4; ni++)
            #pragma unroll
            for (int q = 0; q < 4; q++) { d0[mi][ni][q] = 0.f; d1[mi][ni][q] = 0.f; }

    int lr[4], lc[4];
    #pragma unroll
    for (int it = 0; it < 4; it++) {
        int idx = tid + it*256;
        lr[it] = idx >> 3;
        lc[it] = idx & 7;
    }

    auto load_stage = [&](int t) {
        uint32_t base = s_u + (uint32_t)(t & 1) * (PR_STG*2);
        int kt = t << 6;
        #pragma unroll
        for (int it = 0; it < 4; it++)
            cp16(base + (lr[it]*LDK + lc[it]*8)*2, A + (m0 + lr[it])*FD + kt + lc[it]*8);
        #pragma unroll
        for (int it = 0; it < 2; it++) {
            cp16(base + (A_PANEL + lr[it]*LDK + lc[it]*8)*2, wfT + (n0 + lr[it])*FD + kt + lc[it]*8);
            cp16(base + (A_PANEL + B_PANEL + lr[it]*LDK + lc[it]*8)*2,
                 wfT + HID*FD + (n0 + lr[it])*FD + kt + lc[it]*8);
        }
        CP_COMMIT();
    };
    load_stage(0);

    uint32_t q_row = (uint32_t)(lane & 15), q_koff = (uint32_t)(lane >> 4) * 8;

    #pragma unroll
    for (int t = 0; t < 2; t++) {
        if (t == 0) { load_stage(1); CP_WAIT1(); } else { CP_WAIT0(); }
        __syncthreads();
        uint32_t sa_u = s_u + (uint32_t)(t & 1) * (PR_STG*2);
        uint32_t sb0  = sa_u + A_PANEL*2;
        uint32_t sb1  = sb0 + B_PANEL*2;
        #pragma unroll
        for (int kk = 0; kk < 64; kk += 16) {
            uint32_t afr[2][4], b0f[2][4], b1f[2][4];
            #pragma unroll
            for (int mi = 0; mi < 2; mi++)
                ldm_x4(afr[mi], sa_u + (((uint32_t)wm + mi*16 + q_row)*LDK + kk + q_koff)*2);
            #pragma unroll
            for (int nj = 0; nj < 2; nj++) {
                ldm_x4(b0f[nj], sb0 + (((uint32_t)wn + nj*16 + q_row)*LDK + kk + q_koff)*2);
                ldm_x4(b1f[nj], sb1 + (((uint32_t)wn + nj*16 + q_row)*LDK + kk + q_koff)*2);
            }
            #pragma unroll
            for (int mi = 0; mi < 2; mi++)
                #pragma unroll
                for (int ni = 0; ni < 4; ni++) {
                    mma16816(d0[mi][ni], afr[mi], b0f[ni>>1][ni&1], b0f[ni>>1][(ni&1)+2]);
                    mma16816(d1[mi][ni], afr[mi], b1f[ni>>1][ni&1], b1f[ni>>1][(ni&1)+2]);
                }
        }
        __syncthreads();
    }

    __half* stg0 = sh_;
    __half* stg1 = sh_ + 128*LDK;
    float* red = (float*)((char*)sh_ + 40960);
    for (int i = tid; i < 128*3; i += 256) red[i] = 0.f;
    __syncthreads();

    int qr = lane >> 2;
    int qc = (lane & 3) * 2;
    const float* bf0 = bf;
    const float* bf1 = bf + HID;
    const __half* hl0 = hl;
    const __half* hl1 = hl + (size_t)HW*HID;
    #pragma unroll
    for (int mi = 0; mi < 2; mi++) {
        #pragma unroll
        for (int rh = 0; rh < 2; rh++) {
            int rloc = wm + mi*16 + rh*8 + qr;
            long long r  = m0 + rloc;
            long long rb = r & (HW - 1);
            float p0 = 0.f, p1 = 0.f, p2 = 0.f;
            #pragma unroll
            for (int ni = 0; ni < 4; ni++) {
                int cloc = wn + ni*8 + qc;
                long long c = n0 + cloc;
                float u0 = d0[mi][ni][rh*2+0];
                float u1 = d0[mi][ni][rh*2+1];
                float2 b2 = *(const float2*)(bf0 + c);
                float2 h2 = __half22float2(*(const __half2*)(hl0 + rb*HID + c));
                u0 = fmaxf(u0 + b2.x + h2.x, 0.f);
                u1 = fmaxf(u1 + b2.y + h2.y, 0.f);
                const float* w0 = outW + c*3;
                p0 += u0*w0[0] + u1*w0[3];
                p1 += u0*w0[1] + u1*w0[4];
                p2 += u0*w0[2] + u1*w0[5];
                *(__half2*)(stg0 + rloc*LDK + cloc) = __floats2half2_rn(u0, u1);
                float v0 = d1[mi][ni][rh*2+0];
                float v1 = d1[mi][ni][rh*2+1];
                float2 b3 = *(const float2*)(bf1 + c);
                float2 h3 = __half22float2(*(const __half2*)(hl1 + rb*HID + c));
                v0 = fmaxf(v0 + b3.x + h3.x, 0.f) + u0;
                v1 = fmaxf(v1 + b3.y + h3.y, 0.f) + u1;
                *(__half2*)(stg1 + rloc*LDK + cloc) = __floats2half2_rn(v0, v1);
            }
            #pragma unroll
            for (int o = 1; o < 4; o <<= 1) {
                p0 += __shfl_xor_sync(0xffffffffu, p0, o);
                p1 += __shfl_xor_sync(0xffffffffu, p1, o);
                p2 += __shfl_xor_sync(0xffffffffu, p2, o);
            }
            if ((lane & 3) == 0) {
                atomicAdd(&red[rloc*3+0], p0);
                atomicAdd(&red[rloc*3+1], p1);
                atomicAdd(&red[rloc*3+2], p2);
            }
        }
    }
    __syncthreads();
    #pragma unroll
    for (int it = 0; it < 4; it++) {
        int c = tid + it*256;
        int row = c >> 3, off = (c & 7) * 8;
        *(uint4*)(m0h + (m0 + row)*HID + n0 + off) = *(const uint4*)(stg0 + row*LDK + off);
        *(uint4*)(s1h + (m0 + row)*HID + n0 + off) = *(const uint4*)(stg1 + row*LDK + off);
    }
    for (int i = tid; i < 128*3; i += 256)
        atomicAdd(&total[(m0 + (i/3))*3 + (i%3)], red[i]);
}

// ================= fused bias (parallelized) =================
__global__ void bf_k(const float* __restrict__ bo, const float* __restrict__ modW,
                     const float* __restrict__ modb, float* __restrict__ bf)
{
    __shared__ float red[256];
    int band = blockIdx.y;
    int n0 = blockIdx.x * 64;
    int nl = threadIdx.x & 63;
    int ks = threadIdx.x >> 6;
    const float* Wm = modW + (size_t)band*HID*HID;
    float s = 0.f;
    for (int k = ks*128; k < ks*128 + 128; k++)
        s += bo[k] * Wm[(size_t)k*HID + n0 + nl];
    red[threadIdx.x] = s;
    __syncthreads();
    if (threadIdx.x < 64) {
        float t = red[threadIdx.x] + red[threadIdx.x+64] + red[threadIdx.x+128] + red[threadIdx.x+192];
        bf[band*HID + n0 + threadIdx.x] = t + modb[band*HID + n0 + threadIdx.x];
    }
}

// ================= flash HMMA attention (P in registers, 2 token chunks) =================
#define AT_QSTR 72
#define AT_KSTR 72
#define AT_VSTR 264
#define AT_SMEM ((128*AT_QSTR + 256*AT_KSTR + 64*AT_VSTR)*2)   // 89088 B
__global__ __launch_bounds__(256, 2)
void attn_mma_k(const __half* __restrict__ qh, const __half* __restrict__ kvh,
                const float* __restrict__ tv, __half* __restrict__ out)
{
    extern __shared__ __half sm[];
    __half* sQ = sm;
    __half* sK = sQ + 128*AT_QSTR;
    __half* sV = sK + 256*AT_KSTR;   // V transposed: [64 dim][256 tok]
    int tid = threadIdx.x, wid = tid >> 5, lane = tid & 31;
    int h = blockIdx.y, b = blockIdx.z;
    long long q0 = (long long)blockIdx.x * 128;
    const __half* kvb = kvh + (size_t)b*NTOK*256;

    for (int idx = tid; idx < 1024; idx += 256) {
        int r = idx >> 3, c8 = idx & 7;
        *(uint4*)(sQ + r*AT_QSTR + c8*8) = *(const uint4*)(qh + (q0 + r)*FD + h*64 + c8*8);
    }
    for (int idx = tid; idx < 2048; idx += 256) {
        int t = idx >> 3, c8 = idx & 7;
        *(uint4*)(sK + t*AT_KSTR + c8*8) = *(const uint4*)(kvb + t*256 + h*64 + c8*8);
    }
    for (int idx = tid; idx < NTOK*64; idx += 256) {
        int t = idx >> 6, dd = idx & 63;
        sV[dd*AT_VSTR + t] = kvb[t*256 + 128 + h*64 + dd];
    }
    __syncthreads();

    uint32_t sQu = smem_u32(sQ), sKu = smem_u32(sK), sVu = smem_u32(sV);

    uint32_t a_row = (uint32_t)(wid*16 + (lane & 15)), a_koff = (uint32_t)(lane >> 4) * 8;
    uint32_t q_row = (uint32_t)(lane & 15), q_koff = (uint32_t)(lane >> 4) * 8;
    int rq = wid*16 + (lane >> 2);
    int qc = (lane & 3) * 2;
    float tq0 = tv[q0 + rq];
    float tq1 = tv[q0 + rq + 8];
    float mx0 = -1e30f, mx1 = -1e30f, den0 = 0.f, den1 = 0.f;

    float o[8][4];
    #pragma unroll
    for (int nj = 0; nj < 8; nj++)
        #pragma unroll
        for (int q = 0; q < 4; q++) o[nj][q] = 0.f;

    #pragma unroll
    for (int c = 0; c < 2; c++) {
        // ---- S chunk = Q K_chunk^T : 16 rows x 128 tokens ----
        float s[16][4];
        #pragma unroll
        for (int ni = 0; ni < 16; ni++)
            #pragma unroll
            for (int q = 0; q < 4; q++) s[ni][q] = 0.f;

        #pragma unroll
        for (int kk = 0; kk < 64; kk += 16) {
            uint32_t afr[4];
            ldm_x4(afr, sQu + (a_row*AT_QSTR + kk + a_koff)*2);
            #pragma unroll
            for (int nj = 0; nj < 8; nj++) {
                uint32_t bfr[4];
                ldm_x4(bfr, sKu + (((uint32_t)(c*128 + nj*16) + q_row)*AT_KSTR + kk + q_koff)*2);
                mma16816(s[nj*2],   afr, bfr[0], bfr[2]);
                mma16816(s[nj*2+1], afr, bfr[1], bfr[3]);
            }
        }

        // ---- bias + chunk max ----
        float cm0 = -1e30f, cm1 = -1e30f;
        #pragma unroll
        for (int ni = 0; ni < 16; ni++) {
            #pragma unroll
            for (int cc = 0; cc < 2; cc++) {
                float pos = ((float)(c*128 + ni*8 + qc + cc) + 0.5f) * (1.0f/256.0f);
                float dd0 = tq0 - pos, dd1 = tq1 - pos;
                s[ni][cc]   = s[ni][cc]*0.125f   - 10.0f*dd0*dd0;
                s[ni][cc+2] = s[ni][cc+2]*0.125f - 10.0f*dd1*dd1;
                cm0 = fmaxf(cm0, s[ni][cc]);
                cm1 = fmaxf(cm1, s[ni][cc+2]);
            }
        }
        #pragma unroll
        for (int oo = 1; oo < 4; oo <<= 1) {
            cm0 = fmaxf(cm0, __shfl_xor_sync(0xffffffffu, cm0, oo));
            cm1 = fmaxf(cm1, __shfl_xor_sync(0xffffffffu, cm1, oo));
        }
        float nm0 = fmaxf(mx0, cm0), nm1 = fmaxf(mx1, cm1);
        float f0 = __expf(mx0 - nm0), f1 = __expf(mx1 - nm1);
        mx0 = nm0; mx1 = nm1;

        float ds0 = 0.f, ds1 = 0.f;
        #pragma unroll
        for (int ni = 0; ni < 16; ni++) {
            s[ni][0] = __expf(s[ni][0] - nm0);
            s[ni][1] = __expf(s[ni][1] - nm0);
            s[ni][2] = __expf(s[ni][2] - nm1);
            s[ni][3] = __expf(s[ni][3] - nm1);
            ds0 += s[ni][0] + s[ni][1];
            ds1 += s[ni][2] + s[ni][3];
        }
        den0 = den0*f0 + ds0;
        den1 = den1*f1 + ds1;

        // rescale O
        #pragma unroll
        for (int nj = 0; nj < 8; nj++) {
            o[nj][0] *= f0; o[nj][1] *= f0;
            o[nj][2] *= f1; o[nj][3] *= f1;
        }

        // ---- PV: P fragments built in registers from S accumulators ----
        #pragma unroll
        for (int m = 0; m < 8; m++) {
            uint32_t pf[4];
            __half2 h0 = __floats2half2_rn(s[2*m][0],   s[2*m][1]);
            __half2 h1 = __floats2half2_rn(s[2*m][2],   s[2*m][3]);
            __half2 h2 = __floats2half2_rn(s[2*m+1][0], s[2*m+1][1]);
            __half2 h3 = __floats2half2_rn(s[2*m+1][2], s[2*m+1][3]);
            pf[0] = *(uint32_t*)&h0; pf[1] = *(uint32_t*)&h1;
            pf[2] = *(uint32_t*)&h2; pf[3] = *(uint32_t*)&h3;
            #pragma unroll
            for (int nj = 0; nj < 4; nj++) {
                uint32_t bfr[4];
                ldm_x4(bfr, sVu + (((uint32_t)(nj*16) + q_row)*AT_VSTR + (c*128 + m*16) + q_koff)*2);
                mma16816(o[nj*2],   pf, bfr[0], bfr[2]);
                mma16816(o[nj*2+1], pf, bfr[1], bfr[3]);
            }
        }
    }

    // FIX (round 13 bug): reduce denominator across the 4 lanes sharing each row.
    #pragma unroll
    for (int oo = 1; oo < 4; oo <<= 1) {
        den0 += __shfl_xor_sync(0xffffffffu, den0, oo);
        den1 += __shfl_xor_sync(0xffffffffu, den1, oo);
    }

    float inv0 = 1.0f / den0, inv1 = 1.0f / den1;
    long long qi0 = q0 + rq;
    __half* op0 = out + ((size_t)b*HW + qi0)*FD + h*64;
    __half* op1 = op0 + (size_t)8*FD;
    #pragma unroll
    for (int nj = 0; nj < 8; nj++) {
        *(__half2*)(op0 + nj*8 + qc) = __floats2half2_rn(o[nj][0]*inv0, o[nj][1]*inv0);
        *(__half2*)(op1 + nj*8 + qc) = __floats2half2_rn(o[nj][2]*inv1, o[nj][3]*inv1);
    }
}

// ================= launch =================
extern "C" void kernel_launch(void* const* d_in, const int* in_sizes, int n_in,
                              void* d_out, int out_size)
{
    const float* x      = (const float*)d_in[0];
    const float* tokens = (const float*)d_in[1];
    const float* qW     = (const float*)d_in[2];
    const float* qb     = (const float*)d_in[3];
    const float* Wq     = (const float*)d_in[4];
    const float* Wkv    = (const float*)d_in[5];
    const float* Wo     = (const float*)d_in[6];
    const float* bo     = (const float*)d_in[7];
    const float* bwW    = (const float*)d_in[8];
    const float* bwb    = (const float*)d_in[9];
    const float* modW   = (const float*)d_in[10];
    const float* modb   = (const float*)d_in[11];
    const float* hvW    = (const float*)d_in[12];
    const float* hvb    = (const float*)d_in[13];
    const float* outW   = (const float*)d_in[14];
    const float* outb   = (const float*)d_in[15];
    float* total = (float*)d_out;

    __half *gqh, *glh, *xqh, *qh, *kvh, *attnh, *s1h, *m0h, *g2h, *tokh, *hlh;
    __half *qWT, *WqT, *WkvT, *bwWT, *modWT, *hvWT, *WoA, *wfT;
    float *tv, *bfp;
    cudaGetSymbolAddress((void**)&gqh,   g_gq_h);
    cudaGetSymbolAddress((void**)&glh,   g_gl_h);
    cudaGetSymbolAddress((void**)&xqh,   g_xq_h);
    cudaGetSymbolAddress((void**)&qh,    g_q_h);
    cudaGetSymbolAddress((void**)&kvh,   g_kv_h);
    cudaGetSymbolAddress((void**)&attnh, g_attn_h);
    cudaGetSymbolAddress((void**)&s1h,   g_s_h);
    cudaGetSymbolAddress((void**)&m0h,   g_m0_h);
    cudaGetSymbolAddress((void**)&g2h,   g_g2_h);
    cudaGetSymbolAddress((void**)&tokh,  g_tok_h);
    cudaGetSymbolAddress((void**)&hlh,   g_hl_h);
    cudaGetSymbolAddress((void**)&qWT,   g_qWT);
    cudaGetSymbolAddress((void**)&WqT,   g_WqT);
    cudaGetSymbolAddress((void**)&WkvT,  g_WkvT);
    cudaGetSymbolAddress((void**)&bwWT,  g_bwWT);
    cudaGetSymbolAddress((void**)&modWT, g_modWT);
    cudaGetSymbolAddress((void**)&hvWT,  g_hvWT);
    cudaGetSymbolAddress((void**)&WoA,   g_WoA);
    cudaGetSymbolAddress((void**)&wfT,   g_wfT);
    cudaGetSymbolAddress((void**)&tv,    g_tv);
    cudaGetSymbolAddress((void**)&bfp,   g_bf);

    cudaFuncSetAttribute(tgemm<true,false,false,false,2>,  cudaFuncAttributeMaxDynamicSharedMemorySize, TG_SMEM);
    cudaFuncSetAttribute(tgemm<false,false,false,false,8>, cudaFuncAttributeMaxDynamicSharedMemorySize, TG_SMEM);
    cudaFuncSetAttribute(tgemm<true,true,false,false,2>,   cudaFuncAttributeMaxDynamicSharedMemorySize, TG_SMEM);
    cudaFuncSetAttribute(tgemm<true,false,true,true,8>,    cudaFuncAttributeMaxDynamicSharedMemorySize, TG_SMEM);
    cudaFuncSetAttribute(tgemm<true,false,false,true,8>,   cudaFuncAttributeMaxDynamicSharedMemorySize, TG_SMEM);
    cudaFuncSetAttribute(pairgemm, cudaFuncAttributeMaxDynamicSharedMemorySize, PR_SMEM);
    cudaFuncSetAttribute(attn_mma_k, cudaFuncAttributeMaxDynamicSharedMemorySize, AT_SMEM);

    // 1) gamma  2) prep  3) bf
    gamma_k<<<HW, 128>>>(x, gqh, glh, tv);
    prep_k<<<(int)((PREP_TOTAL + 255)/256), 256>>>(
        qW, Wq, Wkv, bwW, modW, hvW, Wo, tokens, outb,
        qWT, WqT, WkvT, bwWT, modWT, hvWT, WoA, tokh, total);
    bf_k<<<dim3(8,3), 256>>>(bo, modW, modb, bfp);

    // 4) xq = relu(gq @ qW + qb) -> fp16
    tgemm<true,false,false,false,2><<<dim3(8,128), 256, TG_SMEM>>>(
        gqh, qWT, qb, nullptr, nullptr, xqh, nullptr, nullptr, nullptr, HW, HID,
        0, 0, 0, 0, 0);

    // 5) kv = tokens @ Wkv -> fp16
    tgemm<false,false,false,false,8><<<dim3(4,16), 256, TG_SMEM>>>(
        tokh, WkvT, nullptr, nullptr, nullptr, kvh, nullptr, nullptr, nullptr, NB*NTOK, 256,
        0, 0, 0, 0, 0);

    // 6) h_l (banded z=0..2) -> fp16
    tgemm<true,false,false,false,2><<<dim3(8,128,3), 256, TG_SMEM>>>(
        glh, bwWT, bwb, nullptr, nullptr, hlh, nullptr, nullptr, nullptr, HW, HID,
        (long long)HW*FD, (long long)HID*FD, HID, (long long)HW*HID, 0);

    // 7) q = xq @ Wq -> fp16
    tgemm<false,false,false,false,8><<<dim3(2,128), 256, TG_SMEM>>>(
        xqh, WqT, nullptr, nullptr, nullptr, qh, nullptr, nullptr, nullptr, HW, FD,
        0, 0, 0, 0, 0);

    // 8) wfT (banded z=0..2) = (Wo @ modW[z])^T -> fp16 [512][128]
    tgemm<false,false,false,false,8><<<dim3(8,1,3), 256, TG_SMEM>>>(
        WoA, modWT, nullptr, nullptr, nullptr,
        nullptr, wfT, nullptr, nullptr, FD, HID,
        0, (long long)HID*HID, 0, 0, (long long)HID*FD);

    // 9) attention (flash, P in registers)
    attn_mma_k<<<dim3(HW/128, 2, NB), 256, AT_SMEM>>>(qh, kvh, tv, attnh);

    // 10) G2 = relu(attn@wf2 + bf2 + hl2) -> g2h
    tgemm<true,true,false,false,2><<<dim3(8,1024), 256, TG_SMEM>>>(
        attnh, wfT + 2*HID*FD, bfp + 2*HID, hlh + 2ull*HW*HID, nullptr,
        g2h, nullptr, nullptr, nullptr, MROWS, HID,
        0, 0, 0, 0, 0);

    // 11) pair: m0h (+outproj outW0) and s1h
    pairgemm<<<dim3(8,1024), 256, PR_SMEM>>>(
        attnh, wfT, bfp, hlh, m0h, s1h, outW, total);

    // 12) HV1: relu(s1@hvW0 + hvb0); total += HV1@outW1; +g2 -> s2 (into m0h)
    tgemm<true,false,true,true,8><<<dim3(8,1024), 256, TG_SMEM>>>(
        s1h, hvWT, hvb, nullptr, g2h, m0h, nullptr,
        outW + 512*3, total, MROWS, HID,
        0, 0, 0, 0, 0);

    // 13) HV2: relu(s2@hvW1 + hvb1); total += HV2@outW2
    tgemm<true,false,false,true,8><<<dim3(8,1024), 256, TG_SMEM>>>(
        m0h, hvWT + (size_t)HID*HID, hvb + HID, nullptr, nullptr, nullptr,
        nullptr, outW + 2*512*3, total, MROWS, HID,
        0, 0, 0, 0, 0);
}

// round 15
// speedup vs baseline: 1.9421x; 1.0147x over previous
#include <cuda_runtime.h>
#include <cuda_fp16.h>
#include <math.h>
#include <stdint.h>

#define HW 16384
#define NB 8
#define MROWS (NB*HW)      // 131072
#define HID 512
#define FD 128
#define NTOK 256
#define PI_D 3.14159265358979323846
#define TWO_PI_D 6.28318530717958647692
#define INV_2PI_D 0.15915494309189533577

// ---------------- fp16 buffers ----------------
__device__ __half g_gq_h[HW*FD];
__device__ __half g_gl_h[3ull*HW*FD];
__device__ __half g_xq_h[HW*HID];
__device__ __half g_q_h[HW*FD];
__device__ __half g_kv_h[NB*NTOK*256];
__device__ __half g_attn_h[(unsigned long long)MROWS*FD];
__device__ __half g_s_h[(unsigned long long)MROWS*HID];   // S1
__device__ __half g_m0_h[(unsigned long long)MROWS*HID];  // M0, reused as S2
__device__ __half g_g2_h[(unsigned long long)MROWS*HID];  // reluG2
__device__ __half g_tok_h[NB*NTOK*HID];
__device__ __half g_hl_h[3ull*HW*HID];
__device__ __half g_qWT[HID*FD];
__device__ __half g_WqT[FD*HID];
__device__ __half g_WkvT[256*HID];
__device__ __half g_bwWT[3*HID*FD];
__device__ __half g_modWT[3*HID*HID];
__device__ __half g_hvWT[2*HID*HID];
__device__ __half g_WoA[FD*HID];
__device__ __half g_wfT[3*HID*FD];
// ---------------- fp32 buffers ----------------
__device__ float g_tv[HW];
__device__ float g_bf[3*HID];

// ================= helpers =================
__device__ __forceinline__ uint32_t smem_u32(const void* p) {
    uint32_t a;
    asm("{ .reg .u64 t; cvta.to.shared.u64 t, %1; cvt.u32.u64 %0, t; }" : "=r"(a) : "l"(p));
    return a;
}
__device__ __forceinline__ void ldm_x4(uint32_t* r, uint32_t addr) {
    asm volatile("ldmatrix.sync.aligned.m8n8.x4.shared.b16 {%0,%1,%2,%3}, [%4];"
                 : "=r"(r[0]), "=r"(r[1]), "=r"(r[2]), "=r"(r[3]) : "r"(addr));
}
__device__ __forceinline__ void mma16816(float* d, const uint32_t* a, uint32_t b0, uint32_t b1) {
    asm volatile(
        "mma.sync.aligned.m16n8k16.row.col.f32.f16.f16.f32 "
        "{%0,%1,%2,%3}, {%4,%5,%6,%7}, {%8,%9}, {%0,%1,%2,%3};"
        : "+f"(d[0]), "+f"(d[1]), "+f"(d[2]), "+f"(d[3])
        : "r"(a[0]), "r"(a[1]), "r"(a[2]), "r"(a[3]), "r"(b0), "r"(b1));
}
__device__ __forceinline__ void cp16(uint32_t dst, const void* src) {
    asm volatile("cp.async.cg.shared.global [%0], [%1], 16;" :: "r"(dst), "l"(src));
}
#define CP_COMMIT() asm volatile("cp.async.commit_group;" ::: "memory")
#define CP_WAIT1()  asm volatile("cp.async.wait_group 1;" ::: "memory")
#define CP_WAIT0()  asm volatile("cp.async.wait_group 0;" ::: "memory")

// ================= Fourier features (fp32 trig + DP range reduction) =================
__global__ void gamma_k(const float* __restrict__ x, __half* __restrict__ gq,
                        __half* __restrict__ gl, float* __restrict__ tv)
{
    __shared__ double omg[128];
    int q = blockIdx.x;
    int f = threadIdx.x;
    {
        const double sig[4] = {128.0, 16.0, 64.0, 256.0};
        int s = f >> 5, j = f & 31;
        double step = (log10(sig[s]) - 1.0) / 31.0;
        omg[f] = pow(10.0, 1.0 + (double)j * step);
    }
    __syncthreads();

    float c0 = x[2*q], c1 = x[2*q+1];
    if (f == 0) {
        int r  = (int)(c0 * 16.0f);
        int cc = (int)(c1 * 16.0f);
        tv[q] = (float)(r*16 + cc) * (1.0f/256.0f);
    }
    int d = f >> 6;
    int rr = f & 63;
    int part = rr >> 5;
    int j = rr & 31;
    double pc = PI_D * (d ? (double)c1 : (double)c0);
    #pragma unroll
    for (int s = 0; s < 4; s++) {
        double arg = pc * omg[s*32 + j];
        double qf  = floor(arg * INV_2PI_D);
        float r    = (float)(arg - qf * TWO_PI_D);
        float val  = part ? cosf(r) : sinf(r);
        __half* dst = (s == 0) ? gq : (gl + (size_t)(s-1)*HW*FD);
        dst[(size_t)q*FD + f] = __float2half_rn(val);
    }
}

// ================= merged weight prep =================
__global__ void prep_k(const float* __restrict__ qW, const float* __restrict__ Wq,
                       const float* __restrict__ Wkv, const float* __restrict__ bwW,
                       const float* __restrict__ modW, const float* __restrict__ hvW,
                       const float* __restrict__ Wo, const float* __restrict__ tokens,
                       const float* __restrict__ outb,
                       __half* __restrict__ qWT, __half* __restrict__ WqT,
                       __half* __restrict__ WkvT, __half* __restrict__ bwWT,
                       __half* __restrict__ modWT, __half* __restrict__ hvWT,
                       __half* __restrict__ WoA, __half* __restrict__ tokh,
                       float* __restrict__ total)
{
    long long i = (long long)blockIdx.x * 256 + threadIdx.x;
    if (i < 65536) {
        int k = (int)(i/512), n = (int)(i%512);
        qWT[n*128+k] = __float2half_rn(qW[i]); return;
    } i -= 65536;
    if (i < 65536) {
        int k = (int)(i/128), n = (int)(i%128);
        WqT[n*512+k] = __float2half_rn(Wq[i]); return;
    } i -= 65536;
    if (i < 131072) {
        int k = (int)(i/256), n = (int)(i%256);
        WkvT[n*512+k] = __float2half_rn(Wkv[i]); return;
    } i -= 131072;
    if (i < 196608) {
        int s = (int)(i/65536); long long j = i%65536;
        int k = (int)(j/512), n = (int)(j%512);
        bwWT[s*65536 + n*128+k] = __float2half_rn(bwW[i]); return;
    } i -= 196608;
    if (i < 786432) {
        int s = (int)(i/262144); long long j = i%262144;
        int k = (int)(j/512), n = (int)(j%512);
        modWT[s*262144 + n*512+k] = __float2half_rn(modW[i]); return;
    } i -= 786432;
    if (i < 524288) {
        int s = (int)(i/262144); long long j = i%262144;
        int k = (int)(j/512), n = (int)(j%512);
        hvWT[s*262144 + n*512+k] = __float2half_rn(hvW[i]); return;
    } i -= 524288;
    if (i < 65536) { WoA[i] = __float2half_rn(Wo[i]); return; } i -= 65536;
    if (i < 1048576) { tokh[i] = __float2half_rn(tokens[i]); return; } i -= 1048576;
    if (i < (long long)MROWS*3) {
        int c = (int)(i % 3);
        total[i] = outb[c] + outb[3+c] + outb[6+c];
    }
}
#define PREP_TOTAL 3276800LL

// ================= HMMA fp16 GEMM (round-10 core; z-strided for banded launches) =================
#define LDK 72
#define A_PANEL (128*LDK)
#define B_PANEL (64*LDK)
#define STG (A_PANEL + B_PANEL)
#define TG_SMEM (2*STG*2)          // 55296 B
template<bool RELU, bool BCAST, bool ADDF, bool OUTP, int KT>
__global__ __launch_bounds__(256, 3)
void tgemm(const __half* __restrict__ A, const __half* __restrict__ WT,
           const float* __restrict__ bias, const __half* __restrict__ bch,
           const __half* __restrict__ af,
           __half* __restrict__ Ch, __half* __restrict__ CTh,
           const float* __restrict__ outWsel, float* __restrict__ total,
           int M, int N,
           long long zA, long long zW, long long zB, long long zC, long long zCT)
{
    const int K = KT*64;
    long long z = blockIdx.z;
    A   += z * zA;
    WT  += z * zW;
    if (bias) bias += z * zB;
    if (Ch)   Ch   += z * zC;
    if (CTh)  CTh  += z * zCT;

    extern __shared__ __half sh_[];
    int tid = threadIdx.x, wid = tid >> 5, lane = tid & 31;
    long long m0 = (long long)blockIdx.y * 128;
    long long n0 = (long long)blockIdx.x * 64;
    int wm = (wid & 3) * 32;
    int wn = (wid >> 2) * 32;

    float d[2][4][4];
    #pragma unroll
    for (int mi = 0; mi < 2; mi++)
        #pragma unroll
        for (int ni = 0; ni < 4; ni++)
            #pragma unroll
            for (int q = 0; q < 4; q++) d[mi][ni][q] = 0.f;

    uint32_t s_u = smem_u32(sh_);
    int lr[4], lc[4];
    #pragma unroll
    for (int it = 0; it < 4; it++) {
        int idx = tid + it*256;
        lr[it] = idx >> 3;
        lc[it] = idx & 7;
    }

    auto load_stage = [&](int t) {
        uint32_t base = s_u + (uint32_t)(t & 1) * (STG*2);
        int kt = t << 6;
        #pragma unroll
        for (int it = 0; it < 4; it++)
            cp16(base + (lr[it]*LDK + lc[it]*8)*2, A + (m0 + lr[it])*(long long)K + kt + lc[it]*8);
        #pragma unroll
        for (int it = 0; it < 2; it++)
            cp16(base + (A_PANEL + lr[it]*LDK + lc[it]*8)*2, WT + (n0 + lr[it])*(long long)K + kt + lc[it]*8);
        CP_COMMIT();
    };

    load_stage(0);

    uint32_t q_row = (uint32_t)(lane & 15), q_koff = (uint32_t)(lane >> 4) * 8;

    #pragma unroll
    for (int t = 0; t < KT; t++) {
        if (t + 1 < KT) { load_stage(t + 1); CP_WAIT1(); }
        else            { CP_WAIT0(); }
        __syncthreads();

        uint32_t sa_u = s_u + (uint32_t)(t & 1) * (STG*2);
        uint32_t sb_u = sa_u + A_PANEL*2;
        #pragma unroll
        for (int kk = 0; kk < 64; kk += 16) {
            uint32_t afr[2][4], bfr[2][4];
            #pragma unroll
            for (int mi = 0; mi < 2; mi++)
                ldm_x4(afr[mi], sa_u + (((uint32_t)wm + mi*16 + q_row)*LDK + kk + q_koff)*2);
            #pragma unroll
            for (int nj = 0; nj < 2; nj++)
                ldm_x4(bfr[nj], sb_u + (((uint32_t)wn + nj*16 + q_row)*LDK + kk + q_koff)*2);
            #pragma unroll
            for (int mi = 0; mi < 2; mi++)
                #pragma unroll
                for (int ni = 0; ni < 4; ni++)
                    mma16816(d[mi][ni], afr[mi], bfr[ni>>1][ni&1], bfr[ni>>1][(ni&1)+2]);
        }
        __syncthreads();
    }

    __half* stg = sh_;
    float* red = (float*)((char*)sh_ + 20480);
    if (OUTP) {
        for (int i = tid; i < 128*3; i += 256) red[i] = 0.f;
        __syncthreads();
    }

    int qr = lane >> 2;
    int qc = (lane & 3) * 2;
    #pragma unroll
    for (int mi = 0; mi < 2; mi++) {
        #pragma unroll
        for (int rh = 0; rh < 2; rh++) {
            int rloc = wm + mi*16 + rh*8 + qr;
            long long r  = m0 + rloc;
            long long rb_ = BCAST ? (r & (HW - 1)) : r;
            float p0 = 0.f, p1 = 0.f, p2 = 0.f;
            #pragma unroll
            for (int ni = 0; ni < 4; ni++) {
                int cloc = wn + ni*8 + qc;
                long long c = n0 + cloc;
                float v0 = d[mi][ni][rh*2+0];
                float v1 = d[mi][ni][rh*2+1];
                if (bias) {
                    float2 b2 = *(const float2*)(bias + c);
                    v0 += b2.x; v1 += b2.y;
                }
                if (BCAST) {
                    float2 b2 = __half22float2(*(const __half2*)(bch + rb_*(long long)N + c));
                    v0 += b2.x; v1 += b2.y;
                }
                if (RELU) { v0 = fmaxf(v0, 0.f); v1 = fmaxf(v1, 0.f); }
                if (OUTP) {
                    const float* w0 = outWsel + c*3;
                    p0 += v0*w0[0] + v1*w0[3];
                    p1 += v0*w0[1] + v1*w0[4];
                    p2 += v0*w0[2] + v1*w0[5];
                }
                if (ADDF) {
                    float2 af2 = __half22float2(*(const __half2*)(af + r*(long long)N + c));
                    v0 += af2.x; v1 += af2.y;
                }
                if (Ch) *(__half2*)(stg + rloc*LDK + cloc) = __floats2half2_rn(v0, v1);
                if (CTh) {
                    CTh[c*(long long)M + r]     = __float2half_rn(v0);
                    CTh[(c+1)*(long long)M + r] = __float2half_rn(v1);
                }
            }
            if (OUTP) {
                #pragma unroll
                for (int o = 1; o < 4; o <<= 1) {
                    p0 += __shfl_xor_sync(0xffffffffu, p0, o);
                    p1 += __shfl_xor_sync(0xffffffffu, p1, o);
                    p2 += __shfl_xor_sync(0xffffffffu, p2, o);
                }
                if ((lane & 3) == 0) {
                    atomicAdd(&red[rloc*3+0], p0);
                    atomicAdd(&red[rloc*3+1], p1);
                    atomicAdd(&red[rloc*3+2], p2);
                }
            }
        }
    }
    __syncthreads();
    if (Ch) {
        #pragma unroll
        for (int it = 0; it < 4; it++) {
            int c = tid + it*256;
            int row = c >> 3, off = (c & 7) * 8;
            *(uint4*)(Ch + (m0 + row)*(long long)N + n0 + off) = *(const uint4*)(stg + row*LDK + off);
        }
    }
    if (OUTP) {
        for (int i = tid; i < 128*3; i += 256)
            atomicAdd(&total[(m0 + (i/3))*3 + (i%3)], red[i]);
    }
}

// ================= pair-band GEMM: G0 + G1 share A (K=128) =================
#define PR_STG (A_PANEL + 2*B_PANEL)
#define PR_SMEM (2*PR_STG*2)                 // 73728 B
__global__ __launch_bounds__(256, 2)
void pairgemm(const __half* __restrict__ A, const __half* __restrict__ wfT,
              const float* __restrict__ bf, const __half* __restrict__ hl,
              __half* __restrict__ m0h, __half* __restrict__ s1h,
              const float* __restrict__ outW, float* __restrict__ total)
{
    extern __shared__ __half sh_[];
    int tid = threadIdx.x, wid = tid >> 5, lane = tid & 31;
    long long m0 = (long long)blockIdx.y * 128;
    long long n0 = (long long)blockIdx.x * 64;
    int wm = (wid & 3) * 32;
    int wn = (wid >> 2) * 32;
    uint32_t s_u = smem_u32(sh_);

    float d0[2][4][4], d1[2][4][4];
    #pragma unroll
    for (int mi = 0; mi < 2; mi++)
        #pragma unroll
        for (int ni = 0; ni < 4; ni++)
            #pragma unroll
            for (int q = 0; q < 4; q++) { d0[mi][ni][q] = 0.f; d1[mi][ni][q] = 0.f; }

    int lr[4], lc[4];
    #pragma unroll
    for (int it = 0; it < 4; it++) {
        int idx = tid + it*256;
        lr[it] = idx >> 3;
        lc[it] = idx & 7;
    }

    auto load_stage = [&](int t) {
        uint32_t base = s_u + (uint32_t)(t & 1) * (PR_STG*2);
        int kt = t << 6;
        #pragma unroll
        for (int it = 0; it < 4; it++)
            cp16(base + (lr[it]*LDK + lc[it]*8)*2, A + (m0 + lr[it])*FD + kt + lc[it]*8);
        #pragma unroll
        for (int it = 0; it < 2; it++) {
            cp16(base + (A_PANEL + lr[it]*LDK + lc[it]*8)*2, wfT + (n0 + lr[it])*FD + kt + lc[it]*8);
            cp16(base + (A_PANEL + B_PANEL + lr[it]*LDK + lc[it]*8)*2,
                 wfT + HID*FD + (n0 + lr[it])*FD + kt + lc[it]*8);
        }
        CP_COMMIT();
    };
    load_stage(0);

    uint32_t q_row = (uint32_t)(lane & 15), q_koff = (uint32_t)(lane >> 4) * 8;

    #pragma unroll
    for (int t = 0; t < 2; t++) {
        if (t == 0) { load_stage(1); CP_WAIT1(); } else { CP_WAIT0(); }
        __syncthreads();
        uint32_t sa_u = s_u + (uint32_t)(t & 1) * (PR_STG*2);
        uint32_t sb0  = sa_u + A_PANEL*2;
        uint32_t sb1  = sb0 + B_PANEL*2;
        #pragma unroll
        for (int kk = 0; kk < 64; kk += 16) {
            uint32_t afr[2][4], b0f[2][4], b1f[2][4];
            #pragma unroll
            for (int mi = 0; mi < 2; mi++)
                ldm_x4(afr[mi], sa_u + (((uint32_t)wm + mi*16 + q_row)*LDK + kk + q_koff)*2);
            #pragma unroll
            for (int nj = 0; nj < 2; nj++) {
                ldm_x4(b0f[nj], sb0 + (((uint32_t)wn + nj*16 + q_row)*LDK + kk + q_koff)*2);
                ldm_x4(b1f[nj], sb1 + (((uint32_t)wn + nj*16 + q_row)*LDK + kk + q_koff)*2);
            }
            #pragma unroll
            for (int mi = 0; mi < 2; mi++)
                #pragma unroll
                for (int ni = 0; ni < 4; ni++) {
                    mma16816(d0[mi][ni], afr[mi], b0f[ni>>1][ni&1], b0f[ni>>1][(ni&1)+2]);
                    mma16816(d1[mi][ni], afr[mi], b1f[ni>>1][ni&1], b1f[ni>>1][(ni&1)+2]);
                }
        }
        __syncthreads();
    }

    __half* stg0 = sh_;
    __half* stg1 = sh_ + 128*LDK;
    float* red = (float*)((char*)sh_ + 40960);
    for (int i = tid; i < 128*3; i += 256) red[i] = 0.f;
    __syncthreads();

    int qr = lane >> 2;
    int qc = (lane & 3) * 2;
    const float* bf0 = bf;
    const float* bf1 = bf + HID;
    const __half* hl0 = hl;
    const __half* hl1 = hl + (size_t)HW*HID;
    #pragma unroll
    for (int mi = 0; mi < 2; mi++) {
        #pragma unroll
        for (int rh = 0; rh < 2; rh++) {
            int rloc = wm + mi*16 + rh*8 + qr;
            long long r  = m0 + rloc;
            long long rb = r & (HW - 1);
            float p0 = 0.f, p1 = 0.f, p2 = 0.f;
            #pragma unroll
            for (int ni = 0; ni < 4; ni++) {
                int cloc = wn + ni*8 + qc;
                long long c = n0 + cloc;
                float u0 = d0[mi][ni][rh*2+0];
                float u1 = d0[mi][ni][rh*2+1];
                float2 b2 = *(const float2*)(bf0 + c);
                float2 h2 = __half22float2(*(const __half2*)(hl0 + rb*HID + c));
                u0 = fmaxf(u0 + b2.x + h2.x, 0.f);
                u1 = fmaxf(u1 + b2.y + h2.y, 0.f);
                const float* w0 = outW + c*3;
                p0 += u0*w0[0] + u1*w0[3];
                p1 += u0*w0[1] + u1*w0[4];
                p2 += u0*w0[2] + u1*w0[5];
                *(__half2*)(stg0 + rloc*LDK + cloc) = __floats2half2_rn(u0, u1);
                float v0 = d1[mi][ni][rh*2+0];
                float v1 = d1[mi][ni][rh*2+1];
                float2 b3 = *(const float2*)(bf1 + c);
                float2 h3 = __half22float2(*(const __half2*)(hl1 + rb*HID + c));
                v0 = fmaxf(v0 + b3.x + h3.x, 0.f) + u0;
                v1 = fmaxf(v1 + b3.y + h3.y, 0.f) + u1;
                *(__half2*)(stg1 + rloc*LDK + cloc) = __floats2half2_rn(v0, v1);
            }
            #pragma unroll
            for (int o = 1; o < 4; o <<= 1) {
                p0 += __shfl_xor_sync(0xffffffffu, p0, o);
                p1 += __shfl_xor_sync(0xffffffffu, p1, o);
                p2 += __shfl_xor_sync(0xffffffffu, p2, o);
            }
            if ((lane & 3) == 0) {
                atomicAdd(&red[rloc*3+0], p0);
                atomicAdd(&red[rloc*3+1], p1);
                atomicAdd(&red[rloc*3+2], p2);
            }
        }
    }
    __syncthreads();
    #pragma unroll
    for (int it = 0; it < 4; it++) {
        int c = tid + it*256;
        int row = c >> 3, off = (c & 7) * 8;
        *(uint4*)(m0h + (m0 + row)*HID + n0 + off) = *(const uint4*)(stg0 + row*LDK + off);
        *(uint4*)(s1h + (m0 + row)*HID + n0 + off) = *(const uint4*)(stg1 + row*LDK + off);
    }
    for (int i = tid; i < 128*3; i += 256)
        atomicAdd(&total[(m0 + (i/3))*3 + (i%3)], red[i]);
}

// ================= fused bias (parallelized) =================
__global__ void bf_k(const float* __restrict__ bo, const float* __restrict__ modW,
                     const float* __restrict__ modb, float* __restrict__ bf)
{
    __shared__ float red[256];
    int band = blockIdx.y;
    int n0 = blockIdx.x * 64;
    int nl = threadIdx.x & 63;
    int ks = threadIdx.x >> 6;
    const float* Wm = modW + (size_t)band*HID*HID;
    float s = 0.f;
    for (int k = ks*128; k < ks*128 + 128; k++)
        s += bo[k] * Wm[(size_t)k*HID + n0 + nl];
    red[threadIdx.x] = s;
    __syncthreads();
    if (threadIdx.x < 64) {
        float t = red[threadIdx.x] + red[threadIdx.x+64] + red[threadIdx.x+128] + red[threadIdx.x+192];
        bf[band*HID + n0 + threadIdx.x] = t + modb[band*HID + n0 + threadIdx.x];
    }
}

// ================= flash HMMA attention (P in registers, 2 token chunks) =================
#define AT_QSTR 72
#define AT_KSTR 72
#define AT_VSTR 264
#define AT_SMEM ((128*AT_QSTR + 256*AT_KSTR + 64*AT_VSTR)*2)   // 89088 B
__global__ __launch_bounds__(256, 2)
void attn_mma_k(const __half* __restrict__ qh, const __half* __restrict__ kvh,
                const float* __restrict__ tv, __half* __restrict__ out)
{
    extern __shared__ __half sm[];
    __half* sQ = sm;
    __half* sK = sQ + 128*AT_QSTR;
    __half* sV = sK + 256*AT_KSTR;
    int tid = threadIdx.x, wid = tid >> 5, lane = tid & 31;
    int h = blockIdx.y, b = blockIdx.z;
    long long q0 = (long long)blockIdx.x * 128;
    const __half* kvb = kvh + (size_t)b*NTOK*256;

    for (int idx = tid; idx < 1024; idx += 256) {
        int r = idx >> 3, c8 = idx & 7;
        *(uint4*)(sQ + r*AT_QSTR + c8*8) = *(const uint4*)(qh + (q0 + r)*FD + h*64 + c8*8);
    }
    for (int idx = tid; idx < 2048; idx += 256) {
        int t = idx >> 3, c8 = idx & 7;
        *(uint4*)(sK + t*AT_KSTR + c8*8) = *(const uint4*)(kvb + t*256 + h*64 + c8*8);
    }
    for (int idx = tid; idx < NTOK*64; idx += 256) {
        int t = idx >> 6, dd = idx & 63;
        sV[dd*AT_VSTR + t] = kvb[t*256 + 128 + h*64 + dd];
    }
    __syncthreads();

    uint32_t sQu = smem_u32(sQ), sKu = smem_u32(sK), sVu = smem_u32(sV);

    uint32_t a_row = (uint32_t)(wid*16 + (lane & 15)), a_koff = (uint32_t)(lane >> 4) * 8;
    uint32_t q_row = (uint32_t)(lane & 15), q_koff = (uint32_t)(lane >> 4) * 8;
    int rq = wid*16 + (lane >> 2);
    int qc = (lane & 3) * 2;
    float tq0 = tv[q0 + rq];
    float tq1 = tv[q0 + rq + 8];
    float mx0 = -1e30f, mx1 = -1e30f, den0 = 0.f, den1 = 0.f;

    float o[8][4];
    #pragma unroll
    for (int nj = 0; nj < 8; nj++)
        #pragma unroll
        for (int q = 0; q < 4; q++) o[nj][q] = 0.f;

    #pragma unroll
    for (int c = 0; c < 2; c++) {
        float s[16][4];
        #pragma unroll
        for (int ni = 0; ni < 16; ni++)
            #pragma unroll
            for (int q = 0; q < 4; q++) s[ni][q] = 0.f;

        #pragma unroll
        for (int kk = 0; kk < 64; kk += 16) {
            uint32_t afr[4];
            ldm_x4(afr, sQu + (a_row*AT_QSTR + kk + a_koff)*2);
            #pragma unroll
            for (int nj = 0; nj < 8; nj++) {
                uint32_t bfr[4];
                ldm_x4(bfr, sKu + (((uint32_t)(c*128 + nj*16) + q_row)*AT_KSTR + kk + q_koff)*2);
                mma16816(s[nj*2],   afr, bfr[0], bfr[2]);
                mma16816(s[nj*2+1], afr, bfr[1], bfr[3]);
            }
        }

        float cm0 = -1e30f, cm1 = -1e30f;
        #pragma unroll
        for (int ni = 0; ni < 16; ni++) {
            #pragma unroll
            for (int cc = 0; cc < 2; cc++) {
                float pos = ((float)(c*128 + ni*8 + qc + cc) + 0.5f) * (1.0f/256.0f);
                float dd0 = tq0 - pos, dd1 = tq1 - pos;
                s[ni][cc]   = s[ni][cc]*0.125f   - 10.0f*dd0*dd0;
                s[ni][cc+2] = s[ni][cc+2]*0.125f - 10.0f*dd1*dd1;
                cm0 = fmaxf(cm0, s[ni][cc]);
                cm1 = fmaxf(cm1, s[ni][cc+2]);
            }
        }
        #pragma unroll
        for (int oo = 1; oo < 4; oo <<= 1) {
            cm0 = fmaxf(cm0, __shfl_xor_sync(0xffffffffu, cm0, oo));
            cm1 = fmaxf(cm1, __shfl_xor_sync(0xffffffffu, cm1, oo));
        }
        float nm0 = fmaxf(mx0, cm0), nm1 = fmaxf(mx1, cm1);
        float f0 = __expf(mx0 - nm0), f1 = __expf(mx1 - nm1);
        mx0 = nm0; mx1 = nm1;

        float ds0 = 0.f, ds1 = 0.f;
        #pragma unroll
        for (int ni = 0; ni < 16; ni++) {
            s[ni][0] = __expf(s[ni][0] - nm0);
            s[ni][1] = __expf(s[ni][1] - nm0);
            s[ni][2] = __expf(s[ni][2] - nm1);
            s[ni][3] = __expf(s[ni][3] - nm1);
            ds0 += s[ni][0] + s[ni][1];
            ds1 += s[ni][2] + s[ni][3];
        }
        den0 = den0*f0 + ds0;
        den1 = den1*f1 + ds1;

        #pragma unroll
        for (int nj = 0; nj < 8; nj++) {
            o[nj][0] *= f0; o[nj][1] *= f0;
            o[nj][2] *= f1; o[nj][3] *= f1;
        }

        #pragma unroll
        for (int m = 0; m < 8; m++) {
            uint32_t pf[4];
            __half2 h0 = __floats2half2_rn(s[2*m][0],   s[2*m][1]);
            __half2 h1 = __floats2half2_rn(s[2*m][2],   s[2*m][3]);
            __half2 h2 = __floats2half2_rn(s[2*m+1][0], s[2*m+1][1]);
            __half2 h3 = __floats2half2_rn(s[2*m+1][2], s[2*m+1][3]);
            pf[0] = *(uint32_t*)&h0; pf[1] = *(uint32_t*)&h1;
            pf[2] = *(uint32_t*)&h2; pf[3] = *(uint32_t*)&h3;
            #pragma unroll
            for (int nj = 0; nj < 4; nj++) {
                uint32_t bfr[4];
                ldm_x4(bfr, sVu + (((uint32_t)(nj*16) + q_row)*AT_VSTR + (c*128 + m*16) + q_koff)*2);
                mma16816(o[nj*2],   pf, bfr[0], bfr[2]);
                mma16816(o[nj*2+1], pf, bfr[1], bfr[3]);
            }
        }
    }

    #pragma unroll
    for (int oo = 1; oo < 4; oo <<= 1) {
        den0 += __shfl_xor_sync(0xffffffffu, den0, oo);
        den1 += __shfl_xor_sync(0xffffffffu, den1, oo);
    }

    float inv0 = 1.0f / den0, inv1 = 1.0f / den1;
    long long qi0 = q0 + rq;
    __half* op0 = out + ((size_t)b*HW + qi0)*FD + h*64;
    __half* op1 = op0 + (size_t)8*FD;
    #pragma unroll
    for (int nj = 0; nj < 8; nj++) {
        *(__half2*)(op0 + nj*8 + qc) = __floats2half2_rn(o[nj][0]*inv0, o[nj][1]*inv0);
        *(__half2*)(op1 + nj*8 + qc) = __floats2half2_rn(o[nj][2]*inv1, o[nj][3]*inv1);
    }
}

// ================= launch (dual-stream fork/join) =================
extern "C" void kernel_launch(void* const* d_in, const int* in_sizes, int n_in,
                              void* d_out, int out_size)
{
    const float* x      = (const float*)d_in[0];
    const float* tokens = (const float*)d_in[1];
    const float* qW     = (const float*)d_in[2];
    const float* qb     = (const float*)d_in[3];
    const float* Wq     = (const float*)d_in[4];
    const float* Wkv    = (const float*)d_in[5];
    const float* Wo     = (const float*)d_in[6];
    const float* bo     = (const float*)d_in[7];
    const float* bwW    = (const float*)d_in[8];
    const float* bwb    = (const float*)d_in[9];
    const float* modW   = (const float*)d_in[10];
    const float* modb   = (const float*)d_in[11];
    const float* hvW    = (const float*)d_in[12];
    const float* hvb    = (const float*)d_in[13];
    const float* outW   = (const float*)d_in[14];
    const float* outb   = (const float*)d_in[15];
    float* total = (float*)d_out;

    __half *gqh, *glh, *xqh, *qh, *kvh, *attnh, *s1h, *m0h, *g2h, *tokh, *hlh;
    __half *qWT, *WqT, *WkvT, *bwWT, *modWT, *hvWT, *WoA, *wfT;
    float *tv, *bfp;
    cudaGetSymbolAddress((void**)&gqh,   g_gq_h);
    cudaGetSymbolAddress((void**)&glh,   g_gl_h);
    cudaGetSymbolAddress((void**)&xqh,   g_xq_h);
    cudaGetSymbolAddress((void**)&qh,    g_q_h);
    cudaGetSymbolAddress((void**)&kvh,   g_kv_h);
    cudaGetSymbolAddress((void**)&attnh, g_attn_h);
    cudaGetSymbolAddress((void**)&s1h,   g_s_h);
    cudaGetSymbolAddress((void**)&m0h,   g_m0_h);
    cudaGetSymbolAddress((void**)&g2h,   g_g2_h);
    cudaGetSymbolAddress((void**)&tokh,  g_tok_h);
    cudaGetSymbolAddress((void**)&hlh,   g_hl_h);
    cudaGetSymbolAddress((void**)&qWT,   g_qWT);
    cudaGetSymbolAddress((void**)&WqT,   g_WqT);
    cudaGetSymbolAddress((void**)&WkvT,  g_WkvT);
    cudaGetSymbolAddress((void**)&bwWT,  g_bwWT);
    cudaGetSymbolAddress((void**)&modWT, g_modWT);
    cudaGetSymbolAddress((void**)&hvWT,  g_hvWT);
    cudaGetSymbolAddress((void**)&WoA,   g_WoA);
    cudaGetSymbolAddress((void**)&wfT,   g_wfT);
    cudaGetSymbolAddress((void**)&tv,    g_tv);
    cudaGetSymbolAddress((void**)&bfp,   g_bf);

    cudaFuncSetAttribute(tgemm<true,false,false,false,2>,  cudaFuncAttributeMaxDynamicSharedMemorySize, TG_SMEM);
    cudaFuncSetAttribute(tgemm<false,false,false,false,8>, cudaFuncAttributeMaxDynamicSharedMemorySize, TG_SMEM);
    cudaFuncSetAttribute(tgemm<true,true,false,false,2>,   cudaFuncAttributeMaxDynamicSharedMemorySize, TG_SMEM);
    cudaFuncSetAttribute(tgemm<true,false,true,true,8>,    cudaFuncAttributeMaxDynamicSharedMemorySize, TG_SMEM);
    cudaFuncSetAttribute(tgemm<true,false,false,true,8>,   cudaFuncAttributeMaxDynamicSharedMemorySize, TG_SMEM);
    cudaFuncSetAttribute(pairgemm, cudaFuncAttributeMaxDynamicSharedMemorySize, PR_SMEM);
    cudaFuncSetAttribute(attn_mma_k, cudaFuncAttributeMaxDynamicSharedMemorySize, AT_SMEM);

    // ---- dual-stream fork/join (graph-capturable; no device allocations) ----
    cudaStream_t sB;
    cudaStreamCreateWithFlags(&sB, cudaStreamNonBlocking);
    cudaEvent_t evA, evB, evC, evD;
    cudaEventCreateWithFlags(&evA, cudaEventDisableTiming);
    cudaEventCreateWithFlags(&evB, cudaEventDisableTiming);
    cudaEventCreateWithFlags(&evC, cudaEventDisableTiming);
    cudaEventCreateWithFlags(&evD, cudaEventDisableTiming);

    // fork: bring sB into the capture
    cudaEventRecord(evA, 0);
    cudaStreamWaitEvent(sB, evA, 0);

    // D: gamma (Fourier features)
    gamma_k<<<HW, 128, 0, 0>>>(x, gqh, glh, tv);

    // B: prep, bf, kv (independent of gamma)
    prep_k<<<(int)((PREP_TOTAL + 255)/256), 256, 0, sB>>>(
        qW, Wq, Wkv, bwW, modW, hvW, Wo, tokens, outb,
        qWT, WqT, WkvT, bwWT, modWT, hvWT, WoA, tokh, total);
    bf_k<<<dim3(8,3), 256, 0, sB>>>(bo, modW, modb, bfp);
    tgemm<false,false,false,false,8><<<dim3(4,16), 256, TG_SMEM, sB>>>(
        tokh, WkvT, nullptr, nullptr, nullptr, kvh, nullptr, nullptr, nullptr, NB*NTOK, 256,
        0, 0, 0, 0, 0);

    // cross-sync: D gets prep+kv results; B gets gamma results
    cudaEventRecord(evB, sB);
    cudaEventRecord(evC, 0);
    cudaStreamWaitEvent(0, evB, 0);
    cudaStreamWaitEvent(sB, evC, 0);

    // D: xq -> q -> attention
    tgemm<true,false,false,false,2><<<dim3(8,128), 256, TG_SMEM, 0>>>(
        gqh, qWT, qb, nullptr, nullptr, xqh, nullptr, nullptr, nullptr, HW, HID,
        0, 0, 0, 0, 0);
    tgemm<false,false,false,false,8><<<dim3(2,128), 256, TG_SMEM, 0>>>(
        xqh, WqT, nullptr, nullptr, nullptr, qh, nullptr, nullptr, nullptr, HW, FD,
        0, 0, 0, 0, 0);
    attn_mma_k<<<dim3(HW/128, 2, NB), 256, AT_SMEM, 0>>>(qh, kvh, tv, attnh);

    // B: h_l (banded), wfT (banded)
    tgemm<true,false,false,false,2><<<dim3(8,128,3), 256, TG_SMEM, sB>>>(
        glh, bwWT, bwb, nullptr, nullptr, hlh, nullptr, nullptr, nullptr, HW, HID,
        (long long)HW*FD, (long long)HID*FD, HID, (long long)HW*HID, 0);
    tgemm<false,false,false,false,8><<<dim3(8,1,3), 256, TG_SMEM, sB>>>(
        WoA, modWT, nullptr, nullptr, nullptr,
        nullptr, wfT, nullptr, nullptr, FD, HID,
        0, (long long)HID*HID, 0, 0, (long long)HID*FD);

    // join: D waits for B
    cudaEventRecord(evD, sB);
    cudaStreamWaitEvent(0, evD, 0);

    // D: G2, pair, HV1, HV2
    tgemm<true,true,false,false,2><<<dim3(8,1024), 256, TG_SMEM, 0>>>(
        attnh, wfT + 2*HID*FD, bfp + 2*HID, hlh + 2ull*HW*HID, nullptr,
        g2h, nullptr, nullptr, nullptr, MROWS, HID,
        0, 0, 0, 0, 0);
    pairgemm<<<dim3(8,1024), 256, PR_SMEM, 0>>>(
        attnh, wfT, bfp, hlh, m0h, s1h, outW, total);
    tgemm<true,false,true,true,8><<<dim3(8,1024), 256, TG_SMEM, 0>>>(
        s1h, hvWT, hvb, nullptr, g2h, m0h, nullptr,
        outW + 512*3, total, MROWS, HID,
        0, 0, 0, 0, 0);
    tgemm<true,false,false,true,8><<<dim3(8,1024), 256, TG_SMEM, 0>>>(
        m0h, hvWT + (size_t)HID*HID, hvb + HID, nullptr, nullptr, nullptr,
        nullptr, outW + 2*512*3, total, MROWS, HID,
        0, 0, 0, 0, 0);
}

// round 16
// speedup vs baseline: 1.9443x; 1.0011x over previous
#include <cuda_runtime.h>
#include <cuda_fp16.h>
#include <math.h>
#include <stdint.h>

#define HW 16384
#define NB 8
#define MROWS (NB*HW)      // 131072
#define HID 512
#define FD 128
#define NTOK 256
#define PI_D 3.14159265358979323846
#define TWO_PI_D 6.28318530717958647692
#define INV_2PI_D 0.15915494309189533577

// ---------------- fp16 buffers ----------------
__device__ __half g_gq_h[HW*FD];
__device__ __half g_gl_h[3ull*HW*FD];
__device__ __half g_xq_h[HW*HID];
__device__ __half g_q_h[HW*FD];
__device__ __half g_kv_h[NB*NTOK*256];
__device__ __half g_attn_h[(unsigned long long)MROWS*FD];
__device__ __half g_s_h[(unsigned long long)MROWS*HID];   // S1
__device__ __half g_m0_h[(unsigned long long)MROWS*HID];  // M0, reused as S2
__device__ __half g_g2_h[(unsigned long long)MROWS*HID];  // reluG2
__device__ __half g_tok_h[NB*NTOK*HID];
__device__ __half g_hl_h[3ull*HW*HID];
__device__ __half g_qWT[HID*FD];
__device__ __half g_WqT[FD*HID];
__device__ __half g_WkvT[256*HID];
__device__ __half g_bwWT[3*HID*FD];
__device__ __half g_modWT[3*HID*HID];
__device__ __half g_hvWT[2*HID*HID];
__device__ __half g_WoA[FD*HID];
__device__ __half g_wfT[3*HID*FD];
// ---------------- fp32 buffers ----------------
__device__ float g_tv[HW];
__device__ float g_bf[3*HID];

// ================= helpers =================
__device__ __forceinline__ uint32_t smem_u32(const void* p) {
    uint32_t a;
    asm("{ .reg .u64 t; cvta.to.shared.u64 t, %1; cvt.u32.u64 %0, t; }" : "=r"(a) : "l"(p));
    return a;
}
__device__ __forceinline__ void ldm_x4(uint32_t* r, uint32_t addr) {
    asm volatile("ldmatrix.sync.aligned.m8n8.x4.shared.b16 {%0,%1,%2,%3}, [%4];"
                 : "=r"(r[0]), "=r"(r[1]), "=r"(r[2]), "=r"(r[3]) : "r"(addr));
}
__device__ __forceinline__ void mma16816(float* d, const uint32_t* a, uint32_t b0, uint32_t b1) {
    asm volatile(
        "mma.sync.aligned.m16n8k16.row.col.f32.f16.f16.f32 "
        "{%0,%1,%2,%3}, {%4,%5,%6,%7}, {%8,%9}, {%0,%1,%2,%3};"
        : "+f"(d[0]), "+f"(d[1]), "+f"(d[2]), "+f"(d[3])
        : "r"(a[0]), "r"(a[1]), "r"(a[2]), "r"(a[3]), "r"(b0), "r"(b1));
}
__device__ __forceinline__ void cp16(uint32_t dst, const void* src) {
    asm volatile("cp.async.cg.shared.global [%0], [%1], 16;" :: "r"(dst), "l"(src));
}
#define CP_COMMIT() asm volatile("cp.async.commit_group;" ::: "memory")
#define CP_WAIT1()  asm volatile("cp.async.wait_group 1;" ::: "memory")
#define CP_WAIT0()  asm volatile("cp.async.wait_group 0;" ::: "memory")

// ================= Fourier features (fp32 trig + DP range reduction) =================
__global__ void gamma_k(const float* __restrict__ x, __half* __restrict__ gq,
                        __half* __restrict__ gl, float* __restrict__ tv)
{
    __shared__ double omg[128];
    int q = blockIdx.x;
    int f = threadIdx.x;
    {
        const double sig[4] = {128.0, 16.0, 64.0, 256.0};
        int s = f >> 5, j = f & 31;
        double step = (log10(sig[s]) - 1.0) / 31.0;
        omg[f] = pow(10.0, 1.0 + (double)j * step);
    }
    __syncthreads();

    float c0 = x[2*q], c1 = x[2*q+1];
    if (f == 0) {
        int r  = (int)(c0 * 16.0f);
        int cc = (int)(c1 * 16.0f);
        tv[q] = (float)(r*16 + cc) * (1.0f/256.0f);
    }
    int d = f >> 6;
    int rr = f & 63;
    int part = rr >> 5;
    int j = rr & 31;
    double pc = PI_D * (d ? (double)c1 : (double)c0);
    #pragma unroll
    for (int s = 0; s < 4; s++) {
        double arg = pc * omg[s*32 + j];
        double qf  = floor(arg * INV_2PI_D);
        float r    = (float)(arg - qf * TWO_PI_D);
        float val  = part ? cosf(r) : sinf(r);
        __half* dst = (s == 0) ? gq : (gl + (size_t)(s-1)*HW*FD);
        dst[(size_t)q*FD + f] = __float2half_rn(val);
    }
}

// ================= merged weight prep =================
__global__ void prep_k(const float* __restrict__ qW, const float* __restrict__ Wq,
                       const float* __restrict__ Wkv, const float* __restrict__ bwW,
                       const float* __restrict__ modW, const float* __restrict__ hvW,
                       const float* __restrict__ Wo, const float* __restrict__ tokens,
                       const float* __restrict__ outb,
                       __half* __restrict__ qWT, __half* __restrict__ WqT,
                       __half* __restrict__ WkvT, __half* __restrict__ bwWT,
                       __half* __restrict__ modWT, __half* __restrict__ hvWT,
                       __half* __restrict__ WoA, __half* __restrict__ tokh,
                       float* __restrict__ total)
{
    long long i = (long long)blockIdx.x * 256 + threadIdx.x;
    if (i < 65536) {
        int k = (int)(i/512), n = (int)(i%512);
        qWT[n*128+k] = __float2half_rn(qW[i]); return;
    } i -= 65536;
    if (i < 65536) {
        int k = (int)(i/128), n = (int)(i%128);
        WqT[n*512+k] = __float2half_rn(Wq[i]); return;
    } i -= 65536;
    if (i < 131072) {
        int k = (int)(i/256), n = (int)(i%256);
        WkvT[n*512+k] = __float2half_rn(Wkv[i]); return;
    } i -= 131072;
    if (i < 196608) {
        int s = (int)(i/65536); long long j = i%65536;
        int k = (int)(j/512), n = (int)(j%512);
        bwWT[s*65536 + n*128+k] = __float2half_rn(bwW[i]); return;
    } i -= 196608;
    if (i < 786432) {
        int s = (int)(i/262144); long long j = i%262144;
        int k = (int)(j/512), n = (int)(j%512);
        modWT[s*262144 + n*512+k] = __float2half_rn(modW[i]); return;
    } i -= 786432;
    if (i < 524288) {
        int s = (int)(i/262144); long long j = i%262144;
        int k = (int)(j/512), n = (int)(j%512);
        hvWT[s*262144 + n*512+k] = __float2half_rn(hvW[i]); return;
    } i -= 524288;
    if (i < 65536) { WoA[i] = __float2half_rn(Wo[i]); return; } i -= 65536;
    if (i < 1048576) { tokh[i] = __float2half_rn(tokens[i]); return; } i -= 1048576;
    if (i < (long long)MROWS*3) {
        int c = (int)(i % 3);
        total[i] = outb[c] + outb[3+c] + outb[6+c];
    }
}
#define PREP_TOTAL 3276800LL

// ================= HMMA fp16 GEMM (round-10 core; z-strided for banded launches) =================
#define LDK 72
#define A_PANEL (128*LDK)
#define B_PANEL (64*LDK)
#define STG (A_PANEL + B_PANEL)
#define TG_SMEM (2*STG*2)          // 55296 B
template<bool RELU, bool BCAST, bool ADDF, bool OUTP, int KT>
__global__ __launch_bounds__(256, 3)
void tgemm(const __half* __restrict__ A, const __half* __restrict__ WT,
           const float* __restrict__ bias, const __half* __restrict__ bch,
           const __half* __restrict__ af,
           __half* __restrict__ Ch, __half* __restrict__ CTh,
           const float* __restrict__ outWsel, float* __restrict__ total,
           int M, int N,
           long long zA, long long zW, long long zB, long long zC, long long zCT)
{
    const int K = KT*64;
    long long z = blockIdx.z;
    A   += z * zA;
    WT  += z * zW;
    if (bias) bias += z * zB;
    if (Ch)   Ch   += z * zC;
    if (CTh)  CTh  += z * zCT;

    extern __shared__ __half sh_[];
    int tid = threadIdx.x, wid = tid >> 5, lane = tid & 31;
    long long m0 = (long long)blockIdx.y * 128;
    long long n0 = (long long)blockIdx.x * 64;
    int wm = (wid & 3) * 32;
    int wn = (wid >> 2) * 32;

    float d[2][4][4];
    #pragma unroll
    for (int mi = 0; mi < 2; mi++)
        #pragma unroll
        for (int ni = 0; ni < 4; ni++)
            #pragma unroll
            for (int q = 0; q < 4; q++) d[mi][ni][q] = 0.f;

    uint32_t s_u = smem_u32(sh_);
    int lr[4], lc[4];
    #pragma unroll
    for (int it = 0; it < 4; it++) {
        int idx = tid + it*256;
        lr[it] = idx >> 3;
        lc[it] = idx & 7;
    }

    auto load_stage = [&](int t) {
        uint32_t base = s_u + (uint32_t)(t & 1) * (STG*2);
        int kt = t << 6;
        #pragma unroll
        for (int it = 0; it < 4; it++)
            cp16(base + (lr[it]*LDK + lc[it]*8)*2, A + (m0 + lr[it])*(long long)K + kt + lc[it]*8);
        #pragma unroll
        for (int it = 0; it < 2; it++)
            cp16(base + (A_PANEL + lr[it]*LDK + lc[it]*8)*2, WT + (n0 + lr[it])*(long long)K + kt + lc[it]*8);
        CP_COMMIT();
    };

    load_stage(0);

    uint32_t q_row = (uint32_t)(lane & 15), q_koff = (uint32_t)(lane >> 4) * 8;

    #pragma unroll
    for (int t = 0; t < KT; t++) {
        if (t + 1 < KT) { load_stage(t + 1); CP_WAIT1(); }
        else            { CP_WAIT0(); }
        __syncthreads();

        uint32_t sa_u = s_u + (uint32_t)(t & 1) * (STG*2);
        uint32_t sb_u = sa_u + A_PANEL*2;
        #pragma unroll
        for (int kk = 0; kk < 64; kk += 16) {
            uint32_t afr[2][4], bfr[2][4];
            #pragma unroll
            for (int mi = 0; mi < 2; mi++)
                ldm_x4(afr[mi], sa_u + (((uint32_t)wm + mi*16 + q_row)*LDK + kk + q_koff)*2);
            #pragma unroll
            for (int nj = 0; nj < 2; nj++)
                ldm_x4(bfr[nj], sb_u + (((uint32_t)wn + nj*16 + q_row)*LDK + kk + q_koff)*2);
            #pragma unroll
            for (int mi = 0; mi < 2; mi++)
                #pragma unroll
                for (int ni = 0; ni < 4; ni++)
                    mma16816(d[mi][ni], afr[mi], bfr[ni>>1][ni&1], bfr[ni>>1][(ni&1)+2]);
        }
        __syncthreads();
    }

    __half* stg = sh_;
    float* red = (float*)((char*)sh_ + 20480);
    if (OUTP) {
        for (int i = tid; i < 128*3; i += 256) red[i] = 0.f;
        __syncthreads();
    }

    int qr = lane >> 2;
    int qc = (lane & 3) * 2;
    #pragma unroll
    for (int mi = 0; mi < 2; mi++) {
        #pragma unroll
        for (int rh = 0; rh < 2; rh++) {
            int rloc = wm + mi*16 + rh*8 + qr;
            long long r  = m0 + rloc;
            long long rb_ = BCAST ? (r & (HW - 1)) : r;
            float p0 = 0.f, p1 = 0.f, p2 = 0.f;
            #pragma unroll
            for (int ni = 0; ni < 4; ni++) {
                int cloc = wn + ni*8 + qc;
                long long c = n0 + cloc;
                float v0 = d[mi][ni][rh*2+0];
                float v1 = d[mi][ni][rh*2+1];
                if (bias) {
                    float2 b2 = *(const float2*)(bias + c);
                    v0 += b2.x; v1 += b2.y;
                }
                if (BCAST) {
                    float2 b2 = __half22float2(*(const __half2*)(bch + rb_*(long long)N + c));
                    v0 += b2.x; v1 += b2.y;
                }
                if (RELU) { v0 = fmaxf(v0, 0.f); v1 = fmaxf(v1, 0.f); }
                if (OUTP) {
                    const float* w0 = outWsel + c*3;
                    p0 += v0*w0[0] + v1*w0[3];
                    p1 += v0*w0[1] + v1*w0[4];
                    p2 += v0*w0[2] + v1*w0[5];
                }
                if (ADDF) {
                    float2 af2 = __half22float2(*(const __half2*)(af + r*(long long)N + c));
                    v0 += af2.x; v1 += af2.y;
                }
                if (Ch) *(__half2*)(stg + rloc*LDK + cloc) = __floats2half2_rn(v0, v1);
                if (CTh) {
                    CTh[c*(long long)M + r]     = __float2half_rn(v0);
                    CTh[(c+1)*(long long)M + r] = __float2half_rn(v1);
                }
            }
            if (OUTP) {
                #pragma unroll
                for (int o = 1; o < 4; o <<= 1) {
                    p0 += __shfl_xor_sync(0xffffffffu, p0, o);
                    p1 += __shfl_xor_sync(0xffffffffu, p1, o);
                    p2 += __shfl_xor_sync(0xffffffffu, p2, o);
                }
                if ((lane & 3) == 0) {
                    atomicAdd(&red[rloc*3+0], p0);
                    atomicAdd(&red[rloc*3+1], p1);
                    atomicAdd(&red[rloc*3+2], p2);
                }
            }
        }
    }
    __syncthreads();
    if (Ch) {
        #pragma unroll
        for (int it = 0; it < 4; it++) {
            int c = tid + it*256;
            int row = c >> 3, off = (c & 7) * 8;
            *(uint4*)(Ch + (m0 + row)*(long long)N + n0 + off) = *(const uint4*)(stg + row*LDK + off);
        }
    }
    if (OUTP) {
        for (int i = tid; i < 128*3; i += 256)
            atomicAdd(&total[(m0 + (i/3))*3 + (i%3)], red[i]);
    }
}

// ================= pair-band GEMM: G0 + G1 share A (K=128) =================
#define PR_STG (A_PANEL + 2*B_PANEL)
#define PR_SMEM (2*PR_STG*2)                 // 73728 B
__global__ __launch_bounds__(256, 2)
void pairgemm(const __half* __restrict__ A, const __half* __restrict__ wfT,
              const float* __restrict__ bf, const __half* __restrict__ hl,
              __half* __restrict__ m0h, __half* __restrict__ s1h,
              const float* __restrict__ outW, float* __restrict__ total)
{
    extern __shared__ __half sh_[];
    int tid = threadIdx.x, wid = tid >> 5, lane = tid & 31;
    long long m0 = (long long)blockIdx.y * 128;
    long long n0 = (long long)blockIdx.x * 64;
    int wm = (wid & 3) * 32;
    int wn = (wid >> 2) * 32;
    uint32_t s_u = smem_u32(sh_);

    float d0[2][4][4], d1[2][4][4];
    #pragma unroll
    for (int mi = 0; mi < 2; mi++)
        #pragma unroll
        for (int ni = 0; ni < 4; ni++)
            #pragma unroll
            for (int q = 0; q < 4; q++) { d0[mi][ni][q] = 0.f; d1[mi][ni][q] = 0.f; }

    int lr[4], lc[4];
    #pragma unroll
    for (int it = 0; it < 4; it++) {
        int idx = tid + it*256;
        lr[it] = idx >> 3;
        lc[it] = idx & 7;
    }

    auto load_stage = [&](int t) {
        uint32_t base = s_u + (uint32_t)(t & 1) * (PR_STG*2);
        int kt = t << 6;
        #pragma unroll
        for (int it = 0; it < 4; it++)
            cp16(base + (lr[it]*LDK + lc[it]*8)*2, A + (m0 + lr[it])*FD + kt + lc[it]*8);
        #pragma unroll
        for (int it = 0; it < 2; it++) {
            cp16(base + (A_PANEL + lr[it]*LDK + lc[it]*8)*2, wfT + (n0 + lr[it])*FD + kt + lc[it]*8);
            cp16(base + (A_PANEL + B_PANEL + lr[it]*LDK + lc[it]*8)*2,
                 wfT + HID*FD + (n0 + lr[it])*FD + kt + lc[it]*8);
        }
        CP_COMMIT();
    };
    load_stage(0);

    uint32_t q_row = (uint32_t)(lane & 15), q_koff = (uint32_t)(lane >> 4) * 8;

    #pragma unroll
    for (int t = 0; t < 2; t++) {
        if (t == 0) { load_stage(1); CP_WAIT1(); } else { CP_WAIT0(); }
        __syncthreads();
        uint32_t sa_u = s_u + (uint32_t)(t & 1) * (PR_STG*2);
        uint32_t sb0  = sa_u + A_PANEL*2;
        uint32_t sb1  = sb0 + B_PANEL*2;
        #pragma unroll
        for (int kk = 0; kk < 64; kk += 16) {
            uint32_t afr[2][4], b0f[2][4], b1f[2][4];
            #pragma unroll
            for (int mi = 0; mi < 2; mi++)
                ldm_x4(afr[mi], sa_u + (((uint32_t)wm + mi*16 + q_row)*LDK + kk + q_koff)*2);
            #pragma unroll
            for (int nj = 0; nj < 2; nj++) {
                ldm_x4(b0f[nj], sb0 + (((uint32_t)wn + nj*16 + q_row)*LDK + kk + q_koff)*2);
                ldm_x4(b1f[nj], sb1 + (((uint32_t)wn + nj*16 + q_row)*LDK + kk + q_koff)*2);
            }
            #pragma unroll
            for (int mi = 0; mi < 2; mi++)
                #pragma unroll
                for (int ni = 0; ni < 4; ni++) {
                    mma16816(d0[mi][ni], afr[mi], b0f[ni>>1][ni&1], b0f[ni>>1][(ni&1)+2]);
                    mma16816(d1[mi][ni], afr[mi], b1f[ni>>1][ni&1], b1f[ni>>1][(ni&1)+2]);
                }
        }
        __syncthreads();
    }

    __half* stg0 = sh_;
    __half* stg1 = sh_ + 128*LDK;
    float* red = (float*)((char*)sh_ + 40960);
    for (int i = tid; i < 128*3; i += 256) red[i] = 0.f;
    __syncthreads();

    int qr = lane >> 2;
    int qc = (lane & 3) * 2;
    const float* bf0 = bf;
    const float* bf1 = bf + HID;
    const __half* hl0 = hl;
    const __half* hl1 = hl + (size_t)HW*HID;
    #pragma unroll
    for (int mi = 0; mi < 2; mi++) {
        #pragma unroll
        for (int rh = 0; rh < 2; rh++) {
            int rloc = wm + mi*16 + rh*8 + qr;
            long long r  = m0 + rloc;
            long long rb = r & (HW - 1);
            float p0 = 0.f, p1 = 0.f, p2 = 0.f;
            #pragma unroll
            for (int ni = 0; ni < 4; ni++) {
                int cloc = wn + ni*8 + qc;
                long long c = n0 + cloc;
                float u0 = d0[mi][ni][rh*2+0];
                float u1 = d0[mi][ni][rh*2+1];
                float2 b2 = *(const float2*)(bf0 + c);
                float2 h2 = __half22float2(*(const __half2*)(hl0 + rb*HID + c));
                u0 = fmaxf(u0 + b2.x + h2.x, 0.f);
                u1 = fmaxf(u1 + b2.y + h2.y, 0.f);
                const float* w0 = outW + c*3;
                p0 += u0*w0[0] + u1*w0[3];
                p1 += u0*w0[1] + u1*w0[4];
                p2 += u0*w0[2] + u1*w0[5];
                *(__half2*)(stg0 + rloc*LDK + cloc) = __floats2half2_rn(u0, u1);
                float v0 = d1[mi][ni][rh*2+0];
                float v1 = d1[mi][ni][rh*2+1];
                float2 b3 = *(const float2*)(bf1 + c);
                float2 h3 = __half22float2(*(const __half2*)(hl1 + rb*HID + c));
                v0 = fmaxf(v0 + b3.x + h3.x, 0.f) + u0;
                v1 = fmaxf(v1 + b3.y + h3.y, 0.f) + u1;
                *(__half2*)(stg1 + rloc*LDK + cloc) = __floats2half2_rn(v0, v1);
            }
            #pragma unroll
            for (int o = 1; o < 4; o <<= 1) {
                p0 += __shfl_xor_sync(0xffffffffu, p0, o);
                p1 += __shfl_xor_sync(0xffffffffu, p1, o);
                p2 += __shfl_xor_sync(0xffffffffu, p2, o);
            }
            if ((lane & 3) == 0) {
                atomicAdd(&red[rloc*3+0], p0);
                atomicAdd(&red[rloc*3+1], p1);
                atomicAdd(&red[rloc*3+2], p2);
            }
        }
    }
    __syncthreads();
    #pragma unroll
    for (int it = 0; it < 4; it++) {
        int c = tid + it*256;
        int row = c >> 3, off = (c & 7) * 8;
        *(uint4*)(m0h + (m0 + row)*HID + n0 + off) = *(const uint4*)(stg0 + row*LDK + off);
        *(uint4*)(s1h + (m0 + row)*HID + n0 + off) = *(const uint4*)(stg1 + row*LDK + off);
    }
    for (int i = tid; i < 128*3; i += 256)
        atomicAdd(&total[(m0 + (i/3))*3 + (i%3)], red[i]);
}

// ================= fused bias (parallelized) =================
__global__ void bf_k(const float* __restrict__ bo, const float* __restrict__ modW,
                     const float* __restrict__ modb, float* __restrict__ bf)
{
    __shared__ float red[256];
    int band = blockIdx.y;
    int n0 = blockIdx.x * 64;
    int nl = threadIdx.x & 63;
    int ks = threadIdx.x >> 6;
    const float* Wm = modW + (size_t)band*HID*HID;
    float s = 0.f;
    for (int k = ks*128; k < ks*128 + 128; k++)
        s += bo[k] * Wm[(size_t)k*HID + n0 + nl];
    red[threadIdx.x] = s;
    __syncthreads();
    if (threadIdx.x < 64) {
        float t = red[threadIdx.x] + red[threadIdx.x+64] + red[threadIdx.x+128] + red[threadIdx.x+192];
        bf[band*HID + n0 + threadIdx.x] = t + modb[band*HID + n0 + threadIdx.x];
    }
}

// ================= flash HMMA attention (P in registers, 2 token chunks) =================
#define AT_QSTR 72
#define AT_KSTR 72
#define AT_VSTR 264
#define AT_SMEM ((128*AT_QSTR + 256*AT_KSTR + 64*AT_VSTR)*2)   // 89088 B
__global__ __launch_bounds__(256, 2)
void attn_mma_k(const __half* __restrict__ qh, const __half* __restrict__ kvh,
                const float* __restrict__ tv, __half* __restrict__ out)
{
    extern __shared__ __half sm[];
    __half* sQ = sm;
    __half* sK = sQ + 128*AT_QSTR;
    __half* sV = sK + 256*AT_KSTR;
    int tid = threadIdx.x, wid = tid >> 5, lane = tid & 31;
    int h = blockIdx.y, b = blockIdx.z;
    long long q0 = (long long)blockIdx.x * 128;
    const __half* kvb = kvh + (size_t)b*NTOK*256;

    for (int idx = tid; idx < 1024; idx += 256) {
        int r = idx >> 3, c8 = idx & 7;
        *(uint4*)(sQ + r*AT_QSTR + c8*8) = *(const uint4*)(qh + (q0 + r)*FD + h*64 + c8*8);
    }
    for (int idx = tid; idx < 2048; idx += 256) {
        int t = idx >> 3, c8 = idx & 7;
        *(uint4*)(sK + t*AT_KSTR + c8*8) = *(const uint4*)(kvb + t*256 + h*64 + c8*8);
    }
    for (int idx = tid; idx < NTOK*64; idx += 256) {
        int t = idx >> 6, dd = idx & 63;
        sV[dd*AT_VSTR + t] = kvb[t*256 + 128 + h*64 + dd];
    }
    __syncthreads();

    uint32_t sQu = smem_u32(sQ), sKu = smem_u32(sK), sVu = smem_u32(sV);

    uint32_t a_row = (uint32_t)(wid*16 + (lane & 15)), a_koff = (uint32_t)(lane >> 4) * 8;
    uint32_t q_row = (uint32_t)(lane & 15), q_koff = (uint32_t)(lane >> 4) * 8;
    int rq = wid*16 + (lane >> 2);
    int qc = (lane & 3) * 2;
    float tq0 = tv[q0 + rq];
    float tq1 = tv[q0 + rq + 8];
    float mx0 = -1e30f, mx1 = -1e30f, den0 = 0.f, den1 = 0.f;

    float o[8][4];
    #pragma unroll
    for (int nj = 0; nj < 8; nj++)
        #pragma unroll
        for (int q = 0; q < 4; q++) o[nj][q] = 0.f;

    #pragma unroll
    for (int c = 0; c < 2; c++) {
        float s[16][4];
        #pragma unroll
        for (int ni = 0; ni < 16; ni++)
            #pragma unroll
            for (int q = 0; q < 4; q++) s[ni][q] = 0.f;

        #pragma unroll
        for (int kk = 0; kk < 64; kk += 16) {
            uint32_t afr[4];
            ldm_x4(afr, sQu + (a_row*AT_QSTR + kk + a_koff)*2);
            #pragma unroll
            for (int nj = 0; nj < 8; nj++) {
                uint32_t bfr[4];
                ldm_x4(bfr, sKu + (((uint32_t)(c*128 + nj*16) + q_row)*AT_KSTR + kk + q_koff)*2);
                mma16816(s[nj*2],   afr, bfr[0], bfr[2]);
                mma16816(s[nj*2+1], afr, bfr[1], bfr[3]);
            }
        }

        float cm0 = -1e30f, cm1 = -1e30f;
        #pragma unroll
        for (int ni = 0; ni < 16; ni++) {
            #pragma unroll
            for (int cc = 0; cc < 2; cc++) {
                float pos = ((float)(c*128 + ni*8 + qc + cc) + 0.5f) * (1.0f/256.0f);
                float dd0 = tq0 - pos, dd1 = tq1 - pos;
                s[ni][cc]   = s[ni][cc]*0.125f   - 10.0f*dd0*dd0;
                s[ni][cc+2] = s[ni][cc+2]*0.125f - 10.0f*dd1*dd1;
                cm0 = fmaxf(cm0, s[ni][cc]);
                cm1 = fmaxf(cm1, s[ni][cc+2]);
            }
        }
        #pragma unroll
        for (int oo = 1; oo < 4; oo <<= 1) {
            cm0 = fmaxf(cm0, __shfl_xor_sync(0xffffffffu, cm0, oo));
            cm1 = fmaxf(cm1, __shfl_xor_sync(0xffffffffu, cm1, oo));
        }
        float nm0 = fmaxf(mx0, cm0), nm1 = fmaxf(mx1, cm1);
        float f0 = __expf(mx0 - nm0), f1 = __expf(mx1 - nm1);
        mx0 = nm0; mx1 = nm1;

        float ds0 = 0.f, ds1 = 0.f;
        #pragma unroll
        for (int ni = 0; ni < 16; ni++) {
            s[ni][0] = __expf(s[ni][0] - nm0);
            s[ni][1] = __expf(s[ni][1] - nm0);
            s[ni][2] = __expf(s[ni][2] - nm1);
            s[ni][3] = __expf(s[ni][3] - nm1);
            ds0 += s[ni][0] + s[ni][1];
            ds1 += s[ni][2] + s[ni][3];
        }
        den0 = den0*f0 + ds0;
        den1 = den1*f1 + ds1;

        #pragma unroll
        for (int nj = 0; nj < 8; nj++) {
            o[nj][0] *= f0; o[nj][1] *= f0;
            o[nj][2] *= f1; o[nj][3] *= f1;
        }

        #pragma unroll
        for (int m = 0; m < 8; m++) {
            uint32_t pf[4];
            __half2 h0 = __floats2half2_rn(s[2*m][0],   s[2*m][1]);
            __half2 h1 = __floats2half2_rn(s[2*m][2],   s[2*m][3]);
            __half2 h2 = __floats2half2_rn(s[2*m+1][0], s[2*m+1][1]);
            __half2 h3 = __floats2half2_rn(s[2*m+1][2], s[2*m+1][3]);
            pf[0] = *(uint32_t*)&h0; pf[1] = *(uint32_t*)&h1;
            pf[2] = *(uint32_t*)&h2; pf[3] = *(uint32_t*)&h3;
            #pragma unroll
            for (int nj = 0; nj < 4; nj++) {
                uint32_t bfr[4];
                ldm_x4(bfr, sVu + (((uint32_t)(nj*16) + q_row)*AT_VSTR + (c*128 + m*16) + q_koff)*2);
                mma16816(o[nj*2],   pf, bfr[0], bfr[2]);
                mma16816(o[nj*2+1], pf, bfr[1], bfr[3]);
            }
        }
    }

    #pragma unroll
    for (int oo = 1; oo < 4; oo <<= 1) {
        den0 += __shfl_xor_sync(0xffffffffu, den0, oo);
        den1 += __shfl_xor_sync(0xffffffffu, den1, oo);
    }

    float inv0 = 1.0f / den0, inv1 = 1.0f / den1;
    long long qi0 = q0 + rq;
    __half* op0 = out + ((size_t)b*HW + qi0)*FD + h*64;
    __half* op1 = op0 + (size_t)8*FD;
    #pragma unroll
    for (int nj = 0; nj < 8; nj++) {
        *(__half2*)(op0 + nj*8 + qc) = __floats2half2_rn(o[nj][0]*inv0, o[nj][1]*inv0);
        *(__half2*)(op1 + nj*8 + qc) = __floats2half2_rn(o[nj][2]*inv1, o[nj][3]*inv1);
    }
}

// ================= launch (dual-stream fork/join, G2 ∥ pair) =================
extern "C" void kernel_launch(void* const* d_in, const int* in_sizes, int n_in,
                              void* d_out, int out_size)
{
    const float* x      = (const float*)d_in[0];
    const float* tokens = (const float*)d_in[1];
    const float* qW     = (const float*)d_in[2];
    const float* qb     = (const float*)d_in[3];
    const float* Wq     = (const float*)d_in[4];
    const float* Wkv    = (const float*)d_in[5];
    const float* Wo     = (const float*)d_in[6];
    const float* bo     = (const float*)d_in[7];
    const float* bwW    = (const float*)d_in[8];
    const float* bwb    = (const float*)d_in[9];
    const float* modW   = (const float*)d_in[10];
    const float* modb   = (const float*)d_in[11];
    const float* hvW    = (const float*)d_in[12];
    const float* hvb    = (const float*)d_in[13];
    const float* outW   = (const float*)d_in[14];
    const float* outb   = (const float*)d_in[15];
    float* total = (float*)d_out;

    __half *gqh, *glh, *xqh, *qh, *kvh, *attnh, *s1h, *m0h, *g2h, *tokh, *hlh;
    __half *qWT, *WqT, *WkvT, *bwWT, *modWT, *hvWT, *WoA, *wfT;
    float *tv, *bfp;
    cudaGetSymbolAddress((void**)&gqh,   g_gq_h);
    cudaGetSymbolAddress((void**)&glh,   g_gl_h);
    cudaGetSymbolAddress((void**)&xqh,   g_xq_h);
    cudaGetSymbolAddress((void**)&qh,    g_q_h);
    cudaGetSymbolAddress((void**)&kvh,   g_kv_h);
    cudaGetSymbolAddress((void**)&attnh, g_attn_h);
    cudaGetSymbolAddress((void**)&s1h,   g_s_h);
    cudaGetSymbolAddress((void**)&m0h,   g_m0_h);
    cudaGetSymbolAddress((void**)&g2h,   g_g2_h);
    cudaGetSymbolAddress((void**)&tokh,  g_tok_h);
    cudaGetSymbolAddress((void**)&hlh,   g_hl_h);
    cudaGetSymbolAddress((void**)&qWT,   g_qWT);
    cudaGetSymbolAddress((void**)&WqT,   g_WqT);
    cudaGetSymbolAddress((void**)&WkvT,  g_WkvT);
    cudaGetSymbolAddress((void**)&bwWT,  g_bwWT);
    cudaGetSymbolAddress((void**)&modWT, g_modWT);
    cudaGetSymbolAddress((void**)&hvWT,  g_hvWT);
    cudaGetSymbolAddress((void**)&WoA,   g_WoA);
    cudaGetSymbolAddress((void**)&wfT,   g_wfT);
    cudaGetSymbolAddress((void**)&tv,    g_tv);
    cudaGetSymbolAddress((void**)&bfp,   g_bf);

    cudaFuncSetAttribute(tgemm<true,false,false,false,2>,  cudaFuncAttributeMaxDynamicSharedMemorySize, TG_SMEM);
    cudaFuncSetAttribute(tgemm<false,false,false,false,8>, cudaFuncAttributeMaxDynamicSharedMemorySize, TG_SMEM);
    cudaFuncSetAttribute(tgemm<true,true,false,false,2>,   cudaFuncAttributeMaxDynamicSharedMemorySize, TG_SMEM);
    cudaFuncSetAttribute(tgemm<true,false,true,true,8>,    cudaFuncAttributeMaxDynamicSharedMemorySize, TG_SMEM);
    cudaFuncSetAttribute(tgemm<true,false,false,true,8>,   cudaFuncAttributeMaxDynamicSharedMemorySize, TG_SMEM);
    cudaFuncSetAttribute(pairgemm, cudaFuncAttributeMaxDynamicSharedMemorySize, PR_SMEM);
    cudaFuncSetAttribute(attn_mma_k, cudaFuncAttributeMaxDynamicSharedMemorySize, AT_SMEM);

    // ---- dual-stream fork/join (graph-capturable; no device allocations) ----
    cudaStream_t sB;
    cudaStreamCreateWithFlags(&sB, cudaStreamNonBlocking);
    cudaEvent_t evA, evB, evC, evD, evE, evF;
    cudaEventCreateWithFlags(&evA, cudaEventDisableTiming);
    cudaEventCreateWithFlags(&evB, cudaEventDisableTiming);
    cudaEventCreateWithFlags(&evC, cudaEventDisableTiming);
    cudaEventCreateWithFlags(&evD, cudaEventDisableTiming);
    cudaEventCreateWithFlags(&evE, cudaEventDisableTiming);
    cudaEventCreateWithFlags(&evF, cudaEventDisableTiming);

    // fork: bring sB into the capture
    cudaEventRecord(evA, 0);
    cudaStreamWaitEvent(sB, evA, 0);

    // D: gamma
    gamma_k<<<HW, 128, 0, 0>>>(x, gqh, glh, tv);

    // B: prep, bf, kv
    prep_k<<<(int)((PREP_TOTAL + 255)/256), 256, 0, sB>>>(
        qW, Wq, Wkv, bwW, modW, hvW, Wo, tokens, outb,
        qWT, WqT, WkvT, bwWT, modWT, hvWT, WoA, tokh, total);
    bf_k<<<dim3(8,3), 256, 0, sB>>>(bo, modW, modb, bfp);
    tgemm<false,false,false,false,8><<<dim3(4,16), 256, TG_SMEM, sB>>>(
        tokh, WkvT, nullptr, nullptr, nullptr, kvh, nullptr, nullptr, nullptr, NB*NTOK, 256,
        0, 0, 0, 0, 0);

    // cross-sync
    cudaEventRecord(evB, sB);
    cudaEventRecord(evC, 0);
    cudaStreamWaitEvent(0, evB, 0);
    cudaStreamWaitEvent(sB, evC, 0);

    // D: xq -> q -> attention
    tgemm<true,false,false,false,2><<<dim3(8,128), 256, TG_SMEM, 0>>>(
        gqh, qWT, qb, nullptr, nullptr, xqh, nullptr, nullptr, nullptr, HW, HID,
        0, 0, 0, 0, 0);
    tgemm<false,false,false,false,8><<<dim3(2,128), 256, TG_SMEM, 0>>>(
        xqh, WqT, nullptr, nullptr, nullptr, qh, nullptr, nullptr, nullptr, HW, FD,
        0, 0, 0, 0, 0);
    attn_mma_k<<<dim3(HW/128, 2, NB), 256, AT_SMEM, 0>>>(qh, kvh, tv, attnh);

    // B: h_l (banded), wfT (banded)
    tgemm<true,false,false,false,2><<<dim3(8,128,3), 256, TG_SMEM, sB>>>(
        glh, bwWT, bwb, nullptr, nullptr, hlh, nullptr, nullptr, nullptr, HW, HID,
        (long long)HW*FD, (long long)HID*FD, HID, (long long)HW*HID, 0);
    tgemm<false,false,false,false,8><<<dim3(8,1,3), 256, TG_SMEM, sB>>>(
        WoA, modWT, nullptr, nullptr, nullptr,
        nullptr, wfT, nullptr, nullptr, FD, HID,
        0, (long long)HID*HID, 0, 0, (long long)HID*FD);

    // sync: B needs attn (for G2); D needs h_l/wfT (for pair)
    cudaEventRecord(evD, sB);         // B done with h_l/wfT
    cudaEventRecord(evE, 0);          // D done with attn
    cudaStreamWaitEvent(0, evD, 0);
    cudaStreamWaitEvent(sB, evE, 0);

    // B: G2 = relu(attn@wf2 + bf2 + hl2) -> g2h   (concurrent with pair on D)
    tgemm<true,true,false,false,2><<<dim3(8,1024), 256, TG_SMEM, sB>>>(
        attnh, wfT + 2*HID*FD, bfp + 2*HID, hlh + 2ull*HW*HID, nullptr,
        g2h, nullptr, nullptr, nullptr, MROWS, HID,
        0, 0, 0, 0, 0);

    // D: pair (m0h + outproj, s1h)
    pairgemm<<<dim3(8,1024), 256, PR_SMEM, 0>>>(
        attnh, wfT, bfp, hlh, m0h, s1h, outW, total);

    // join: D waits for G2 before HV1 (reads g2h)
    cudaEventRecord(evF, sB);
    cudaStreamWaitEvent(0, evF, 0);

    // D: HV1, HV2
    tgemm<true,false,true,true,8><<<dim3(8,1024), 256, TG_SMEM, 0>>>(
        s1h, hvWT, hvb, nullptr, g2h, m0h, nullptr,
        outW + 512*3, total, MROWS, HID,
        0, 0, 0, 0, 0);
    tgemm<true,false,false,true,8><<<dim3(8,1024), 256, TG_SMEM, 0>>>(
        m0h, hvWT + (size_t)HID*HID, hvb + HID, nullptr, nullptr, nullptr,
        nullptr, outW + 2*512*3, total, MROWS, HID,
        0, 0, 0, 0, 0);
}